// round 1
// baseline (speedup 1.0000x reference)
#include <cuda_runtime.h>
#include <math.h>

#define Bb 2
#define Tt 2048
#define TCc 512
#define Cc 1024
#define CCc 512
#define Hh 16
#define Dd 64

// Scratch (allocation-free rule: __device__ globals)
__device__ float g_q [Bb*Tt*Cc];
__device__ float g_k [Bb*Tt*Cc];
__device__ float g_v [Bb*Tt*Cc];
__device__ float g_qc[Bb*Tt*Cc];
__device__ float g_kc[Bb*TCc*Cc];
__device__ float g_vc[Bb*TCc*Cc];
__device__ float g_y [Bb*Tt*Cc];

// ---------------------------------------------------------------------------
// Tiled fp32 GEMM: out[M,N] = A[M,K] @ W[K,N] + bias[N]
// BM=BN=64, BK=16, 256 threads, 4x4 register tile per thread.
// ---------------------------------------------------------------------------
__global__ __launch_bounds__(256) void gemm_bias_kernel(
    const float* __restrict__ A, const float* __restrict__ W,
    const float* __restrict__ bias, float* __restrict__ out,
    int M, int N, int K)
{
    __shared__ float As[16][68];   // transposed: As[k][m], pad to dodge conflicts
    __shared__ float Bs[16][64];   // Bs[k][n]

    const int tid = threadIdx.x;
    const int tx = tid & 15, ty = tid >> 4;
    const int bm = blockIdx.y * 64, bn = blockIdx.x * 64;

    // loader indices
    const int ar = tid >> 2, ac = (tid & 3) * 4;   // A: 64 rows x 4 float4
    const int br = tid >> 4, bc = (tid & 15) * 4;  // W: 16 rows x 16 float4

    float acc[4][4] = {};

    for (int kb = 0; kb < K; kb += 16) {
        float4 av = *(const float4*)&A[(size_t)(bm + ar) * K + kb + ac];
        float4 bv = *(const float4*)&W[(size_t)(kb + br) * N + bn + bc];
        As[ac + 0][ar] = av.x; As[ac + 1][ar] = av.y;
        As[ac + 2][ar] = av.z; As[ac + 3][ar] = av.w;
        *(float4*)&Bs[br][bc] = bv;
        __syncthreads();

        #pragma unroll
        for (int kk = 0; kk < 16; kk++) {
            float4 a4 = *(const float4*)&As[kk][ty * 4];
            float4 b4 = *(const float4*)&Bs[kk][tx * 4];
            float a[4] = {a4.x, a4.y, a4.z, a4.w};
            float b[4] = {b4.x, b4.y, b4.z, b4.w};
            #pragma unroll
            for (int i = 0; i < 4; i++)
                #pragma unroll
                for (int j = 0; j < 4; j++)
                    acc[i][j] += a[i] * b[j];
        }
        __syncthreads();
    }

    #pragma unroll
    for (int i = 0; i < 4; i++) {
        const int r = bm + ty * 4 + i;
        #pragma unroll
        for (int j = 0; j < 4; j++) {
            const int c = bn + tx * 4 + j;
            out[(size_t)r * N + c] = acc[i][j] + bias[c];
        }
    }
}

// ---------------------------------------------------------------------------
// Flash attention: 64-query tile per block, online softmax.
// Q/K/V are [B, L, C] with head h occupying columns h*64..h*64+63.
// Output written to Y [B, Tq, C] (merged-head layout); accumulate=1 adds.
// ---------------------------------------------------------------------------
__global__ __launch_bounds__(256) void attn_kernel(
    const float* __restrict__ Q, const float* __restrict__ Kg,
    const float* __restrict__ Vg, float* __restrict__ Y,
    int Tq, int Tk, int causal, int accumulate)
{
    extern __shared__ float sm[];
    float* Qt = sm;               // [64][68]  transposed [d][q]
    float* Kt = Qt + 64 * 68;     // [64][68]  transposed [d][k]
    float* Vs = Kt + 64 * 68;     // [64][64]  natural    [k][d]
    float* Ps = Vs + 64 * 64;     // [64][68]  transposed [k][q]

    const int tid = threadIdx.x;
    const int tx = tid & 15, ty = tid >> 4;
    const int qt = blockIdx.x, h = blockIdx.y, b = blockIdx.z;
    const int q0 = qt * 64;

    const float* Qb = Q  + ((size_t)b * Tq) * Cc + h * Dd;
    const float* Kb = Kg + ((size_t)b * Tk) * Cc + h * Dd;
    const float* Vb = Vg + ((size_t)b * Tk) * Cc + h * Dd;

    // Load Q tile, transposed
    #pragma unroll
    for (int it = 0; it < 4; it++) {
        int idx = it * 256 + tid;
        int r = idx >> 4, c = (idx & 15) * 4;
        float4 v4 = *(const float4*)&Qb[(size_t)(q0 + r) * Cc + c];
        Qt[(c + 0) * 68 + r] = v4.x; Qt[(c + 1) * 68 + r] = v4.y;
        Qt[(c + 2) * 68 + r] = v4.z; Qt[(c + 3) * 68 + r] = v4.w;
    }

    float o[4][4] = {};
    float m_old[4], lsum[4];
    #pragma unroll
    for (int i = 0; i < 4; i++) { m_old[i] = -1e30f; lsum[i] = 0.f; }

    const float scale = 0.125f;  // 1/sqrt(64)
    const int ntiles = causal ? (qt + 1) : (Tk / 64);

    for (int kt = 0; kt < ntiles; kt++) {
        __syncthreads();   // protect Kt/Vs/Ps from previous iteration readers
        // Load K (transposed) and V (natural) tiles
        #pragma unroll
        for (int it = 0; it < 4; it++) {
            int idx = it * 256 + tid;
            int r = idx >> 4, c = (idx & 15) * 4;
            float4 kv = *(const float4*)&Kb[(size_t)(kt * 64 + r) * Cc + c];
            Kt[(c + 0) * 68 + r] = kv.x; Kt[(c + 1) * 68 + r] = kv.y;
            Kt[(c + 2) * 68 + r] = kv.z; Kt[(c + 3) * 68 + r] = kv.w;
            float4 vv = *(const float4*)&Vb[(size_t)(kt * 64 + r) * Cc + c];
            *(float4*)&Vs[r * 64 + c] = vv;
        }
        __syncthreads();

        // S = Q K^T  (4x4 per thread: rows ty*4+i queries, cols tx*4+j keys)
        float s[4][4] = {};
        #pragma unroll 8
        for (int d = 0; d < 64; d++) {
            float4 a4 = *(const float4*)&Qt[d * 68 + ty * 4];
            float4 b4 = *(const float4*)&Kt[d * 68 + tx * 4];
            float a[4] = {a4.x, a4.y, a4.z, a4.w};
            float bfr[4] = {b4.x, b4.y, b4.z, b4.w};
            #pragma unroll
            for (int i = 0; i < 4; i++)
                #pragma unroll
                for (int j = 0; j < 4; j++)
                    s[i][j] += a[i] * bfr[j];
        }

        const bool diag = causal && (kt == qt);
        #pragma unroll
        for (int i = 0; i < 4; i++)
            #pragma unroll
            for (int j = 0; j < 4; j++) {
                float val = s[i][j] * scale;
                if (diag && (tx * 4 + j > ty * 4 + i)) val = -1e30f;
                s[i][j] = val;
            }

        // Online softmax per query row (reduce across the 16 tx lanes)
        #pragma unroll
        for (int i = 0; i < 4; i++) {
            float mt = fmaxf(fmaxf(s[i][0], s[i][1]), fmaxf(s[i][2], s[i][3]));
            #pragma unroll
            for (int off = 8; off >= 1; off >>= 1)
                mt = fmaxf(mt, __shfl_xor_sync(0xFFFFFFFFu, mt, off, 32));
            float m_new = fmaxf(m_old[i], mt);
            float alpha = __expf(m_old[i] - m_new);
            float ls = 0.f;
            #pragma unroll
            for (int j = 0; j < 4; j++) {
                float p = __expf(s[i][j] - m_new);
                s[i][j] = p;
                ls += p;
            }
            #pragma unroll
            for (int off = 8; off >= 1; off >>= 1)
                ls += __shfl_xor_sync(0xFFFFFFFFu, ls, off, 32);
            lsum[i] = lsum[i] * alpha + ls;
            m_old[i] = m_new;
            #pragma unroll
            for (int jd = 0; jd < 4; jd++) o[i][jd] *= alpha;
        }

        // Write P transposed: Ps[key][query]
        #pragma unroll
        for (int i = 0; i < 4; i++)
            #pragma unroll
            for (int j = 0; j < 4; j++)
                Ps[(tx * 4 + j) * 68 + ty * 4 + i] = s[i][j];
        __syncthreads();

        // O += P V
        #pragma unroll 8
        for (int j = 0; j < 64; j++) {
            float4 a4 = *(const float4*)&Ps[j * 68 + ty * 4];
            float4 b4 = *(const float4*)&Vs[j * 64 + tx * 4];
            float a[4] = {a4.x, a4.y, a4.z, a4.w};
            float bfr[4] = {b4.x, b4.y, b4.z, b4.w};
            #pragma unroll
            for (int i = 0; i < 4; i++)
                #pragma unroll
                for (int jd = 0; jd < 4; jd++)
                    o[i][jd] += a[i] * bfr[jd];
        }
    }

    // Epilogue: O / l, write to merged-head Y
    #pragma unroll
    for (int i = 0; i < 4; i++) {
        const float inv = 1.f / lsum[i];
        const int r = q0 + ty * 4 + i;
        #pragma unroll
        for (int jd = 0; jd < 4; jd++) {
            const int c = h * Dd + tx * 4 + jd;
            const size_t off = ((size_t)b * Tq + r) * Cc + c;
            const float val = o[i][jd] * inv;
            if (accumulate) Y[off] += val; else Y[off] = val;
        }
    }
}

// ---------------------------------------------------------------------------

extern "C" void kernel_launch(void* const* d_in, const int* in_sizes, int n_in,
                              void* d_out, int out_size)
{
    const float* x     = (const float*)d_in[0];
    const float* cross = (const float*)d_in[1];
    const float* Wk  = (const float*)d_in[2];   const float* bk  = (const float*)d_in[3];
    const float* Wq  = (const float*)d_in[4];   const float* bq  = (const float*)d_in[5];
    const float* Wv  = (const float*)d_in[6];   const float* bv  = (const float*)d_in[7];
    const float* Wck = (const float*)d_in[8];   const float* bck = (const float*)d_in[9];
    const float* Wcq = (const float*)d_in[10];  const float* bcq = (const float*)d_in[11];
    const float* Wcv = (const float*)d_in[12];  const float* bcv = (const float*)d_in[13];
    const float* Wp  = (const float*)d_in[14];  const float* bp  = (const float*)d_in[15];
    float* out = (float*)d_out;

    float *q, *k, *v, *qc, *kc, *vc, *y;
    cudaGetSymbolAddress((void**)&q,  g_q);
    cudaGetSymbolAddress((void**)&k,  g_k);
    cudaGetSymbolAddress((void**)&v,  g_v);
    cudaGetSymbolAddress((void**)&qc, g_qc);
    cudaGetSymbolAddress((void**)&kc, g_kc);
    cudaGetSymbolAddress((void**)&vc, g_vc);
    cudaGetSymbolAddress((void**)&y,  g_y);

    const dim3 blk(256);
    const dim3 g1(Cc / 64, (Bb * Tt) / 64);    // 16 x 64
    const dim3 g2(Cc / 64, (Bb * TCc) / 64);   // 16 x 16

    // Projections
    gemm_bias_kernel<<<g1, blk>>>(x, Wq,  bq,  q,  Bb * Tt,  Cc, Cc);
    gemm_bias_kernel<<<g1, blk>>>(x, Wk,  bk,  k,  Bb * Tt,  Cc, Cc);
    gemm_bias_kernel<<<g1, blk>>>(x, Wv,  bv,  v,  Bb * Tt,  Cc, Cc);
    gemm_bias_kernel<<<g1, blk>>>(x, Wcq, bcq, qc, Bb * Tt,  Cc, Cc);
    gemm_bias_kernel<<<g2, blk>>>(cross, Wck, bck, kc, Bb * TCc, Cc, CCc);
    gemm_bias_kernel<<<g2, blk>>>(cross, Wcv, bcv, vc, Bb * TCc, Cc, CCc);

    // Attention (self causal overwrite, cross accumulate)
    const size_t smem = (size_t)(64 * 68 * 3 + 64 * 64) * sizeof(float); // 68608 B
    cudaFuncSetAttribute(attn_kernel, cudaFuncAttributeMaxDynamicSharedMemorySize, (int)smem);
    const dim3 ga(Tt / 64, Hh, Bb);
    attn_kernel<<<ga, blk, smem>>>(q,  k,  v,  y, Tt, Tt,  1, 0);
    attn_kernel<<<ga, blk, smem>>>(qc, kc, vc, y, Tt, TCc, 0, 1);

    // Output projection
    gemm_bias_kernel<<<g1, blk>>>(y, Wp, bp, out, Bb * Tt, Cc, Cc);
}

// round 4
// speedup vs baseline: 1.4627x; 1.4627x over previous
#include <cuda_runtime.h>
#include <cuda_bf16.h>
#include <cstdint>
#include <math.h>

#define Bb 2
#define Tt 2048
#define TCc 512
#define Cc 1024
#define CCc 512
#define Hh 16
#define Dd 64

// ---------------------------------------------------------------------------
// Scratch (__device__ globals; no allocation allowed)
// ---------------------------------------------------------------------------
__device__ float g_q [Bb*Tt*Cc];
__device__ float g_k [Bb*Tt*Cc];
__device__ float g_v [Bb*Tt*Cc];
__device__ float g_qc[Bb*Tt*Cc];
__device__ float g_kc[Bb*TCc*Cc];
__device__ float g_vc[Bb*TCc*Cc];
__device__ float g_y [Bb*Tt*Cc];

__device__ __nv_bfloat16 g_xh[Bb*Tt*Cc],   g_xl[Bb*Tt*Cc];
__device__ __nv_bfloat16 g_ch[Bb*TCc*CCc], g_cl[Bb*TCc*CCc];
__device__ __nv_bfloat16 g_yh[Bb*Tt*Cc],   g_yl[Bb*Tt*Cc];

__device__ __nv_bfloat16 g_Wq_h [Cc*Cc],  g_Wq_l [Cc*Cc];
__device__ __nv_bfloat16 g_Wk_h [Cc*Cc],  g_Wk_l [Cc*Cc];
__device__ __nv_bfloat16 g_Wv_h [Cc*Cc],  g_Wv_l [Cc*Cc];
__device__ __nv_bfloat16 g_Wcq_h[Cc*Cc],  g_Wcq_l[Cc*Cc];
__device__ __nv_bfloat16 g_Wck_h[Cc*CCc], g_Wck_l[Cc*CCc];
__device__ __nv_bfloat16 g_Wcv_h[Cc*CCc], g_Wcv_l[Cc*CCc];
__device__ __nv_bfloat16 g_Wp_h [Cc*Cc],  g_Wp_l [Cc*Cc];

// ---------------------------------------------------------------------------
// helpers
// ---------------------------------------------------------------------------
__device__ __forceinline__ uint32_t smem_u32(const void* p) {
    uint32_t a;
    asm("{ .reg .u64 t; cvta.to.shared.u64 t, %1; cvt.u32.u64 %0, t; }"
        : "=r"(a) : "l"(p));
    return a;
}

#define CP_ASYNC16(dst, src) \
    asm volatile("cp.async.cg.shared.global [%0], [%1], 16;" :: "r"(dst), "l"(src))
#define CP_COMMIT() asm volatile("cp.async.commit_group;" ::: "memory")
#define CP_WAIT0()  asm volatile("cp.async.wait_group 0;" ::: "memory")
#define CP_WAIT1()  asm volatile("cp.async.wait_group 1;" ::: "memory")

#define LDSM_X4(r0, r1, r2, r3, a) \
    asm volatile("ldmatrix.sync.aligned.m8n8.x4.shared.b16 {%0,%1,%2,%3}, [%4];" \
                 : "=r"(r0), "=r"(r1), "=r"(r2), "=r"(r3) : "r"(a))
// NON-trans: smem is [N,K] k-contiguous == col-major B(k,n); lane L of each
// 8x8 tile gets (n = L/4, k-pair = L%4) which is exactly the b-fragment.
#define LDSM_X2(r0, r1, a) \
    asm volatile("ldmatrix.sync.aligned.m8n8.x2.shared.b16 {%0,%1}, [%2];" \
                 : "=r"(r0), "=r"(r1) : "r"(a))

#define MMA_BF16(d, a, b) \
    asm volatile("mma.sync.aligned.m16n8k16.row.col.f32.bf16.bf16.f32 " \
                 "{%0,%1,%2,%3}, {%4,%5,%6,%7}, {%8,%9}, {%0,%1,%2,%3};" \
                 : "+f"((d)[0]), "+f"((d)[1]), "+f"((d)[2]), "+f"((d)[3]) \
                 : "r"((a)[0]), "r"((a)[1]), "r"((a)[2]), "r"((a)[3]), \
                   "r"((b)[0]), "r"((b)[1]))

// ---------------------------------------------------------------------------
// fp32 -> bf16 hi/lo split
// ---------------------------------------------------------------------------
__global__ void cvt_kernel(const float* __restrict__ s, __nv_bfloat16* __restrict__ h,
                           __nv_bfloat16* __restrict__ l, int n)
{
    int i = blockIdx.x * blockDim.x + threadIdx.x;
    if (i < n) {
        float v = s[i];
        __nv_bfloat16 hh = __float2bfloat16(v);
        h[i] = hh;
        l[i] = __float2bfloat16(v - __bfloat162float(hh));
    }
}

// W[K,N] fp32 -> Wt[N,K] bf16 hi/lo
__global__ void transpose_w_kernel(const float* __restrict__ W,
    __nv_bfloat16* __restrict__ Th, __nv_bfloat16* __restrict__ Tl, int K, int N)
{
    __shared__ float t[32][33];
    const int n0 = blockIdx.x * 32, k0 = blockIdx.y * 32;
    const int tx = threadIdx.x, ty = threadIdx.y;
    #pragma unroll
    for (int i = 0; i < 4; i++)
        t[ty + 8 * i][tx] = W[(size_t)(k0 + ty + 8 * i) * N + n0 + tx];
    __syncthreads();
    #pragma unroll
    for (int i = 0; i < 4; i++) {
        float v = t[tx][ty + 8 * i];
        __nv_bfloat16 h = __float2bfloat16(v);
        __nv_bfloat16 l = __float2bfloat16(v - __bfloat162float(h));
        size_t o = (size_t)(n0 + ty + 8 * i) * K + k0 + tx;
        Th[o] = h; Tl[o] = l;
    }
}

// ---------------------------------------------------------------------------
// HMMA GEMM: out[M,N] = A @ W + bias, 3xBF16 split.
// A hi/lo: [M,K] bf16 k-major.  B hi/lo: [N,K] bf16 k-major (W^T).
// CTA tile 128x128, BK=32, 8 warps (4m x 2n), each 32x64.
// ---------------------------------------------------------------------------
#define BKg 32
#define LDAg 40                       // 32 + 8 pad (elements)
#define TILEB (128 * LDAg * 2)        // 10240 B per matrix
#define STAGEB (4 * TILEB)            // Ah, Al, Bh, Bl
#define GEMM_SMEM (2 * STAGEB)        // 81920 B

__global__ __launch_bounds__(256, 1) void hmma_gemm_kernel(
    const __nv_bfloat16* __restrict__ Ah, const __nv_bfloat16* __restrict__ Al,
    const __nv_bfloat16* __restrict__ Bh, const __nv_bfloat16* __restrict__ Bl,
    const float* __restrict__ bias, float* __restrict__ out,
    int M, int N, int K)
{
    extern __shared__ char smem[];
    const uint32_t sb = smem_u32(smem);
    const int tid = threadIdx.x;
    const int wid = tid >> 5, lane = tid & 31;
    const int bm = blockIdx.y * 128, bn = blockIdx.x * 128;

    const int wr = wid & 3;        // m: wr*32
    const int wc = wid >> 2;       // n: wc*64

    const char* gsrc[4] = {
        (const char*)(Ah + (size_t)bm * K),
        (const char*)(Al + (size_t)bm * K),
        (const char*)(Bh + (size_t)bn * K),
        (const char*)(Bl + (size_t)bn * K) };

    const int row0 = tid >> 2, c16a = tid & 3;
    const int row1 = (tid + 256) >> 2;

    auto load_chunk = [&](int kb, int st) {
        const uint32_t sdst = sb + st * STAGEB;
        #pragma unroll
        for (int m = 0; m < 4; m++) {
            const char* g = gsrc[m] + (size_t)kb * (BKg * 2);
            uint32_t d = sdst + m * TILEB;
            CP_ASYNC16(d + row0 * (LDAg * 2) + c16a * 16,
                       g + (size_t)row0 * (K * 2) + c16a * 16);
            CP_ASYNC16(d + row1 * (LDAg * 2) + c16a * 16,
                       g + (size_t)row1 * (K * 2) + c16a * 16);
        }
    };

    float acc[2][8][4] = {};

    const int nchunks = K / BKg;
    load_chunk(0, 0);
    CP_COMMIT();

    for (int kb = 0; kb < nchunks; kb++) {
        const int st = kb & 1;
        if (kb + 1 < nchunks) { load_chunk(kb + 1, st ^ 1); CP_COMMIT(); CP_WAIT1(); }
        else                  { CP_WAIT0(); }
        __syncthreads();

        const uint32_t ah = sb + st * STAGEB;
        const uint32_t al = ah + TILEB;
        const uint32_t bh = ah + 2 * TILEB;
        const uint32_t bl = ah + 3 * TILEB;

        #pragma unroll
        for (int ks = 0; ks < 2; ks++) {
            const int k0 = ks * 16;
            uint32_t Ahf[2][4], Alf[2][4], Bhf[8][2], Blf[8][2];

            #pragma unroll
            for (int mt = 0; mt < 2; mt++) {
                const int arow = wr * 32 + mt * 16 + (lane & 15);
                const int acol = k0 + (lane >> 4) * 8;
                const uint32_t ao = (uint32_t)(arow * LDAg + acol) * 2;
                LDSM_X4(Ahf[mt][0], Ahf[mt][1], Ahf[mt][2], Ahf[mt][3], ah + ao);
                LDSM_X4(Alf[mt][0], Alf[mt][1], Alf[mt][2], Alf[mt][3], al + ao);
            }
            #pragma unroll
            for (int nt = 0; nt < 8; nt++) {
                const int brow = wc * 64 + nt * 8 + (lane & 7);
                const int bcol = k0 + ((lane >> 3) & 1) * 8;
                const uint32_t bo = (uint32_t)(brow * LDAg + bcol) * 2;
                LDSM_X2(Bhf[nt][0], Bhf[nt][1], bh + bo);
                LDSM_X2(Blf[nt][0], Blf[nt][1], bl + bo);
            }

            #pragma unroll
            for (int mt = 0; mt < 2; mt++)
                #pragma unroll
                for (int nt = 0; nt < 8; nt++) {
                    MMA_BF16(acc[mt][nt], Ahf[mt], Bhf[nt]);
                    MMA_BF16(acc[mt][nt], Ahf[mt], Blf[nt]);
                    MMA_BF16(acc[mt][nt], Alf[mt], Bhf[nt]);
                }
        }
        __syncthreads();
    }

    const int crow = lane >> 2, ccol = (lane & 3) * 2;
    #pragma unroll
    for (int mt = 0; mt < 2; mt++) {
        #pragma unroll
        for (int half = 0; half < 2; half++) {
            const int r = bm + wr * 32 + mt * 16 + crow + half * 8;
            float* orow = out + (size_t)r * N;
            #pragma unroll
            for (int nt = 0; nt < 8; nt++) {
                const int c = bn + wc * 64 + nt * 8 + ccol;
                float2 b2 = *(const float2*)&bias[c];
                float2 v;
                v.x = acc[mt][nt][half * 2 + 0] + b2.x;
                v.y = acc[mt][nt][half * 2 + 1] + b2.y;
                *(float2*)&orow[c] = v;
            }
        }
    }
}

// ---------------------------------------------------------------------------
// Flash attention (fp32 SIMT, unchanged)
// ---------------------------------------------------------------------------
__global__ __launch_bounds__(256) void attn_kernel(
    const float* __restrict__ Q, const float* __restrict__ Kg,
    const float* __restrict__ Vg, float* __restrict__ Y,
    int Tq, int Tk, int causal, int accumulate)
{
    extern __shared__ float sm[];
    float* Qt = sm;
    float* Kt = Qt + 64 * 68;
    float* Vs = Kt + 64 * 68;
    float* Ps = Vs + 64 * 64;

    const int tid = threadIdx.x;
    const int tx = tid & 15, ty = tid >> 4;
    const int qt = blockIdx.x, h = blockIdx.y, b = blockIdx.z;
    const int q0 = qt * 64;

    const float* Qb = Q  + ((size_t)b * Tq) * Cc + h * Dd;
    const float* Kb = Kg + ((size_t)b * Tk) * Cc + h * Dd;
    const float* Vb = Vg + ((size_t)b * Tk) * Cc + h * Dd;

    #pragma unroll
    for (int it = 0; it < 4; it++) {
        int idx = it * 256 + tid;
        int r = idx >> 4, c = (idx & 15) * 4;
        float4 v4 = *(const float4*)&Qb[(size_t)(q0 + r) * Cc + c];
        Qt[(c + 0) * 68 + r] = v4.x; Qt[(c + 1) * 68 + r] = v4.y;
        Qt[(c + 2) * 68 + r] = v4.z; Qt[(c + 3) * 68 + r] = v4.w;
    }

    float o[4][4] = {};
    float m_old[4], lsum[4];
    #pragma unroll
    for (int i = 0; i < 4; i++) { m_old[i] = -1e30f; lsum[i] = 0.f; }

    const float scale = 0.125f;
    const int ntiles = causal ? (qt + 1) : (Tk / 64);

    for (int kt = 0; kt < ntiles; kt++) {
        __syncthreads();
        #pragma unroll
        for (int it = 0; it < 4; it++) {
            int idx = it * 256 + tid;
            int r = idx >> 4, c = (idx & 15) * 4;
            float4 kv = *(const float4*)&Kb[(size_t)(kt * 64 + r) * Cc + c];
            Kt[(c + 0) * 68 + r] = kv.x; Kt[(c + 1) * 68 + r] = kv.y;
            Kt[(c + 2) * 68 + r] = kv.z; Kt[(c + 3) * 68 + r] = kv.w;
            float4 vv = *(const float4*)&Vb[(size_t)(kt * 64 + r) * Cc + c];
            *(float4*)&Vs[r * 64 + c] = vv;
        }
        __syncthreads();

        float s[4][4] = {};
        #pragma unroll 8
        for (int d = 0; d < 64; d++) {
            float4 a4 = *(const float4*)&Qt[d * 68 + ty * 4];
            float4 b4 = *(const float4*)&Kt[d * 68 + tx * 4];
            float a[4] = {a4.x, a4.y, a4.z, a4.w};
            float bfr[4] = {b4.x, b4.y, b4.z, b4.w};
            #pragma unroll
            for (int i = 0; i < 4; i++)
                #pragma unroll
                for (int j = 0; j < 4; j++)
                    s[i][j] += a[i] * bfr[j];
        }

        const bool diag = causal && (kt == qt);
        #pragma unroll
        for (int i = 0; i < 4; i++)
            #pragma unroll
            for (int j = 0; j < 4; j++) {
                float val = s[i][j] * scale;
                if (diag && (tx * 4 + j > ty * 4 + i)) val = -1e30f;
                s[i][j] = val;
            }

        #pragma unroll
        for (int i = 0; i < 4; i++) {
            float mt = fmaxf(fmaxf(s[i][0], s[i][1]), fmaxf(s[i][2], s[i][3]));
            #pragma unroll
            for (int off = 8; off >= 1; off >>= 1)
                mt = fmaxf(mt, __shfl_xor_sync(0xFFFFFFFFu, mt, off, 32));
            float m_new = fmaxf(m_old[i], mt);
            float alpha = __expf(m_old[i] - m_new);
            float ls = 0.f;
            #pragma unroll
            for (int j = 0; j < 4; j++) {
                float p = __expf(s[i][j] - m_new);
                s[i][j] = p;
                ls += p;
            }
            #pragma unroll
            for (int off = 8; off >= 1; off >>= 1)
                ls += __shfl_xor_sync(0xFFFFFFFFu, ls, off, 32);
            lsum[i] = lsum[i] * alpha + ls;
            m_old[i] = m_new;
            #pragma unroll
            for (int jd = 0; jd < 4; jd++) o[i][jd] *= alpha;
        }

        #pragma unroll
        for (int i = 0; i < 4; i++)
            #pragma unroll
            for (int j = 0; j < 4; j++)
                Ps[(tx * 4 + j) * 68 + ty * 4 + i] = s[i][j];
        __syncthreads();

        #pragma unroll 8
        for (int j = 0; j < 64; j++) {
            float4 a4 = *(const float4*)&Ps[j * 68 + ty * 4];
            float4 b4 = *(const float4*)&Vs[j * 64 + tx * 4];
            float a[4] = {a4.x, a4.y, a4.z, a4.w};
            float bfr[4] = {b4.x, b4.y, b4.z, b4.w};
            #pragma unroll
            for (int i = 0; i < 4; i++)
                #pragma unroll
                for (int jd = 0; jd < 4; jd++)
                    o[i][jd] += a[i] * bfr[jd];
        }
    }

    #pragma unroll
    for (int i = 0; i < 4; i++) {
        const float inv = 1.f / lsum[i];
        const int r = q0 + ty * 4 + i;
        #pragma unroll
        for (int jd = 0; jd < 4; jd++) {
            const int c = h * Dd + tx * 4 + jd;
            const size_t off = ((size_t)b * Tq + r) * Cc + c;
            const float val = o[i][jd] * inv;
            if (accumulate) Y[off] += val; else Y[off] = val;
        }
    }
}

// ---------------------------------------------------------------------------

extern "C" void kernel_launch(void* const* d_in, const int* in_sizes, int n_in,
                              void* d_out, int out_size)
{
    const float* x     = (const float*)d_in[0];
    const float* cross = (const float*)d_in[1];
    const float* Wk  = (const float*)d_in[2];   const float* bk  = (const float*)d_in[3];
    const float* Wq  = (const float*)d_in[4];   const float* bq  = (const float*)d_in[5];
    const float* Wv  = (const float*)d_in[6];   const float* bv  = (const float*)d_in[7];
    const float* Wck = (const float*)d_in[8];   const float* bck = (const float*)d_in[9];
    const float* Wcq = (const float*)d_in[10];  const float* bcq = (const float*)d_in[11];
    const float* Wcv = (const float*)d_in[12];  const float* bcv = (const float*)d_in[13];
    const float* Wp  = (const float*)d_in[14];  const float* bp  = (const float*)d_in[15];
    float* out = (float*)d_out;

    float *q, *k, *v, *qc, *kc, *vc, *y;
    cudaGetSymbolAddress((void**)&q,  g_q);
    cudaGetSymbolAddress((void**)&k,  g_k);
    cudaGetSymbolAddress((void**)&v,  g_v);
    cudaGetSymbolAddress((void**)&qc, g_qc);
    cudaGetSymbolAddress((void**)&kc, g_kc);
    cudaGetSymbolAddress((void**)&vc, g_vc);
    cudaGetSymbolAddress((void**)&y,  g_y);

    __nv_bfloat16 *xh, *xl, *ch, *cl, *yh, *yl;
    cudaGetSymbolAddress((void**)&xh, g_xh); cudaGetSymbolAddress((void**)&xl, g_xl);
    cudaGetSymbolAddress((void**)&ch, g_ch); cudaGetSymbolAddress((void**)&cl, g_cl);
    cudaGetSymbolAddress((void**)&yh, g_yh); cudaGetSymbolAddress((void**)&yl, g_yl);

    __nv_bfloat16 *wqh, *wql, *wkh, *wkl, *wvh, *wvl, *wcqh, *wcql, *wckh, *wckl, *wcvh, *wcvl, *wph, *wpl;
    cudaGetSymbolAddress((void**)&wqh,  g_Wq_h);  cudaGetSymbolAddress((void**)&wql,  g_Wq_l);
    cudaGetSymbolAddress((void**)&wkh,  g_Wk_h);  cudaGetSymbolAddress((void**)&wkl,  g_Wk_l);
    cudaGetSymbolAddress((void**)&wvh,  g_Wv_h);  cudaGetSymbolAddress((void**)&wvl,  g_Wv_l);
    cudaGetSymbolAddress((void**)&wcqh, g_Wcq_h); cudaGetSymbolAddress((void**)&wcql, g_Wcq_l);
    cudaGetSymbolAddress((void**)&wckh, g_Wck_h); cudaGetSymbolAddress((void**)&wckl, g_Wck_l);
    cudaGetSymbolAddress((void**)&wcvh, g_Wcv_h); cudaGetSymbolAddress((void**)&wcvl, g_Wcv_l);
    cudaGetSymbolAddress((void**)&wph,  g_Wp_h);  cudaGetSymbolAddress((void**)&wpl,  g_Wp_l);

    const dim3 tblk(32, 8);
    transpose_w_kernel<<<dim3(Cc/32, Cc/32),  tblk>>>(Wq,  wqh,  wql,  Cc,  Cc);
    transpose_w_kernel<<<dim3(Cc/32, Cc/32),  tblk>>>(Wk,  wkh,  wkl,  Cc,  Cc);
    transpose_w_kernel<<<dim3(Cc/32, Cc/32),  tblk>>>(Wv,  wvh,  wvl,  Cc,  Cc);
    transpose_w_kernel<<<dim3(Cc/32, Cc/32),  tblk>>>(Wcq, wcqh, wcql, Cc,  Cc);
    transpose_w_kernel<<<dim3(Cc/32, CCc/32), tblk>>>(Wck, wckh, wckl, CCc, Cc);
    transpose_w_kernel<<<dim3(Cc/32, CCc/32), tblk>>>(Wcv, wcvh, wcvl, CCc, Cc);
    transpose_w_kernel<<<dim3(Cc/32, Cc/32),  tblk>>>(Wp,  wph,  wpl,  Cc,  Cc);

    const int nx = Bb * Tt * Cc, nc = Bb * TCc * CCc;
    cvt_kernel<<<(nx + 255) / 256, 256>>>(x, xh, xl, nx);
    cvt_kernel<<<(nc + 255) / 256, 256>>>(cross, ch, cl, nc);

    cudaFuncSetAttribute(hmma_gemm_kernel, cudaFuncAttributeMaxDynamicSharedMemorySize, GEMM_SMEM);
    const dim3 gblk(256);
    const dim3 gbig(Cc / 128, (Bb * Tt) / 128);    // 8 x 32
    const dim3 gcrs(Cc / 128, (Bb * TCc) / 128);   // 8 x 8

    hmma_gemm_kernel<<<gbig, gblk, GEMM_SMEM>>>(xh, xl, wqh,  wql,  bq,  q,  Bb*Tt,  Cc, Cc);
    hmma_gemm_kernel<<<gbig, gblk, GEMM_SMEM>>>(xh, xl, wkh,  wkl,  bk,  k,  Bb*Tt,  Cc, Cc);
    hmma_gemm_kernel<<<gbig, gblk, GEMM_SMEM>>>(xh, xl, wvh,  wvl,  bv,  v,  Bb*Tt,  Cc, Cc);
    hmma_gemm_kernel<<<gbig, gblk, GEMM_SMEM>>>(xh, xl, wcqh, wcql, bcq, qc, Bb*Tt,  Cc, Cc);
    hmma_gemm_kernel<<<gcrs, gblk, GEMM_SMEM>>>(ch, cl, wckh, wckl, bck, kc, Bb*TCc, Cc, CCc);
    hmma_gemm_kernel<<<gcrs, gblk, GEMM_SMEM>>>(ch, cl, wcvh, wcvl, bcv, vc, Bb*TCc, Cc, CCc);

    const size_t asmem = (size_t)(64 * 68 * 3 + 64 * 64) * sizeof(float);
    cudaFuncSetAttribute(attn_kernel, cudaFuncAttributeMaxDynamicSharedMemorySize, (int)asmem);
    const dim3 ga(Tt / 64, Hh, Bb);
    attn_kernel<<<ga, gblk, asmem>>>(q,  k,  v,  y, Tt, Tt,  1, 0);
    attn_kernel<<<ga, gblk, asmem>>>(qc, kc, vc, y, Tt, TCc, 0, 1);

    cvt_kernel<<<(nx + 255) / 256, 256>>>(y, yh, yl, nx);
    hmma_gemm_kernel<<<gbig, gblk, GEMM_SMEM>>>(yh, yl, wph, wpl, bp, out, Bb*Tt, Cc, Cc);
}

// round 5
// speedup vs baseline: 2.5248x; 1.7261x over previous
#include <cuda_runtime.h>
#include <cuda_bf16.h>
#include <cstdint>
#include <math.h>

#define Bb 2
#define Tt 2048
#define TCc 512
#define Cc 1024
#define CCc 512
#define Hh 16
#define Dd 64

// ---------------------------------------------------------------------------
// Scratch (__device__ globals; no allocation allowed)
// ---------------------------------------------------------------------------
__device__ float g_y [Bb*Tt*Cc];

__device__ __nv_bfloat16 g_xh[Bb*Tt*Cc],   g_xl[Bb*Tt*Cc];
__device__ __nv_bfloat16 g_ch[Bb*TCc*CCc], g_cl[Bb*TCc*CCc];
__device__ __nv_bfloat16 g_yh[Bb*Tt*Cc],   g_yl[Bb*Tt*Cc];

// projection outputs, bf16 hi/lo
__device__ __nv_bfloat16 g_qh [Bb*Tt*Cc],  g_ql [Bb*Tt*Cc];
__device__ __nv_bfloat16 g_kh [Bb*Tt*Cc],  g_kl [Bb*Tt*Cc];
__device__ __nv_bfloat16 g_vh [Bb*Tt*Cc],  g_vl [Bb*Tt*Cc];
__device__ __nv_bfloat16 g_qch[Bb*Tt*Cc],  g_qcl[Bb*Tt*Cc];
__device__ __nv_bfloat16 g_kch[Bb*TCc*Cc], g_kcl[Bb*TCc*Cc];
__device__ __nv_bfloat16 g_vch[Bb*TCc*Cc], g_vcl[Bb*TCc*Cc];

__device__ __nv_bfloat16 g_Wq_h [Cc*Cc],  g_Wq_l [Cc*Cc];
__device__ __nv_bfloat16 g_Wk_h [Cc*Cc],  g_Wk_l [Cc*Cc];
__device__ __nv_bfloat16 g_Wv_h [Cc*Cc],  g_Wv_l [Cc*Cc];
__device__ __nv_bfloat16 g_Wcq_h[Cc*Cc],  g_Wcq_l[Cc*Cc];
__device__ __nv_bfloat16 g_Wck_h[Cc*CCc], g_Wck_l[Cc*CCc];
__device__ __nv_bfloat16 g_Wcv_h[Cc*CCc], g_Wcv_l[Cc*CCc];
__device__ __nv_bfloat16 g_Wp_h [Cc*Cc],  g_Wp_l [Cc*Cc];

// ---------------------------------------------------------------------------
// helpers
// ---------------------------------------------------------------------------
__device__ __forceinline__ uint32_t smem_u32(const void* p) {
    uint32_t a;
    asm("{ .reg .u64 t; cvta.to.shared.u64 t, %1; cvt.u32.u64 %0, t; }"
        : "=r"(a) : "l"(p));
    return a;
}
__device__ __forceinline__ float ex2(float x) {
    float y; asm("ex2.approx.ftz.f32 %0, %1;" : "=f"(y) : "f"(x)); return y;
}

#define CP_ASYNC16(dst, src) \
    asm volatile("cp.async.cg.shared.global [%0], [%1], 16;" :: "r"(dst), "l"(src))
#define CP_COMMIT() asm volatile("cp.async.commit_group;" ::: "memory")
#define CP_WAIT0()  asm volatile("cp.async.wait_group 0;" ::: "memory")
#define CP_WAIT1()  asm volatile("cp.async.wait_group 1;" ::: "memory")

#define LDSM_X4(r0, r1, r2, r3, a) \
    asm volatile("ldmatrix.sync.aligned.m8n8.x4.shared.b16 {%0,%1,%2,%3}, [%4];" \
                 : "=r"(r0), "=r"(r1), "=r"(r2), "=r"(r3) : "r"(a))
#define LDSM_X4T(r0, r1, r2, r3, a) \
    asm volatile("ldmatrix.sync.aligned.m8n8.x4.trans.shared.b16 {%0,%1,%2,%3}, [%4];" \
                 : "=r"(r0), "=r"(r1), "=r"(r2), "=r"(r3) : "r"(a))
#define LDSM_X2(r0, r1, a) \
    asm volatile("ldmatrix.sync.aligned.m8n8.x2.shared.b16 {%0,%1}, [%2];" \
                 : "=r"(r0), "=r"(r1) : "r"(a))

#define MMA_BF16(d, a, b) \
    asm volatile("mma.sync.aligned.m16n8k16.row.col.f32.bf16.bf16.f32 " \
                 "{%0,%1,%2,%3}, {%4,%5,%6,%7}, {%8,%9}, {%0,%1,%2,%3};" \
                 : "+f"((d)[0]), "+f"((d)[1]), "+f"((d)[2]), "+f"((d)[3]) \
                 : "r"((a)[0]), "r"((a)[1]), "r"((a)[2]), "r"((a)[3]), \
                   "r"((b)[0]), "r"((b)[1]))

// ---------------------------------------------------------------------------
// fp32 -> bf16 hi/lo split (used for x, cross, y)
// ---------------------------------------------------------------------------
__global__ void cvt_kernel(const float* __restrict__ s, __nv_bfloat16* __restrict__ h,
                           __nv_bfloat16* __restrict__ l, int n)
{
    int i = blockIdx.x * blockDim.x + threadIdx.x;
    if (i < n) {
        float v = s[i];
        __nv_bfloat16 hh = __float2bfloat16(v);
        h[i] = hh;
        l[i] = __float2bfloat16(v - __bfloat162float(hh));
    }
}

// W[K,N] fp32 -> Wt[N,K] bf16 hi/lo
__global__ void transpose_w_kernel(const float* __restrict__ W,
    __nv_bfloat16* __restrict__ Th, __nv_bfloat16* __restrict__ Tl, int K, int N)
{
    __shared__ float t[32][33];
    const int n0 = blockIdx.x * 32, k0 = blockIdx.y * 32;
    const int tx = threadIdx.x, ty = threadIdx.y;
    #pragma unroll
    for (int i = 0; i < 4; i++)
        t[ty + 8 * i][tx] = W[(size_t)(k0 + ty + 8 * i) * N + n0 + tx];
    __syncthreads();
    #pragma unroll
    for (int i = 0; i < 4; i++) {
        float v = t[tx][ty + 8 * i];
        __nv_bfloat16 h = __float2bfloat16(v);
        __nv_bfloat16 l = __float2bfloat16(v - __bfloat162float(h));
        size_t o = (size_t)(n0 + ty + 8 * i) * K + k0 + tx;
        Th[o] = h; Tl[o] = l;
    }
}

// ---------------------------------------------------------------------------
// HMMA GEMM (3xBF16 split). Output: fp32 (outf) OR bf16 hi/lo (outh/outl).
// ---------------------------------------------------------------------------
#define BKg 32
#define LDAg 40
#define TILEB (128 * LDAg * 2)
#define STAGEB (4 * TILEB)
#define GEMM_SMEM (2 * STAGEB)

__global__ __launch_bounds__(256, 1) void hmma_gemm_kernel(
    const __nv_bfloat16* __restrict__ Ah, const __nv_bfloat16* __restrict__ Al,
    const __nv_bfloat16* __restrict__ Bh, const __nv_bfloat16* __restrict__ Bl,
    const float* __restrict__ bias, float* __restrict__ outf,
    __nv_bfloat16* __restrict__ outh, __nv_bfloat16* __restrict__ outl,
    int M, int N, int K)
{
    extern __shared__ char smem[];
    const uint32_t sb = smem_u32(smem);
    const int tid = threadIdx.x;
    const int wid = tid >> 5, lane = tid & 31;
    const int bm = blockIdx.y * 128, bn = blockIdx.x * 128;

    const int wr = wid & 3;
    const int wc = wid >> 2;

    const char* gsrc[4] = {
        (const char*)(Ah + (size_t)bm * K),
        (const char*)(Al + (size_t)bm * K),
        (const char*)(Bh + (size_t)bn * K),
        (const char*)(Bl + (size_t)bn * K) };

    const int row0 = tid >> 2, c16a = tid & 3;
    const int row1 = (tid + 256) >> 2;

    auto load_chunk = [&](int kb, int st) {
        const uint32_t sdst = sb + st * STAGEB;
        #pragma unroll
        for (int m = 0; m < 4; m++) {
            const char* g = gsrc[m] + (size_t)kb * (BKg * 2);
            uint32_t d = sdst + m * TILEB;
            CP_ASYNC16(d + row0 * (LDAg * 2) + c16a * 16,
                       g + (size_t)row0 * (K * 2) + c16a * 16);
            CP_ASYNC16(d + row1 * (LDAg * 2) + c16a * 16,
                       g + (size_t)row1 * (K * 2) + c16a * 16);
        }
    };

    float acc[2][8][4] = {};

    const int nchunks = K / BKg;
    load_chunk(0, 0);
    CP_COMMIT();

    for (int kb = 0; kb < nchunks; kb++) {
        const int st = kb & 1;
        if (kb + 1 < nchunks) { load_chunk(kb + 1, st ^ 1); CP_COMMIT(); CP_WAIT1(); }
        else                  { CP_WAIT0(); }
        __syncthreads();

        const uint32_t ah = sb + st * STAGEB;
        const uint32_t al = ah + TILEB;
        const uint32_t bh = ah + 2 * TILEB;
        const uint32_t bl = ah + 3 * TILEB;

        #pragma unroll
        for (int ks = 0; ks < 2; ks++) {
            const int k0 = ks * 16;
            uint32_t Ahf[2][4], Alf[2][4], Bhf[8][2], Blf[8][2];

            #pragma unroll
            for (int mt = 0; mt < 2; mt++) {
                const int arow = wr * 32 + mt * 16 + (lane & 15);
                const int acol = k0 + (lane >> 4) * 8;
                const uint32_t ao = (uint32_t)(arow * LDAg + acol) * 2;
                LDSM_X4(Ahf[mt][0], Ahf[mt][1], Ahf[mt][2], Ahf[mt][3], ah + ao);
                LDSM_X4(Alf[mt][0], Alf[mt][1], Alf[mt][2], Alf[mt][3], al + ao);
            }
            #pragma unroll
            for (int nt = 0; nt < 8; nt++) {
                const int brow = wc * 64 + nt * 8 + (lane & 7);
                const int bcol = k0 + ((lane >> 3) & 1) * 8;
                const uint32_t bo = (uint32_t)(brow * LDAg + bcol) * 2;
                LDSM_X2(Bhf[nt][0], Bhf[nt][1], bh + bo);
                LDSM_X2(Blf[nt][0], Blf[nt][1], bl + bo);
            }

            #pragma unroll
            for (int mt = 0; mt < 2; mt++)
                #pragma unroll
                for (int nt = 0; nt < 8; nt++) {
                    MMA_BF16(acc[mt][nt], Ahf[mt], Bhf[nt]);
                    MMA_BF16(acc[mt][nt], Ahf[mt], Blf[nt]);
                    MMA_BF16(acc[mt][nt], Alf[mt], Bhf[nt]);
                }
        }
        __syncthreads();
    }

    const int crow = lane >> 2, ccol = (lane & 3) * 2;
    #pragma unroll
    for (int mt = 0; mt < 2; mt++) {
        #pragma unroll
        for (int half = 0; half < 2; half++) {
            const int r = bm + wr * 32 + mt * 16 + crow + half * 8;
            #pragma unroll
            for (int nt = 0; nt < 8; nt++) {
                const int c = bn + wc * 64 + nt * 8 + ccol;
                float2 b2 = *(const float2*)&bias[c];
                float vx = acc[mt][nt][half * 2 + 0] + b2.x;
                float vy = acc[mt][nt][half * 2 + 1] + b2.y;
                if (outf) {
                    float2 v; v.x = vx; v.y = vy;
                    *(float2*)&outf[(size_t)r * N + c] = v;
                } else {
                    __nv_bfloat162 hh = __float22bfloat162_rn(make_float2(vx, vy));
                    float2 hf = __bfloat1622float2(hh);
                    __nv_bfloat162 ll = __float22bfloat162_rn(
                        make_float2(vx - hf.x, vy - hf.y));
                    *(uint32_t*)&outh[(size_t)r * N + c] = *(uint32_t*)&hh;
                    *(uint32_t*)&outl[(size_t)r * N + c] = *(uint32_t*)&ll;
                }
            }
        }
    }
}

// ---------------------------------------------------------------------------
// HMMA flash attention. BM=128 (8 warps x m16), BN=64 keys, D=64.
// Q/K/V: bf16 hi/lo, [B, L, C] rows with head slice at col h*64.
// 3-term split on both QK^T and PV. Online softmax in exp2 domain.
// ---------------------------------------------------------------------------
#define AP 72
#define APB 144
#define QTILE (128 * APB)         // 18432
#define KVTILE (64 * APB)         // 9216
#define KVSTAGE (4 * KVTILE)      // 36864
#define ATT_SMEM (2 * QTILE + 2 * KVSTAGE)   // 110592

__global__ __launch_bounds__(256, 1) void attn_mma_kernel(
    const __nv_bfloat16* __restrict__ Qh, const __nv_bfloat16* __restrict__ Ql,
    const __nv_bfloat16* __restrict__ Kh, const __nv_bfloat16* __restrict__ Kl,
    const __nv_bfloat16* __restrict__ Vh, const __nv_bfloat16* __restrict__ Vl,
    float* __restrict__ Y, int Tq, int Tk, int causal, int accumulate)
{
    extern __shared__ char smem[];
    const uint32_t sb = smem_u32(smem);
    const int tid = threadIdx.x, wid = tid >> 5, lane = tid & 31;
    const int qt = blockIdx.x, h = blockIdx.y, b = blockIdx.z;
    const int q0 = qt * 128;

    const size_t qoff = ((size_t)b * Tq + q0) * Cc + h * Dd;
    const size_t koff = ((size_t)b * Tk) * Cc + h * Dd;

    const uint32_t sQh = sb, sQl = sb + QTILE;
    const uint32_t sKV = sb + 2 * QTILE;

    // ---- load Q (hi/lo) ----
    {
        const char* gq[2] = { (const char*)(Qh + qoff), (const char*)(Ql + qoff) };
        #pragma unroll
        for (int m = 0; m < 2; m++) {
            uint32_t dst = m ? sQl : sQh;
            #pragma unroll
            for (int it = 0; it < 4; it++) {
                int idx = it * 256 + tid;
                int r = idx >> 3, c = idx & 7;
                CP_ASYNC16(dst + r * APB + c * 16,
                           gq[m] + (size_t)r * (Cc * 2) + c * 16);
            }
        }
    }
    CP_COMMIT();

    const char* gk[4] = {
        (const char*)(Kh + koff), (const char*)(Kl + koff),
        (const char*)(Vh + koff), (const char*)(Vl + koff) };
    auto load_kv = [&](int kt, int st) {
        uint32_t dst = sKV + st * KVSTAGE;
        #pragma unroll
        for (int m = 0; m < 4; m++) {
            #pragma unroll
            for (int it = 0; it < 2; it++) {
                int idx = it * 256 + tid;
                int r = idx >> 3, c = idx & 7;
                CP_ASYNC16(dst + m * KVTILE + r * APB + c * 16,
                           gk[m] + ((size_t)(kt * 64 + r)) * (Cc * 2) + c * 16);
            }
        }
    };

    load_kv(0, 0);
    CP_COMMIT();
    CP_WAIT1();            // Q done (kv0 may be in flight)
    __syncthreads();

    // ---- extract Q a-fragments ----
    uint32_t Qhf[4][4], Qlf[4][4];
    {
        const int r = wid * 16 + (lane & 7) + 8 * ((lane >> 3) & 1);
        const int cb = 8 * (lane >> 4);
        #pragma unroll
        for (int kc = 0; kc < 4; kc++) {
            const uint32_t off = (uint32_t)r * APB + (kc * 16 + cb) * 2;
            LDSM_X4(Qhf[kc][0], Qhf[kc][1], Qhf[kc][2], Qhf[kc][3], sQh + off);
            LDSM_X4(Qlf[kc][0], Qlf[kc][1], Qlf[kc][2], Qlf[kc][3], sQl + off);
        }
    }

    float o[8][4] = {};
    float m0 = -1e30f, m1 = -1e30f, l0 = 0.f, l1 = 0.f;
    const int crow = lane >> 2, ccol = (lane & 3) * 2;
    const int wrow = q0 + wid * 16;
    const int ntt = causal ? (2 * qt + 2) : (Tk / 64);
    const float cs = 0.125f * 1.44269504089f;   // scale * log2(e)

    for (int kt = 0; kt < ntt; kt++) {
        const int st = kt & 1;
        if (kt + 1 < ntt) { load_kv(kt + 1, st ^ 1); CP_COMMIT(); CP_WAIT1(); }
        else              { CP_WAIT0(); }
        __syncthreads();

        const int k0 = kt * 64;
        const bool active = !causal || (k0 <= wrow + 15);
        if (active) {
            const uint32_t sKhT = sKV + st * KVSTAGE;
            const uint32_t sKlT = sKhT + KVTILE;
            const uint32_t sVhT = sKhT + 2 * KVTILE;
            const uint32_t sVlT = sKhT + 3 * KVTILE;

            // ---- S = Q K^T (3-term) ----
            float s[8][4] = {};
            {
                const int krow = (lane & 7) + 8 * (lane >> 4);
                const int kcolb = 8 * ((lane >> 3) & 1);
                #pragma unroll
                for (int kc = 0; kc < 4; kc++) {
                    uint32_t bh[8][2], bl[8][2];
                    #pragma unroll
                    for (int np = 0; np < 4; np++) {
                        const uint32_t off =
                            (uint32_t)(np * 16 + krow) * APB + (kc * 16 + kcolb) * 2;
                        LDSM_X4(bh[2*np][0], bh[2*np][1], bh[2*np+1][0], bh[2*np+1][1],
                                sKhT + off);
                        LDSM_X4(bl[2*np][0], bl[2*np][1], bl[2*np+1][0], bl[2*np+1][1],
                                sKlT + off);
                    }
                    #pragma unroll
                    for (int nt = 0; nt < 8; nt++) {
                        MMA_BF16(s[nt], Qhf[kc], bh[nt]);
                        MMA_BF16(s[nt], Qhf[kc], bl[nt]);
                        MMA_BF16(s[nt], Qlf[kc], bh[nt]);
                    }
                }
            }

            // ---- scale / mask / online softmax ----
            const bool dm = causal && (k0 + 63 > wrow);
            float zx0 = -1e30f, zx1 = -1e30f;
            #pragma unroll
            for (int nt = 0; nt < 8; nt++) {
                #pragma unroll
                for (int r = 0; r < 4; r++) {
                    float z = s[nt][r] * cs;
                    if (dm) {
                        const int col = k0 + nt * 8 + ccol + (r & 1);
                        const int row = wrow + crow + 8 * (r >> 1);
                        if (col > row) z = -1e30f;
                    }
                    s[nt][r] = z;
                }
                zx0 = fmaxf(zx0, fmaxf(s[nt][0], s[nt][1]));
                zx1 = fmaxf(zx1, fmaxf(s[nt][2], s[nt][3]));
            }
            zx0 = fmaxf(zx0, __shfl_xor_sync(0xffffffffu, zx0, 1));
            zx0 = fmaxf(zx0, __shfl_xor_sync(0xffffffffu, zx0, 2));
            zx1 = fmaxf(zx1, __shfl_xor_sync(0xffffffffu, zx1, 1));
            zx1 = fmaxf(zx1, __shfl_xor_sync(0xffffffffu, zx1, 2));
            const float mn0 = fmaxf(m0, zx0), mn1 = fmaxf(m1, zx1);
            const float a0 = ex2(m0 - mn0), a1 = ex2(m1 - mn1);
            m0 = mn0; m1 = mn1;

            float ps0 = 0.f, ps1 = 0.f;
            uint32_t pah[4][4], pal[4][4];
            #pragma unroll
            for (int nt = 0; nt < 8; nt++) {
                const float p0 = ex2(s[nt][0] - mn0), p1 = ex2(s[nt][1] - mn0);
                const float p2 = ex2(s[nt][2] - mn1), p3 = ex2(s[nt][3] - mn1);
                ps0 += p0 + p1; ps1 += p2 + p3;
                __nv_bfloat162 h01 = __float22bfloat162_rn(make_float2(p0, p1));
                __nv_bfloat162 h23 = __float22bfloat162_rn(make_float2(p2, p3));
                float2 f01 = __bfloat1622float2(h01);
                float2 f23 = __bfloat1622float2(h23);
                __nv_bfloat162 q01 = __float22bfloat162_rn(
                    make_float2(p0 - f01.x, p1 - f01.y));
                __nv_bfloat162 q23 = __float22bfloat162_rn(
                    make_float2(p2 - f23.x, p3 - f23.y));
                pah[nt >> 1][(nt & 1) * 2 + 0] = *(uint32_t*)&h01;
                pah[nt >> 1][(nt & 1) * 2 + 1] = *(uint32_t*)&h23;
                pal[nt >> 1][(nt & 1) * 2 + 0] = *(uint32_t*)&q01;
                pal[nt >> 1][(nt & 1) * 2 + 1] = *(uint32_t*)&q23;
            }
            l0 = l0 * a0 + ps0;
            l1 = l1 * a1 + ps1;
            #pragma unroll
            for (int nt = 0; nt < 8; nt++) {
                o[nt][0] *= a0; o[nt][1] *= a0;
                o[nt][2] *= a1; o[nt][3] *= a1;
            }

            // ---- O += P V (3-term) ----
            {
                const int vrl = (lane & 7) + 8 * ((lane >> 3) & 1);
                const int vcb = 8 * (lane >> 4);
                #pragma unroll
                for (int kc = 0; kc < 4; kc++) {
                    uint32_t vh[8][2], vl[8][2];
                    #pragma unroll
                    for (int dp = 0; dp < 4; dp++) {
                        const uint32_t off =
                            (uint32_t)(kc * 16 + vrl) * APB + (dp * 16 + vcb) * 2;
                        LDSM_X4T(vh[2*dp][0], vh[2*dp][1], vh[2*dp+1][0], vh[2*dp+1][1],
                                 sVhT + off);
                        LDSM_X4T(vl[2*dp][0], vl[2*dp][1], vl[2*dp+1][0], vl[2*dp+1][1],
                                 sVlT + off);
                    }
                    #pragma unroll
                    for (int nt = 0; nt < 8; nt++) {
                        MMA_BF16(o[nt], pah[kc], vh[nt]);
                        MMA_BF16(o[nt], pal[kc], vh[nt]);
                        MMA_BF16(o[nt], pah[kc], vl[nt]);
                    }
                }
            }
        }
        __syncthreads();
    }

    // ---- epilogue ----
    l0 += __shfl_xor_sync(0xffffffffu, l0, 1);
    l0 += __shfl_xor_sync(0xffffffffu, l0, 2);
    l1 += __shfl_xor_sync(0xffffffffu, l1, 1);
    l1 += __shfl_xor_sync(0xffffffffu, l1, 2);
    const float i0 = 1.f / l0, i1 = 1.f / l1;

    const int r0 = q0 + wid * 16 + crow;
    float* y0 = Y + ((size_t)b * Tq + r0) * Cc + h * Dd;
    float* y1 = y0 + 8 * Cc;
    #pragma unroll
    for (int nt = 0; nt < 8; nt++) {
        const int c = nt * 8 + ccol;
        float2 v0 = make_float2(o[nt][0] * i0, o[nt][1] * i0);
        float2 v1 = make_float2(o[nt][2] * i1, o[nt][3] * i1);
        if (accumulate) {
            float2 u0 = *(float2*)&y0[c], u1 = *(float2*)&y1[c];
            v0.x += u0.x; v0.y += u0.y; v1.x += u1.x; v1.y += u1.y;
        }
        *(float2*)&y0[c] = v0;
        *(float2*)&y1[c] = v1;
    }
}

// ---------------------------------------------------------------------------

extern "C" void kernel_launch(void* const* d_in, const int* in_sizes, int n_in,
                              void* d_out, int out_size)
{
    const float* x     = (const float*)d_in[0];
    const float* cross = (const float*)d_in[1];
    const float* Wk  = (const float*)d_in[2];   const float* bk  = (const float*)d_in[3];
    const float* Wq  = (const float*)d_in[4];   const float* bq  = (const float*)d_in[5];
    const float* Wv  = (const float*)d_in[6];   const float* bv  = (const float*)d_in[7];
    const float* Wck = (const float*)d_in[8];   const float* bck = (const float*)d_in[9];
    const float* Wcq = (const float*)d_in[10];  const float* bcq = (const float*)d_in[11];
    const float* Wcv = (const float*)d_in[12];  const float* bcv = (const float*)d_in[13];
    const float* Wp  = (const float*)d_in[14];  const float* bp  = (const float*)d_in[15];
    float* out = (float*)d_out;

    float* y;
    cudaGetSymbolAddress((void**)&y, g_y);

    __nv_bfloat16 *xh, *xl, *ch, *cl, *yh, *yl;
    cudaGetSymbolAddress((void**)&xh, g_xh); cudaGetSymbolAddress((void**)&xl, g_xl);
    cudaGetSymbolAddress((void**)&ch, g_ch); cudaGetSymbolAddress((void**)&cl, g_cl);
    cudaGetSymbolAddress((void**)&yh, g_yh); cudaGetSymbolAddress((void**)&yl, g_yl);

    __nv_bfloat16 *qh,*ql,*kh,*kl,*vh,*vl,*qch,*qcl,*kch,*kcl,*vch,*vcl;
    cudaGetSymbolAddress((void**)&qh,  g_qh);  cudaGetSymbolAddress((void**)&ql,  g_ql);
    cudaGetSymbolAddress((void**)&kh,  g_kh);  cudaGetSymbolAddress((void**)&kl,  g_kl);
    cudaGetSymbolAddress((void**)&vh,  g_vh);  cudaGetSymbolAddress((void**)&vl,  g_vl);
    cudaGetSymbolAddress((void**)&qch, g_qch); cudaGetSymbolAddress((void**)&qcl, g_qcl);
    cudaGetSymbolAddress((void**)&kch, g_kch); cudaGetSymbolAddress((void**)&kcl, g_kcl);
    cudaGetSymbolAddress((void**)&vch, g_vch); cudaGetSymbolAddress((void**)&vcl, g_vcl);

    __nv_bfloat16 *wqh,*wql,*wkh,*wkl,*wvh,*wvl,*wcqh,*wcql,*wckh,*wckl,*wcvh,*wcvl,*wph,*wpl;
    cudaGetSymbolAddress((void**)&wqh,  g_Wq_h);  cudaGetSymbolAddress((void**)&wql,  g_Wq_l);
    cudaGetSymbolAddress((void**)&wkh,  g_Wk_h);  cudaGetSymbolAddress((void**)&wkl,  g_Wk_l);
    cudaGetSymbolAddress((void**)&wvh,  g_Wv_h);  cudaGetSymbolAddress((void**)&wvl,  g_Wv_l);
    cudaGetSymbolAddress((void**)&wcqh, g_Wcq_h); cudaGetSymbolAddress((void**)&wcql, g_Wcq_l);
    cudaGetSymbolAddress((void**)&wckh, g_Wck_h); cudaGetSymbolAddress((void**)&wckl, g_Wck_l);
    cudaGetSymbolAddress((void**)&wcvh, g_Wcv_h); cudaGetSymbolAddress((void**)&wcvl, g_Wcv_l);
    cudaGetSymbolAddress((void**)&wph,  g_Wp_h);  cudaGetSymbolAddress((void**)&wpl,  g_Wp_l);

    const dim3 tblk(32, 8);
    transpose_w_kernel<<<dim3(Cc/32, Cc/32),  tblk>>>(Wq,  wqh,  wql,  Cc,  Cc);
    transpose_w_kernel<<<dim3(Cc/32, Cc/32),  tblk>>>(Wk,  wkh,  wkl,  Cc,  Cc);
    transpose_w_kernel<<<dim3(Cc/32, Cc/32),  tblk>>>(Wv,  wvh,  wvl,  Cc,  Cc);
    transpose_w_kernel<<<dim3(Cc/32, Cc/32),  tblk>>>(Wcq, wcqh, wcql, Cc,  Cc);
    transpose_w_kernel<<<dim3(Cc/32, CCc/32), tblk>>>(Wck, wckh, wckl, CCc, Cc);
    transpose_w_kernel<<<dim3(Cc/32, CCc/32), tblk>>>(Wcv, wcvh, wcvl, CCc, Cc);
    transpose_w_kernel<<<dim3(Cc/32, Cc/32),  tblk>>>(Wp,  wph,  wpl,  Cc,  Cc);

    const int nx = Bb * Tt * Cc, nc = Bb * TCc * CCc;
    cvt_kernel<<<(nx + 255) / 256, 256>>>(x, xh, xl, nx);
    cvt_kernel<<<(nc + 255) / 256, 256>>>(cross, ch, cl, nc);

    cudaFuncSetAttribute(hmma_gemm_kernel, cudaFuncAttributeMaxDynamicSharedMemorySize, GEMM_SMEM);
    const dim3 gblk(256);
    const dim3 gbig(Cc / 128, (Bb * Tt) / 128);
    const dim3 gcrs(Cc / 128, (Bb * TCc) / 128);

    hmma_gemm_kernel<<<gbig, gblk, GEMM_SMEM>>>(xh, xl, wqh,  wql,  bq,  nullptr, qh,  ql,  Bb*Tt,  Cc, Cc);
    hmma_gemm_kernel<<<gbig, gblk, GEMM_SMEM>>>(xh, xl, wkh,  wkl,  bk,  nullptr, kh,  kl,  Bb*Tt,  Cc, Cc);
    hmma_gemm_kernel<<<gbig, gblk, GEMM_SMEM>>>(xh, xl, wvh,  wvl,  bv,  nullptr, vh,  vl,  Bb*Tt,  Cc, Cc);
    hmma_gemm_kernel<<<gbig, gblk, GEMM_SMEM>>>(xh, xl, wcqh, wcql, bcq, nullptr, qch, qcl, Bb*Tt,  Cc, Cc);
    hmma_gemm_kernel<<<gcrs, gblk, GEMM_SMEM>>>(ch, cl, wckh, wckl, bck, nullptr, kch, kcl, Bb*TCc, Cc, CCc);
    hmma_gemm_kernel<<<gcrs, gblk, GEMM_SMEM>>>(ch, cl, wcvh, wcvl, bcv, nullptr, vch, vcl, Bb*TCc, Cc, CCc);

    cudaFuncSetAttribute(attn_mma_kernel, cudaFuncAttributeMaxDynamicSharedMemorySize, ATT_SMEM);
    const dim3 ga(Tt / 128, Hh, Bb);
    attn_mma_kernel<<<ga, gblk, ATT_SMEM>>>(qh,  ql,  kh,  kl,  vh,  vl,  y, Tt, Tt,  1, 0);
    attn_mma_kernel<<<ga, gblk, ATT_SMEM>>>(qch, qcl, kch, kcl, vch, vcl, y, Tt, TCc, 0, 1);

    cvt_kernel<<<(nx + 255) / 256, 256>>>(y, yh, yl, nx);
    hmma_gemm_kernel<<<gbig, gblk, GEMM_SMEM>>>(yh, yl, wph, wpl, bp, out, nullptr, nullptr, Bb*Tt, Cc, Cc);
}

// round 6
// speedup vs baseline: 2.8167x; 1.1156x over previous
#include <cuda_runtime.h>
#include <cuda_bf16.h>
#include <cstdint>
#include <math.h>

#define Bb 2
#define Tt 2048
#define TCc 512
#define Cc 1024
#define CCc 512
#define Hh 16
#define Dd 64

// ---------------------------------------------------------------------------
// Scratch (__device__ globals; no allocation allowed)
// ---------------------------------------------------------------------------
__device__ float g_y [Bb*Tt*Cc];

__device__ __nv_bfloat16 g_xh[Bb*Tt*Cc],   g_xl[Bb*Tt*Cc];
__device__ __nv_bfloat16 g_ch[Bb*TCc*CCc], g_cl[Bb*TCc*CCc];
__device__ __nv_bfloat16 g_yh[Bb*Tt*Cc],   g_yl[Bb*Tt*Cc];

// fused projection outputs: [B*T, 4096] = [q | k | v | qc], bf16 hi/lo
__device__ __nv_bfloat16 g_qkvh[Bb*Tt*4*Cc], g_qkvl[Bb*Tt*4*Cc];
// fused cross outputs: [B*TC, 2048] = [kc | vc]
__device__ __nv_bfloat16 g_kvch[Bb*TCc*2*Cc], g_kvcl[Bb*TCc*2*Cc];

// fused transposed weights
__device__ __nv_bfloat16 g_W4_h[4*Cc*Cc], g_W4_l[4*Cc*Cc];     // [4096, 1024]
__device__ __nv_bfloat16 g_W2_h[2*Cc*CCc], g_W2_l[2*Cc*CCc];   // [2048, 512]
__device__ __nv_bfloat16 g_Wp_h[Cc*Cc],   g_Wp_l[Cc*Cc];       // [1024, 1024]
__device__ float g_b4[4*Cc], g_b2[2*Cc];

// ---------------------------------------------------------------------------
// helpers
// ---------------------------------------------------------------------------
__device__ __forceinline__ uint32_t smem_u32(const void* p) {
    uint32_t a;
    asm("{ .reg .u64 t; cvta.to.shared.u64 t, %1; cvt.u32.u64 %0, t; }"
        : "=r"(a) : "l"(p));
    return a;
}
__device__ __forceinline__ float ex2(float x) {
    float y; asm("ex2.approx.ftz.f32 %0, %1;" : "=f"(y) : "f"(x)); return y;
}

#define CP_ASYNC16(dst, src) \
    asm volatile("cp.async.cg.shared.global [%0], [%1], 16;" :: "r"(dst), "l"(src))
#define CP_COMMIT() asm volatile("cp.async.commit_group;" ::: "memory")
#define CP_WAIT0()  asm volatile("cp.async.wait_group 0;" ::: "memory")
#define CP_WAIT1()  asm volatile("cp.async.wait_group 1;" ::: "memory")

#define LDSM_X4(r0, r1, r2, r3, a) \
    asm volatile("ldmatrix.sync.aligned.m8n8.x4.shared.b16 {%0,%1,%2,%3}, [%4];" \
                 : "=r"(r0), "=r"(r1), "=r"(r2), "=r"(r3) : "r"(a))
#define LDSM_X4T(r0, r1, r2, r3, a) \
    asm volatile("ldmatrix.sync.aligned.m8n8.x4.trans.shared.b16 {%0,%1,%2,%3}, [%4];" \
                 : "=r"(r0), "=r"(r1), "=r"(r2), "=r"(r3) : "r"(a))
#define LDSM_X2(r0, r1, a) \
    asm volatile("ldmatrix.sync.aligned.m8n8.x2.shared.b16 {%0,%1}, [%2];" \
                 : "=r"(r0), "=r"(r1) : "r"(a))

#define MMA_BF16(d, a, b) \
    asm volatile("mma.sync.aligned.m16n8k16.row.col.f32.bf16.bf16.f32 " \
                 "{%0,%1,%2,%3}, {%4,%5,%6,%7}, {%8,%9}, {%0,%1,%2,%3};" \
                 : "+f"((d)[0]), "+f"((d)[1]), "+f"((d)[2]), "+f"((d)[3]) \
                 : "r"((a)[0]), "r"((a)[1]), "r"((a)[2]), "r"((a)[3]), \
                   "r"((b)[0]), "r"((b)[1]))

// ---------------------------------------------------------------------------
// fp32 -> bf16 hi/lo split
// ---------------------------------------------------------------------------
__global__ void cvt_kernel(const float* __restrict__ s, __nv_bfloat16* __restrict__ h,
                           __nv_bfloat16* __restrict__ l, int n)
{
    int i = blockIdx.x * blockDim.x + threadIdx.x;
    if (i < n) {
        float v = s[i];
        __nv_bfloat16 hh = __float2bfloat16(v);
        h[i] = hh;
        l[i] = __float2bfloat16(v - __bfloat162float(hh));
    }
}

// all weight transposes in ONE launch: blockIdx.z selects the weight.
__global__ void transpose_all_kernel(
    const float* __restrict__ Wq,  const float* __restrict__ Wk,
    const float* __restrict__ Wv,  const float* __restrict__ Wcq,
    const float* __restrict__ Wck, const float* __restrict__ Wcv,
    const float* __restrict__ Wp)
{
    const int z = blockIdx.z;
    const float* W;
    __nv_bfloat16 *Th, *Tl;
    int K;
    switch (z) {
        case 0: W = Wq;  Th = g_W4_h;                 Tl = g_W4_l;                 K = 1024; break;
        case 1: W = Wk;  Th = g_W4_h + 1024 * 1024;   Tl = g_W4_l + 1024 * 1024;   K = 1024; break;
        case 2: W = Wv;  Th = g_W4_h + 2048 * 1024;   Tl = g_W4_l + 2048 * 1024;   K = 1024; break;
        case 3: W = Wcq; Th = g_W4_h + 3072 * 1024;   Tl = g_W4_l + 3072 * 1024;   K = 1024; break;
        case 4: W = Wck; Th = g_W2_h;                 Tl = g_W2_l;                 K = 512;  break;
        case 5: W = Wcv; Th = g_W2_h + 1024 * 512;    Tl = g_W2_l + 1024 * 512;    K = 512;  break;
        default: W = Wp; Th = g_Wp_h;                 Tl = g_Wp_l;                 K = 1024; break;
    }
    if (K == 512 && blockIdx.y >= 16) return;

    __shared__ float t[32][33];
    const int n0 = blockIdx.x * 32, k0 = blockIdx.y * 32;
    const int tx = threadIdx.x, ty = threadIdx.y;
    #pragma unroll
    for (int i = 0; i < 4; i++)
        t[ty + 8 * i][tx] = W[(size_t)(k0 + ty + 8 * i) * 1024 + n0 + tx];
    __syncthreads();
    #pragma unroll
    for (int i = 0; i < 4; i++) {
        float v = t[tx][ty + 8 * i];
        __nv_bfloat16 h = __float2bfloat16(v);
        __nv_bfloat16 l = __float2bfloat16(v - __bfloat162float(h));
        size_t o = (size_t)(n0 + ty + 8 * i) * K + k0 + tx;
        Th[o] = h; Tl[o] = l;
    }
}

// concat biases into g_b4 (4096) and g_b2 (2048)
__global__ void bias_concat_kernel(
    const float* __restrict__ bq, const float* __restrict__ bk,
    const float* __restrict__ bv, const float* __restrict__ bcq,
    const float* __restrict__ bck, const float* __restrict__ bcv)
{
    int i = blockIdx.x * blockDim.x + threadIdx.x;
    if (i < 4096) {
        const float* s[4] = {bq, bk, bv, bcq};
        g_b4[i] = s[i >> 10][i & 1023];
    } else if (i < 6144) {
        int j = i - 4096;
        g_b2[j] = (j < 1024) ? bck[j] : bcv[j - 1024];
    }
}

// ---------------------------------------------------------------------------
// HMMA GEMM (3xBF16 split). Output: fp32 (outf) OR bf16 hi/lo (outh/outl).
// ---------------------------------------------------------------------------
#define BKg 32
#define LDAg 40
#define TILEB (128 * LDAg * 2)
#define STAGEB (4 * TILEB)
#define GEMM_SMEM (2 * STAGEB)

__global__ __launch_bounds__(256, 1) void hmma_gemm_kernel(
    const __nv_bfloat16* __restrict__ Ah, const __nv_bfloat16* __restrict__ Al,
    const __nv_bfloat16* __restrict__ Bh, const __nv_bfloat16* __restrict__ Bl,
    const float* __restrict__ bias, float* __restrict__ outf,
    __nv_bfloat16* __restrict__ outh, __nv_bfloat16* __restrict__ outl,
    int M, int N, int K)
{
    extern __shared__ char smem[];
    const uint32_t sb = smem_u32(smem);
    const int tid = threadIdx.x;
    const int wid = tid >> 5, lane = tid & 31;
    const int bm = blockIdx.y * 128, bn = blockIdx.x * 128;

    const int wr = wid & 3;
    const int wc = wid >> 2;

    const char* gsrc[4] = {
        (const char*)(Ah + (size_t)bm * K),
        (const char*)(Al + (size_t)bm * K),
        (const char*)(Bh + (size_t)bn * K),
        (const char*)(Bl + (size_t)bn * K) };

    const int row0 = tid >> 2, c16a = tid & 3;
    const int row1 = (tid + 256) >> 2;

    auto load_chunk = [&](int kb, int st) {
        const uint32_t sdst = sb + st * STAGEB;
        #pragma unroll
        for (int m = 0; m < 4; m++) {
            const char* g = gsrc[m] + (size_t)kb * (BKg * 2);
            uint32_t d = sdst + m * TILEB;
            CP_ASYNC16(d + row0 * (LDAg * 2) + c16a * 16,
                       g + (size_t)row0 * (K * 2) + c16a * 16);
            CP_ASYNC16(d + row1 * (LDAg * 2) + c16a * 16,
                       g + (size_t)row1 * (K * 2) + c16a * 16);
        }
    };

    float acc[2][8][4] = {};

    const int nchunks = K / BKg;
    load_chunk(0, 0);
    CP_COMMIT();

    for (int kb = 0; kb < nchunks; kb++) {
        const int st = kb & 1;
        if (kb + 1 < nchunks) { load_chunk(kb + 1, st ^ 1); CP_COMMIT(); CP_WAIT1(); }
        else                  { CP_WAIT0(); }
        __syncthreads();

        const uint32_t ah = sb + st * STAGEB;
        const uint32_t al = ah + TILEB;
        const uint32_t bh = ah + 2 * TILEB;
        const uint32_t bl = ah + 3 * TILEB;

        #pragma unroll
        for (int ks = 0; ks < 2; ks++) {
            const int k0 = ks * 16;
            uint32_t Ahf[2][4], Alf[2][4], Bhf[8][2], Blf[8][2];

            #pragma unroll
            for (int mt = 0; mt < 2; mt++) {
                const int arow = wr * 32 + mt * 16 + (lane & 15);
                const int acol = k0 + (lane >> 4) * 8;
                const uint32_t ao = (uint32_t)(arow * LDAg + acol) * 2;
                LDSM_X4(Ahf[mt][0], Ahf[mt][1], Ahf[mt][2], Ahf[mt][3], ah + ao);
                LDSM_X4(Alf[mt][0], Alf[mt][1], Alf[mt][2], Alf[mt][3], al + ao);
            }
            #pragma unroll
            for (int nt = 0; nt < 8; nt++) {
                const int brow = wc * 64 + nt * 8 + (lane & 7);
                const int bcol = k0 + ((lane >> 3) & 1) * 8;
                const uint32_t bo = (uint32_t)(brow * LDAg + bcol) * 2;
                LDSM_X2(Bhf[nt][0], Bhf[nt][1], bh + bo);
                LDSM_X2(Blf[nt][0], Blf[nt][1], bl + bo);
            }

            #pragma unroll
            for (int mt = 0; mt < 2; mt++)
                #pragma unroll
                for (int nt = 0; nt < 8; nt++) {
                    MMA_BF16(acc[mt][nt], Ahf[mt], Bhf[nt]);
                    MMA_BF16(acc[mt][nt], Ahf[mt], Blf[nt]);
                    MMA_BF16(acc[mt][nt], Alf[mt], Bhf[nt]);
                }
        }
        __syncthreads();
    }

    const int crow = lane >> 2, ccol = (lane & 3) * 2;
    #pragma unroll
    for (int mt = 0; mt < 2; mt++) {
        #pragma unroll
        for (int half = 0; half < 2; half++) {
            const int r = bm + wr * 32 + mt * 16 + crow + half * 8;
            #pragma unroll
            for (int nt = 0; nt < 8; nt++) {
                const int c = bn + wc * 64 + nt * 8 + ccol;
                float2 b2 = *(const float2*)&bias[c];
                float vx = acc[mt][nt][half * 2 + 0] + b2.x;
                float vy = acc[mt][nt][half * 2 + 1] + b2.y;
                if (outf) {
                    float2 v; v.x = vx; v.y = vy;
                    *(float2*)&outf[(size_t)r * N + c] = v;
                } else {
                    __nv_bfloat162 hh = __float22bfloat162_rn(make_float2(vx, vy));
                    float2 hf = __bfloat1622float2(hh);
                    __nv_bfloat162 ll = __float22bfloat162_rn(
                        make_float2(vx - hf.x, vy - hf.y));
                    *(uint32_t*)&outh[(size_t)r * N + c] = *(uint32_t*)&hh;
                    *(uint32_t*)&outl[(size_t)r * N + c] = *(uint32_t*)&ll;
                }
            }
        }
    }
}

// ---------------------------------------------------------------------------
// HMMA flash attention with strided Q/KV sources (fused projection buffers).
// ---------------------------------------------------------------------------
#define APB 144
#define QTILE (128 * APB)
#define KVTILE (64 * APB)
#define KVSTAGE (4 * KVTILE)
#define ATT_SMEM (2 * QTILE + 2 * KVSTAGE)

__global__ __launch_bounds__(256, 1) void attn_mma_kernel(
    const __nv_bfloat16* __restrict__ Qh, const __nv_bfloat16* __restrict__ Ql,
    const __nv_bfloat16* __restrict__ Kh, const __nv_bfloat16* __restrict__ Kl,
    const __nv_bfloat16* __restrict__ Vh, const __nv_bfloat16* __restrict__ Vl,
    float* __restrict__ Y, int Tq, int Tk, int ldq, int ldkv,
    int causal, int accumulate)
{
    extern __shared__ char smem[];
    const uint32_t sb = smem_u32(smem);
    const int tid = threadIdx.x, wid = tid >> 5, lane = tid & 31;
    // heavy (large qt) blocks first for causal wave balance
    const int qt = causal ? (gridDim.x - 1 - blockIdx.x) : blockIdx.x;
    const int h = blockIdx.y, b = blockIdx.z;
    const int q0 = qt * 128;

    const size_t qoff = ((size_t)b * Tq + q0) * ldq + h * Dd;
    const size_t koff = ((size_t)b * Tk) * ldkv + h * Dd;

    const uint32_t sQh = sb, sQl = sb + QTILE;
    const uint32_t sKV = sb + 2 * QTILE;

    // ---- load Q (hi/lo) ----
    {
        const char* gq[2] = { (const char*)(Qh + qoff), (const char*)(Ql + qoff) };
        #pragma unroll
        for (int m = 0; m < 2; m++) {
            uint32_t dst = m ? sQl : sQh;
            #pragma unroll
            for (int it = 0; it < 4; it++) {
                int idx = it * 256 + tid;
                int r = idx >> 3, c = idx & 7;
                CP_ASYNC16(dst + r * APB + c * 16,
                           gq[m] + (size_t)r * (ldq * 2) + c * 16);
            }
        }
    }
    CP_COMMIT();

    const char* gk[4] = {
        (const char*)(Kh + koff), (const char*)(Kl + koff),
        (const char*)(Vh + koff), (const char*)(Vl + koff) };
    auto load_kv = [&](int kt, int st) {
        uint32_t dst = sKV + st * KVSTAGE;
        #pragma unroll
        for (int m = 0; m < 4; m++) {
            #pragma unroll
            for (int it = 0; it < 2; it++) {
                int idx = it * 256 + tid;
                int r = idx >> 3, c = idx & 7;
                CP_ASYNC16(dst + m * KVTILE + r * APB + c * 16,
                           gk[m] + ((size_t)(kt * 64 + r)) * (ldkv * 2) + c * 16);
            }
        }
    };

    load_kv(0, 0);
    CP_COMMIT();
    CP_WAIT1();
    __syncthreads();

    uint32_t Qhf[4][4], Qlf[4][4];
    {
        const int r = wid * 16 + (lane & 7) + 8 * ((lane >> 3) & 1);
        const int cb = 8 * (lane >> 4);
        #pragma unroll
        for (int kc = 0; kc < 4; kc++) {
            const uint32_t off = (uint32_t)r * APB + (kc * 16 + cb) * 2;
            LDSM_X4(Qhf[kc][0], Qhf[kc][1], Qhf[kc][2], Qhf[kc][3], sQh + off);
            LDSM_X4(Qlf[kc][0], Qlf[kc][1], Qlf[kc][2], Qlf[kc][3], sQl + off);
        }
    }

    float o[8][4] = {};
    float m0 = -1e30f, m1 = -1e30f, l0 = 0.f, l1 = 0.f;
    const int crow = lane >> 2, ccol = (lane & 3) * 2;
    const int wrow = q0 + wid * 16;
    const int ntt = causal ? (2 * qt + 2) : (Tk / 64);
    const float cs = 0.125f * 1.44269504089f;

    for (int kt = 0; kt < ntt; kt++) {
        const int st = kt & 1;
        if (kt + 1 < ntt) { load_kv(kt + 1, st ^ 1); CP_COMMIT(); CP_WAIT1(); }
        else              { CP_WAIT0(); }
        __syncthreads();

        const int k0 = kt * 64;
        const bool active = !causal || (k0 <= wrow + 15);
        if (active) {
            const uint32_t sKhT = sKV + st * KVSTAGE;
            const uint32_t sKlT = sKhT + KVTILE;
            const uint32_t sVhT = sKhT + 2 * KVTILE;
            const uint32_t sVlT = sKhT + 3 * KVTILE;

            float s[8][4] = {};
            {
                const int krow = (lane & 7) + 8 * (lane >> 4);
                const int kcolb = 8 * ((lane >> 3) & 1);
                #pragma unroll
                for (int kc = 0; kc < 4; kc++) {
                    uint32_t bh[8][2], bl[8][2];
                    #pragma unroll
                    for (int np = 0; np < 4; np++) {
                        const uint32_t off =
                            (uint32_t)(np * 16 + krow) * APB + (kc * 16 + kcolb) * 2;
                        LDSM_X4(bh[2*np][0], bh[2*np][1], bh[2*np+1][0], bh[2*np+1][1],
                                sKhT + off);
                        LDSM_X4(bl[2*np][0], bl[2*np][1], bl[2*np+1][0], bl[2*np+1][1],
                                sKlT + off);
                    }
                    #pragma unroll
                    for (int nt = 0; nt < 8; nt++) {
                        MMA_BF16(s[nt], Qhf[kc], bh[nt]);
                        MMA_BF16(s[nt], Qhf[kc], bl[nt]);
                        MMA_BF16(s[nt], Qlf[kc], bh[nt]);
                    }
                }
            }

            const bool dm = causal && (k0 + 63 > wrow);
            float zx0 = -1e30f, zx1 = -1e30f;
            #pragma unroll
            for (int nt = 0; nt < 8; nt++) {
                #pragma unroll
                for (int r = 0; r < 4; r++) {
                    float z = s[nt][r] * cs;
                    if (dm) {
                        const int col = k0 + nt * 8 + ccol + (r & 1);
                        const int row = wrow + crow + 8 * (r >> 1);
                        if (col > row) z = -1e30f;
                    }
                    s[nt][r] = z;
                }
                zx0 = fmaxf(zx0, fmaxf(s[nt][0], s[nt][1]));
                zx1 = fmaxf(zx1, fmaxf(s[nt][2], s[nt][3]));
            }
            zx0 = fmaxf(zx0, __shfl_xor_sync(0xffffffffu, zx0, 1));
            zx0 = fmaxf(zx0, __shfl_xor_sync(0xffffffffu, zx0, 2));
            zx1 = fmaxf(zx1, __shfl_xor_sync(0xffffffffu, zx1, 1));
            zx1 = fmaxf(zx1, __shfl_xor_sync(0xffffffffu, zx1, 2));
            const float mn0 = fmaxf(m0, zx0), mn1 = fmaxf(m1, zx1);
            const float a0 = ex2(m0 - mn0), a1 = ex2(m1 - mn1);
            m0 = mn0; m1 = mn1;

            float ps0 = 0.f, ps1 = 0.f;
            uint32_t pah[4][4], pal[4][4];
            #pragma unroll
            for (int nt = 0; nt < 8; nt++) {
                const float p0 = ex2(s[nt][0] - mn0), p1 = ex2(s[nt][1] - mn0);
                const float p2 = ex2(s[nt][2] - mn1), p3 = ex2(s[nt][3] - mn1);
                ps0 += p0 + p1; ps1 += p2 + p3;
                __nv_bfloat162 h01 = __float22bfloat162_rn(make_float2(p0, p1));
                __nv_bfloat162 h23 = __float22bfloat162_rn(make_float2(p2, p3));
                float2 f01 = __bfloat1622float2(h01);
                float2 f23 = __bfloat1622float2(h23);
                __nv_bfloat162 q01 = __float22bfloat162_rn(
                    make_float2(p0 - f01.x, p1 - f01.y));
                __nv_bfloat162 q23 = __float22bfloat162_rn(
                    make_float2(p2 - f23.x, p3 - f23.y));
                pah[nt >> 1][(nt & 1) * 2 + 0] = *(uint32_t*)&h01;
                pah[nt >> 1][(nt & 1) * 2 + 1] = *(uint32_t*)&h23;
                pal[nt >> 1][(nt & 1) * 2 + 0] = *(uint32_t*)&q01;
                pal[nt >> 1][(nt & 1) * 2 + 1] = *(uint32_t*)&q23;
            }
            l0 = l0 * a0 + ps0;
            l1 = l1 * a1 + ps1;
            #pragma unroll
            for (int nt = 0; nt < 8; nt++) {
                o[nt][0] *= a0; o[nt][1] *= a0;
                o[nt][2] *= a1; o[nt][3] *= a1;
            }

            {
                const int vrl = (lane & 7) + 8 * ((lane >> 3) & 1);
                const int vcb = 8 * (lane >> 4);
                #pragma unroll
                for (int kc = 0; kc < 4; kc++) {
                    uint32_t vh[8][2], vl[8][2];
                    #pragma unroll
                    for (int dp = 0; dp < 4; dp++) {
                        const uint32_t off =
                            (uint32_t)(kc * 16 + vrl) * APB + (dp * 16 + vcb) * 2;
                        LDSM_X4T(vh[2*dp][0], vh[2*dp][1], vh[2*dp+1][0], vh[2*dp+1][1],
                                 sVhT + off);
                        LDSM_X4T(vl[2*dp][0], vl[2*dp][1], vl[2*dp+1][0], vl[2*dp+1][1],
                                 sVlT + off);
                    }
                    #pragma unroll
                    for (int nt = 0; nt < 8; nt++) {
                        MMA_BF16(o[nt], pah[kc], vh[nt]);
                        MMA_BF16(o[nt], pal[kc], vh[nt]);
                        MMA_BF16(o[nt], pah[kc], vl[nt]);
                    }
                }
            }
        }
        __syncthreads();
    }

    l0 += __shfl_xor_sync(0xffffffffu, l0, 1);
    l0 += __shfl_xor_sync(0xffffffffu, l0, 2);
    l1 += __shfl_xor_sync(0xffffffffu, l1, 1);
    l1 += __shfl_xor_sync(0xffffffffu, l1, 2);
    const float i0 = 1.f / l0, i1 = 1.f / l1;

    const int r0 = q0 + wid * 16 + crow;
    float* y0 = Y + ((size_t)b * Tq + r0) * Cc + h * Dd;
    float* y1 = y0 + 8 * Cc;
    #pragma unroll
    for (int nt = 0; nt < 8; nt++) {
        const int c = nt * 8 + ccol;
        float2 v0 = make_float2(o[nt][0] * i0, o[nt][1] * i0);
        float2 v1 = make_float2(o[nt][2] * i1, o[nt][3] * i1);
        if (accumulate) {
            float2 u0 = *(float2*)&y0[c], u1 = *(float2*)&y1[c];
            v0.x += u0.x; v0.y += u0.y; v1.x += u1.x; v1.y += u1.y;
        }
        *(float2*)&y0[c] = v0;
        *(float2*)&y1[c] = v1;
    }
}

// ---------------------------------------------------------------------------

extern "C" void kernel_launch(void* const* d_in, const int* in_sizes, int n_in,
                              void* d_out, int out_size)
{
    const float* x     = (const float*)d_in[0];
    const float* cross = (const float*)d_in[1];
    const float* Wk  = (const float*)d_in[2];   const float* bk  = (const float*)d_in[3];
    const float* Wq  = (const float*)d_in[4];   const float* bq  = (const float*)d_in[5];
    const float* Wv  = (const float*)d_in[6];   const float* bv  = (const float*)d_in[7];
    const float* Wck = (const float*)d_in[8];   const float* bck = (const float*)d_in[9];
    const float* Wcq = (const float*)d_in[10];  const float* bcq = (const float*)d_in[11];
    const float* Wcv = (const float*)d_in[12];  const float* bcv = (const float*)d_in[13];
    const float* Wp  = (const float*)d_in[14];  const float* bp  = (const float*)d_in[15];
    float* out = (float*)d_out;

    float* y;     cudaGetSymbolAddress((void**)&y, g_y);
    __nv_bfloat16 *xh, *xl, *ch, *cl, *yh, *yl;
    cudaGetSymbolAddress((void**)&xh, g_xh); cudaGetSymbolAddress((void**)&xl, g_xl);
    cudaGetSymbolAddress((void**)&ch, g_ch); cudaGetSymbolAddress((void**)&cl, g_cl);
    cudaGetSymbolAddress((void**)&yh, g_yh); cudaGetSymbolAddress((void**)&yl, g_yl);

    __nv_bfloat16 *qkvh, *qkvl, *kvch, *kvcl;
    cudaGetSymbolAddress((void**)&qkvh, g_qkvh); cudaGetSymbolAddress((void**)&qkvl, g_qkvl);
    cudaGetSymbolAddress((void**)&kvch, g_kvch); cudaGetSymbolAddress((void**)&kvcl, g_kvcl);

    __nv_bfloat16 *w4h, *w4l, *w2h, *w2l, *wph, *wpl;
    cudaGetSymbolAddress((void**)&w4h, g_W4_h); cudaGetSymbolAddress((void**)&w4l, g_W4_l);
    cudaGetSymbolAddress((void**)&w2h, g_W2_h); cudaGetSymbolAddress((void**)&w2l, g_W2_l);
    cudaGetSymbolAddress((void**)&wph, g_Wp_h); cudaGetSymbolAddress((void**)&wpl, g_Wp_l);
    float *b4, *b2;
    cudaGetSymbolAddress((void**)&b4, g_b4); cudaGetSymbolAddress((void**)&b2, g_b2);

    // prep
    transpose_all_kernel<<<dim3(32, 32, 7), dim3(32, 8)>>>(Wq, Wk, Wv, Wcq, Wck, Wcv, Wp);
    bias_concat_kernel<<<24, 256>>>(bq, bk, bv, bcq, bck, bcv);
    const int nx = Bb * Tt * Cc, nc = Bb * TCc * CCc;
    cvt_kernel<<<(nx + 255) / 256, 256>>>(x, xh, xl, nx);
    cvt_kernel<<<(nc + 255) / 256, 256>>>(cross, ch, cl, nc);

    cudaFuncSetAttribute(hmma_gemm_kernel, cudaFuncAttributeMaxDynamicSharedMemorySize, GEMM_SMEM);
    const dim3 gblk(256);

    // fused projections: [4096,1024] @ [4096,1024]^T -> [4096, 4096]
    hmma_gemm_kernel<<<dim3(32, 32), gblk, GEMM_SMEM>>>(
        xh, xl, w4h, w4l, b4, nullptr, qkvh, qkvl, Bb*Tt, 4*Cc, Cc);
    // fused cross: [1024,512] @ [2048,512]^T -> [1024, 2048]
    hmma_gemm_kernel<<<dim3(16, 8), gblk, GEMM_SMEM>>>(
        ch, cl, w2h, w2l, b2, nullptr, kvch, kvcl, Bb*TCc, 2*Cc, CCc);

    cudaFuncSetAttribute(attn_mma_kernel, cudaFuncAttributeMaxDynamicSharedMemorySize, ATT_SMEM);
    const dim3 ga(Tt / 128, Hh, Bb);
    // self: q at col 0, k at 1024, v at 2048 of qkv (stride 4096)
    attn_mma_kernel<<<ga, gblk, ATT_SMEM>>>(
        qkvh, qkvl, qkvh + 1024, qkvl + 1024, qkvh + 2048, qkvl + 2048,
        y, Tt, Tt, 4*Cc, 4*Cc, 1, 0);
    // cross: qc at col 3072 (stride 4096); kc/vc in kvc (stride 2048)
    attn_mma_kernel<<<ga, gblk, ATT_SMEM>>>(
        qkvh + 3072, qkvl + 3072, kvch, kvcl, kvch + 1024, kvcl + 1024,
        y, Tt, TCc, 4*Cc, 2*Cc, 0, 1);

    // output projection
    cvt_kernel<<<(nx + 255) / 256, 256>>>(y, yh, yl, nx);
    hmma_gemm_kernel<<<dim3(8, 32), gblk, GEMM_SMEM>>>(
        yh, yl, wph, wpl, bp, out, nullptr, nullptr, Bb*Tt, Cc, Cc);
}

// round 7
// speedup vs baseline: 2.9336x; 1.0415x over previous
#include <cuda_runtime.h>
#include <cuda_bf16.h>
#include <cstdint>
#include <math.h>

#define Bb 2
#define Tt 2048
#define TCc 512
#define Cc 1024
#define CCc 512
#define Hh 16
#define Dd 64

// ---------------------------------------------------------------------------
// Scratch (__device__ globals; no allocation allowed)
// ---------------------------------------------------------------------------
__device__ __nv_bfloat16 g_xh[Bb*Tt*Cc],   g_xl[Bb*Tt*Cc];
__device__ __nv_bfloat16 g_ch[Bb*TCc*CCc], g_cl[Bb*TCc*CCc];
__device__ __nv_bfloat16 g_yh[Bb*Tt*Cc],   g_yl[Bb*Tt*Cc];

// fused projection outputs: [B*T, 4096] = [q | k | v | qc], bf16 hi/lo
__device__ __nv_bfloat16 g_qkvh[Bb*Tt*4*Cc], g_qkvl[Bb*Tt*4*Cc];
// fused cross outputs: [B*TC, 2048] = [kc | vc]
__device__ __nv_bfloat16 g_kvch[Bb*TCc*2*Cc], g_kvcl[Bb*TCc*2*Cc];

// fused transposed weights
__device__ __nv_bfloat16 g_W4_h[4*Cc*Cc], g_W4_l[4*Cc*Cc];
__device__ __nv_bfloat16 g_W2_h[2*Cc*CCc], g_W2_l[2*Cc*CCc];
__device__ __nv_bfloat16 g_Wp_h[Cc*Cc],   g_Wp_l[Cc*Cc];
__device__ float g_b4[4*Cc], g_b2[2*Cc];

// ---------------------------------------------------------------------------
// helpers
// ---------------------------------------------------------------------------
__device__ __forceinline__ uint32_t smem_u32(const void* p) {
    uint32_t a;
    asm("{ .reg .u64 t; cvta.to.shared.u64 t, %1; cvt.u32.u64 %0, t; }"
        : "=r"(a) : "l"(p));
    return a;
}
__device__ __forceinline__ float ex2(float x) {
    float y; asm("ex2.approx.ftz.f32 %0, %1;" : "=f"(y) : "f"(x)); return y;
}

#define CP_ASYNC16(dst, src) \
    asm volatile("cp.async.cg.shared.global [%0], [%1], 16;" :: "r"(dst), "l"(src))
#define CP_COMMIT() asm volatile("cp.async.commit_group;" ::: "memory")
#define CP_WAIT0()  asm volatile("cp.async.wait_group 0;" ::: "memory")
#define CP_WAIT1()  asm volatile("cp.async.wait_group 1;" ::: "memory")

#define LDSM_X4(r0, r1, r2, r3, a) \
    asm volatile("ldmatrix.sync.aligned.m8n8.x4.shared.b16 {%0,%1,%2,%3}, [%4];" \
                 : "=r"(r0), "=r"(r1), "=r"(r2), "=r"(r3) : "r"(a))
#define LDSM_X4T(r0, r1, r2, r3, a) \
    asm volatile("ldmatrix.sync.aligned.m8n8.x4.trans.shared.b16 {%0,%1,%2,%3}, [%4];" \
                 : "=r"(r0), "=r"(r1), "=r"(r2), "=r"(r3) : "r"(a))

#define MMA_BF16(d, a, b) \
    asm volatile("mma.sync.aligned.m16n8k16.row.col.f32.bf16.bf16.f32 " \
                 "{%0,%1,%2,%3}, {%4,%5,%6,%7}, {%8,%9}, {%0,%1,%2,%3};" \
                 : "+f"((d)[0]), "+f"((d)[1]), "+f"((d)[2]), "+f"((d)[3]) \
                 : "r"((a)[0]), "r"((a)[1]), "r"((a)[2]), "r"((a)[3]), \
                   "r"((b)[0]), "r"((b)[1]))

// ---------------------------------------------------------------------------
// prep kernels
// ---------------------------------------------------------------------------
__global__ void cvt_kernel(const float* __restrict__ s, __nv_bfloat16* __restrict__ h,
                           __nv_bfloat16* __restrict__ l, int n)
{
    int i = blockIdx.x * blockDim.x + threadIdx.x;
    if (i < n) {
        float v = s[i];
        __nv_bfloat16 hh = __float2bfloat16(v);
        h[i] = hh;
        l[i] = __float2bfloat16(v - __bfloat162float(hh));
    }
}

__global__ void transpose_all_kernel(
    const float* __restrict__ Wq,  const float* __restrict__ Wk,
    const float* __restrict__ Wv,  const float* __restrict__ Wcq,
    const float* __restrict__ Wck, const float* __restrict__ Wcv,
    const float* __restrict__ Wp)
{
    const int z = blockIdx.z;
    const float* W;
    __nv_bfloat16 *Th, *Tl;
    int K;
    switch (z) {
        case 0: W = Wq;  Th = g_W4_h;               Tl = g_W4_l;               K = 1024; break;
        case 1: W = Wk;  Th = g_W4_h + 1024 * 1024; Tl = g_W4_l + 1024 * 1024; K = 1024; break;
        case 2: W = Wv;  Th = g_W4_h + 2048 * 1024; Tl = g_W4_l + 2048 * 1024; K = 1024; break;
        case 3: W = Wcq; Th = g_W4_h + 3072 * 1024; Tl = g_W4_l + 3072 * 1024; K = 1024; break;
        case 4: W = Wck; Th = g_W2_h;               Tl = g_W2_l;               K = 512;  break;
        case 5: W = Wcv; Th = g_W2_h + 1024 * 512;  Tl = g_W2_l + 1024 * 512;  K = 512;  break;
        default: W = Wp; Th = g_Wp_h;               Tl = g_Wp_l;               K = 1024; break;
    }
    if (K == 512 && blockIdx.y >= 16) return;

    __shared__ float t[32][33];
    const int n0 = blockIdx.x * 32, k0 = blockIdx.y * 32;
    const int tx = threadIdx.x, ty = threadIdx.y;
    #pragma unroll
    for (int i = 0; i < 4; i++)
        t[ty + 8 * i][tx] = W[(size_t)(k0 + ty + 8 * i) * 1024 + n0 + tx];
    __syncthreads();
    #pragma unroll
    for (int i = 0; i < 4; i++) {
        float v = t[tx][ty + 8 * i];
        __nv_bfloat16 h = __float2bfloat16(v);
        __nv_bfloat16 l = __float2bfloat16(v - __bfloat162float(h));
        size_t o = (size_t)(n0 + ty + 8 * i) * K + k0 + tx;
        Th[o] = h; Tl[o] = l;
    }
}

__global__ void bias_concat_kernel(
    const float* __restrict__ bq, const float* __restrict__ bk,
    const float* __restrict__ bv, const float* __restrict__ bcq,
    const float* __restrict__ bck, const float* __restrict__ bcv)
{
    int i = blockIdx.x * blockDim.x + threadIdx.x;
    if (i < 4096) {
        const float* s[4] = {bq, bk, bv, bcq};
        g_b4[i] = s[i >> 10][i & 1023];
    } else if (i < 6144) {
        int j = i - 4096;
        g_b2[j] = (j < 1024) ? bck[j] : bcv[j - 1024];
    }
}

// ---------------------------------------------------------------------------
// HMMA GEMM (3xBF16 split), 3-stage cp.async pipeline, one sync per chunk.
// ---------------------------------------------------------------------------
#define BKg 32
#define LDAg 40
#define TILEB (128 * LDAg * 2)
#define STAGEB (4 * TILEB)
#define GEMM_SMEM (3 * STAGEB)          // 122880

__global__ __launch_bounds__(256, 1) void hmma_gemm_kernel(
    const __nv_bfloat16* __restrict__ Ah, const __nv_bfloat16* __restrict__ Al,
    const __nv_bfloat16* __restrict__ Bh, const __nv_bfloat16* __restrict__ Bl,
    const float* __restrict__ bias, float* __restrict__ outf,
    __nv_bfloat16* __restrict__ outh, __nv_bfloat16* __restrict__ outl,
    int M, int N, int K)
{
    extern __shared__ char smem[];
    const uint32_t sb = smem_u32(smem);
    const int tid = threadIdx.x;
    const int wid = tid >> 5, lane = tid & 31;
    const int bm = blockIdx.y * 128, bn = blockIdx.x * 128;

    const int wr = wid & 3;
    const int wc = wid >> 2;

    const char* gsrc[4] = {
        (const char*)(Ah + (size_t)bm * K),
        (const char*)(Al + (size_t)bm * K),
        (const char*)(Bh + (size_t)bn * K),
        (const char*)(Bl + (size_t)bn * K) };

    const int row0 = tid >> 2, c16a = tid & 3;
    const int row1 = (tid + 256) >> 2;

    auto load_chunk = [&](int kb, int st) {
        const uint32_t sdst = sb + st * STAGEB;
        #pragma unroll
        for (int m = 0; m < 4; m++) {
            const char* g = gsrc[m] + (size_t)kb * (BKg * 2);
            uint32_t d = sdst + m * TILEB;
            CP_ASYNC16(d + row0 * (LDAg * 2) + c16a * 16,
                       g + (size_t)row0 * (K * 2) + c16a * 16);
            CP_ASYNC16(d + row1 * (LDAg * 2) + c16a * 16,
                       g + (size_t)row1 * (K * 2) + c16a * 16);
        }
    };

    float acc[2][8][4] = {};

    const int nchunks = K / BKg;
    load_chunk(0, 0); CP_COMMIT();
    load_chunk(1, 1); CP_COMMIT();

    for (int kb = 0; kb < nchunks; kb++) {
        const int st = kb % 3;
        if (kb + 1 < nchunks) { CP_WAIT1(); } else { CP_WAIT0(); }
        __syncthreads();
        if (kb + 2 < nchunks) { load_chunk(kb + 2, (kb + 2) % 3); CP_COMMIT(); }

        const uint32_t ah = sb + st * STAGEB;
        const uint32_t al = ah + TILEB;
        const uint32_t bh = ah + 2 * TILEB;
        const uint32_t bl = ah + 3 * TILEB;

        #pragma unroll
        for (int ks = 0; ks < 2; ks++) {
            const int k0 = ks * 16;
            uint32_t Ahf[2][4], Alf[2][4], Bhf[8][2], Blf[8][2];

            #pragma unroll
            for (int mt = 0; mt < 2; mt++) {
                const int arow = wr * 32 + mt * 16 + (lane & 15);
                const int acol = k0 + (lane >> 4) * 8;
                const uint32_t ao = (uint32_t)(arow * LDAg + acol) * 2;
                LDSM_X4(Ahf[mt][0], Ahf[mt][1], Ahf[mt][2], Ahf[mt][3], ah + ao);
                LDSM_X4(Alf[mt][0], Alf[mt][1], Alf[mt][2], Alf[mt][3], al + ao);
            }
            // B: one x4 per pair of n8 tiles (lanes 0-7:n0-7/k0, 8-15:n0-7/k8,
            // 16-23:n8-15/k0, 24-31:n8-15/k8)
            #pragma unroll
            for (int np = 0; np < 4; np++) {
                const int brow = wc * 64 + np * 16 + ((lane >> 4) & 1) * 8 + (lane & 7);
                const int bcol = k0 + ((lane >> 3) & 1) * 8;
                const uint32_t bo = (uint32_t)(brow * LDAg + bcol) * 2;
                LDSM_X4(Bhf[2*np][0], Bhf[2*np][1], Bhf[2*np+1][0], Bhf[2*np+1][1], bh + bo);
                LDSM_X4(Blf[2*np][0], Blf[2*np][1], Blf[2*np+1][0], Blf[2*np+1][1], bl + bo);
            }

            #pragma unroll
            for (int mt = 0; mt < 2; mt++)
                #pragma unroll
                for (int nt = 0; nt < 8; nt++) {
                    MMA_BF16(acc[mt][nt], Ahf[mt], Bhf[nt]);
                    MMA_BF16(acc[mt][nt], Ahf[mt], Blf[nt]);
                    MMA_BF16(acc[mt][nt], Alf[mt], Bhf[nt]);
                }
        }
    }

    const int crow = lane >> 2, ccol = (lane & 3) * 2;
    #pragma unroll
    for (int mt = 0; mt < 2; mt++) {
        #pragma unroll
        for (int half = 0; half < 2; half++) {
            const int r = bm + wr * 32 + mt * 16 + crow + half * 8;
            #pragma unroll
            for (int nt = 0; nt < 8; nt++) {
                const int c = bn + wc * 64 + nt * 8 + ccol;
                float2 b2 = *(const float2*)&bias[c];
                float vx = acc[mt][nt][half * 2 + 0] + b2.x;
                float vy = acc[mt][nt][half * 2 + 1] + b2.y;
                if (outf) {
                    float2 v; v.x = vx; v.y = vy;
                    *(float2*)&outf[(size_t)r * N + c] = v;
                } else {
                    __nv_bfloat162 hh = __float22bfloat162_rn(make_float2(vx, vy));
                    float2 hf = __bfloat1622float2(hh);
                    __nv_bfloat162 ll = __float22bfloat162_rn(
                        make_float2(vx - hf.x, vy - hf.y));
                    *(uint32_t*)&outh[(size_t)r * N + c] = *(uint32_t*)&hh;
                    *(uint32_t*)&outl[(size_t)r * N + c] = *(uint32_t*)&ll;
                }
            }
        }
    }
}

// ---------------------------------------------------------------------------
// Fused HMMA flash attention: phase 0 = causal self, phase 1 = cross.
// Self result parked in smem; cross epilogue adds and writes bf16 hi/lo.
// ---------------------------------------------------------------------------
#define APB 144
#define QTILE (128 * APB)               // 18432
#define KVTILE (64 * APB)               // 9216
#define KVSTAGE (4 * KVTILE)            // 36864
#define SO_OFF (2 * QTILE + 2 * KVSTAGE)
#define ATT_SMEM (SO_OFF + 128 * 68 * 4)   // 145408

__global__ __launch_bounds__(256, 1) void attn_fused_kernel(
    const __nv_bfloat16* __restrict__ qkvh, const __nv_bfloat16* __restrict__ qkvl,
    const __nv_bfloat16* __restrict__ kvch, const __nv_bfloat16* __restrict__ kvcl,
    __nv_bfloat16* __restrict__ Yh, __nv_bfloat16* __restrict__ Yl)
{
    extern __shared__ char smem[];
    const uint32_t sb = smem_u32(smem);
    float* sO = (float*)(smem + SO_OFF);
    const int tid = threadIdx.x, wid = tid >> 5, lane = tid & 31;
    const int qt = gridDim.x - 1 - blockIdx.x;   // heavy first
    const int h = blockIdx.y, b = blockIdx.z;
    const int q0 = qt * 128;

    const uint32_t sQh = sb, sQl = sb + QTILE;
    const uint32_t sKV = sb + 2 * QTILE;

    const int crow = lane >> 2, ccol = (lane & 3) * 2;
    const int rloc = wid * 16 + crow;
    const int wrow = q0 + wid * 16;
    const float cs = 0.125f * 1.44269504089f;

    for (int phase = 0; phase < 2; phase++) {
        const bool causal = (phase == 0);
        const int ldq  = 4 * Cc;
        const int ldkv = causal ? 4 * Cc : 2 * Cc;
        const int ntt  = causal ? (2 * qt + 2) : (TCc / 64);

        const __nv_bfloat16* Qhp = causal ? qkvh            : qkvh + 3072;
        const __nv_bfloat16* Qlp = causal ? qkvl            : qkvl + 3072;
        const __nv_bfloat16* Khp = causal ? qkvh + 1024     : kvch;
        const __nv_bfloat16* Klp = causal ? qkvl + 1024     : kvcl;
        const __nv_bfloat16* Vhp = causal ? qkvh + 2048     : kvch + 1024;
        const __nv_bfloat16* Vlp = causal ? qkvl + 2048     : kvcl + 1024;

        const size_t qoff = ((size_t)b * Tt + q0) * ldq + h * Dd;
        const size_t koff = ((size_t)b * (causal ? Tt : TCc)) * ldkv + h * Dd;

        // ---- load Q ----
        {
            const char* gq[2] = { (const char*)(Qhp + qoff), (const char*)(Qlp + qoff) };
            #pragma unroll
            for (int m = 0; m < 2; m++) {
                uint32_t dst = m ? sQl : sQh;
                #pragma unroll
                for (int it = 0; it < 4; it++) {
                    int idx = it * 256 + tid;
                    int r = idx >> 3, c = idx & 7;
                    CP_ASYNC16(dst + r * APB + c * 16,
                               gq[m] + (size_t)r * (ldq * 2) + c * 16);
                }
            }
        }
        CP_COMMIT();

        const char* gk[4] = {
            (const char*)(Khp + koff), (const char*)(Klp + koff),
            (const char*)(Vhp + koff), (const char*)(Vlp + koff) };
        auto load_kv = [&](int kt, int st) {
            uint32_t dst = sKV + st * KVSTAGE;
            #pragma unroll
            for (int m = 0; m < 4; m++) {
                #pragma unroll
                for (int it = 0; it < 2; it++) {
                    int idx = it * 256 + tid;
                    int r = idx >> 3, c = idx & 7;
                    CP_ASYNC16(dst + m * KVTILE + r * APB + c * 16,
                               gk[m] + ((size_t)(kt * 64 + r)) * (ldkv * 2) + c * 16);
                }
            }
        };

        load_kv(0, 0);
        CP_COMMIT();
        CP_WAIT1();
        __syncthreads();

        uint32_t Qhf[4][4], Qlf[4][4];
        {
            const int r = wid * 16 + (lane & 7) + 8 * ((lane >> 3) & 1);
            const int cb = 8 * (lane >> 4);
            #pragma unroll
            for (int kc = 0; kc < 4; kc++) {
                const uint32_t off = (uint32_t)r * APB + (kc * 16 + cb) * 2;
                LDSM_X4(Qhf[kc][0], Qhf[kc][1], Qhf[kc][2], Qhf[kc][3], sQh + off);
                LDSM_X4(Qlf[kc][0], Qlf[kc][1], Qlf[kc][2], Qlf[kc][3], sQl + off);
            }
        }

        float o[8][4] = {};
        float m0 = -1e30f, m1 = -1e30f, l0 = 0.f, l1 = 0.f;

        for (int kt = 0; kt < ntt; kt++) {
            const int st = kt & 1;
            if (kt + 1 < ntt) { load_kv(kt + 1, st ^ 1); CP_COMMIT(); CP_WAIT1(); }
            else              { CP_WAIT0(); }
            __syncthreads();

            const int k0 = kt * 64;
            const bool active = !causal || (k0 <= wrow + 15);
            if (active) {
                const uint32_t sKhT = sKV + st * KVSTAGE;
                const uint32_t sKlT = sKhT + KVTILE;
                const uint32_t sVhT = sKhT + 2 * KVTILE;
                const uint32_t sVlT = sKhT + 3 * KVTILE;

                float s[8][4] = {};
                {
                    const int krow = (lane & 7) + 8 * (lane >> 4);
                    const int kcolb = 8 * ((lane >> 3) & 1);
                    #pragma unroll
                    for (int kc = 0; kc < 4; kc++) {
                        uint32_t bh[8][2], bl[8][2];
                        #pragma unroll
                        for (int np = 0; np < 4; np++) {
                            const uint32_t off =
                                (uint32_t)(np * 16 + krow) * APB + (kc * 16 + kcolb) * 2;
                            LDSM_X4(bh[2*np][0], bh[2*np][1], bh[2*np+1][0], bh[2*np+1][1],
                                    sKhT + off);
                            LDSM_X4(bl[2*np][0], bl[2*np][1], bl[2*np+1][0], bl[2*np+1][1],
                                    sKlT + off);
                        }
                        #pragma unroll
                        for (int nt = 0; nt < 8; nt++) {
                            MMA_BF16(s[nt], Qhf[kc], bh[nt]);
                            MMA_BF16(s[nt], Qhf[kc], bl[nt]);
                            MMA_BF16(s[nt], Qlf[kc], bh[nt]);
                        }
                    }
                }

                const bool dm = causal && (k0 + 63 > wrow);
                float zx0 = -1e30f, zx1 = -1e30f;
                #pragma unroll
                for (int nt = 0; nt < 8; nt++) {
                    #pragma unroll
                    for (int r = 0; r < 4; r++) {
                        float z = s[nt][r] * cs;
                        if (dm) {
                            const int col = k0 + nt * 8 + ccol + (r & 1);
                            const int row = wrow + crow + 8 * (r >> 1);
                            if (col > row) z = -1e30f;
                        }
                        s[nt][r] = z;
                    }
                    zx0 = fmaxf(zx0, fmaxf(s[nt][0], s[nt][1]));
                    zx1 = fmaxf(zx1, fmaxf(s[nt][2], s[nt][3]));
                }
                zx0 = fmaxf(zx0, __shfl_xor_sync(0xffffffffu, zx0, 1));
                zx0 = fmaxf(zx0, __shfl_xor_sync(0xffffffffu, zx0, 2));
                zx1 = fmaxf(zx1, __shfl_xor_sync(0xffffffffu, zx1, 1));
                zx1 = fmaxf(zx1, __shfl_xor_sync(0xffffffffu, zx1, 2));
                const float mn0 = fmaxf(m0, zx0), mn1 = fmaxf(m1, zx1);
                const float a0 = ex2(m0 - mn0), a1 = ex2(m1 - mn1);
                m0 = mn0; m1 = mn1;

                float ps0 = 0.f, ps1 = 0.f;
                uint32_t pah[4][4], pal[4][4];
                #pragma unroll
                for (int nt = 0; nt < 8; nt++) {
                    const float p0 = ex2(s[nt][0] - mn0), p1 = ex2(s[nt][1] - mn0);
                    const float p2 = ex2(s[nt][2] - mn1), p3 = ex2(s[nt][3] - mn1);
                    ps0 += p0 + p1; ps1 += p2 + p3;
                    __nv_bfloat162 h01 = __float22bfloat162_rn(make_float2(p0, p1));
                    __nv_bfloat162 h23 = __float22bfloat162_rn(make_float2(p2, p3));
                    float2 f01 = __bfloat1622float2(h01);
                    float2 f23 = __bfloat1622float2(h23);
                    __nv_bfloat162 q01 = __float22bfloat162_rn(
                        make_float2(p0 - f01.x, p1 - f01.y));
                    __nv_bfloat162 q23 = __float22bfloat162_rn(
                        make_float2(p2 - f23.x, p3 - f23.y));
                    pah[nt >> 1][(nt & 1) * 2 + 0] = *(uint32_t*)&h01;
                    pah[nt >> 1][(nt & 1) * 2 + 1] = *(uint32_t*)&h23;
                    pal[nt >> 1][(nt & 1) * 2 + 0] = *(uint32_t*)&q01;
                    pal[nt >> 1][(nt & 1) * 2 + 1] = *(uint32_t*)&q23;
                }
                l0 = l0 * a0 + ps0;
                l1 = l1 * a1 + ps1;
                #pragma unroll
                for (int nt = 0; nt < 8; nt++) {
                    o[nt][0] *= a0; o[nt][1] *= a0;
                    o[nt][2] *= a1; o[nt][3] *= a1;
                }

                {
                    const int vrl = (lane & 7) + 8 * ((lane >> 3) & 1);
                    const int vcb = 8 * (lane >> 4);
                    #pragma unroll
                    for (int kc = 0; kc < 4; kc++) {
                        uint32_t vh[8][2], vl[8][2];
                        #pragma unroll
                        for (int dp = 0; dp < 4; dp++) {
                            const uint32_t off =
                                (uint32_t)(kc * 16 + vrl) * APB + (dp * 16 + vcb) * 2;
                            LDSM_X4T(vh[2*dp][0], vh[2*dp][1], vh[2*dp+1][0], vh[2*dp+1][1],
                                     sVhT + off);
                            LDSM_X4T(vl[2*dp][0], vl[2*dp][1], vl[2*dp+1][0], vl[2*dp+1][1],
                                     sVlT + off);
                        }
                        #pragma unroll
                        for (int nt = 0; nt < 8; nt++) {
                            MMA_BF16(o[nt], pah[kc], vh[nt]);
                            MMA_BF16(o[nt], pal[kc], vh[nt]);
                            MMA_BF16(o[nt], pah[kc], vl[nt]);
                        }
                    }
                }
            }
            __syncthreads();
        }

        l0 += __shfl_xor_sync(0xffffffffu, l0, 1);
        l0 += __shfl_xor_sync(0xffffffffu, l0, 2);
        l1 += __shfl_xor_sync(0xffffffffu, l1, 1);
        l1 += __shfl_xor_sync(0xffffffffu, l1, 2);
        const float i0 = 1.f / l0, i1 = 1.f / l1;

        if (phase == 0) {
            // park normalized self result in smem (thread-private slots)
            #pragma unroll
            for (int nt = 0; nt < 8; nt++) {
                const int c = nt * 8 + ccol;
                sO[rloc * 68 + c]           = o[nt][0] * i0;
                sO[rloc * 68 + c + 1]       = o[nt][1] * i0;
                sO[(rloc + 8) * 68 + c]     = o[nt][2] * i1;
                sO[(rloc + 8) * 68 + c + 1] = o[nt][3] * i1;
            }
            // all warps finished the kt loop (trailing sync above); safe to
            // overwrite sQ / sKV in the next phase.
        } else {
            const int r0 = q0 + wid * 16 + crow;
            __nv_bfloat16* yh0 = Yh + ((size_t)b * Tt + r0) * Cc + h * Dd;
            __nv_bfloat16* yl0 = Yl + ((size_t)b * Tt + r0) * Cc + h * Dd;
            __nv_bfloat16* yh1 = yh0 + 8 * Cc;
            __nv_bfloat16* yl1 = yl0 + 8 * Cc;
            #pragma unroll
            for (int nt = 0; nt < 8; nt++) {
                const int c = nt * 8 + ccol;
                float vx0 = sO[rloc * 68 + c]           + o[nt][0] * i0;
                float vy0 = sO[rloc * 68 + c + 1]       + o[nt][1] * i0;
                float vx1 = sO[(rloc + 8) * 68 + c]     + o[nt][2] * i1;
                float vy1 = sO[(rloc + 8) * 68 + c + 1] + o[nt][3] * i1;
                __nv_bfloat162 h0 = __float22bfloat162_rn(make_float2(vx0, vy0));
                float2 f0 = __bfloat1622float2(h0);
                __nv_bfloat162 l0b = __float22bfloat162_rn(
                    make_float2(vx0 - f0.x, vy0 - f0.y));
                __nv_bfloat162 h1 = __float22bfloat162_rn(make_float2(vx1, vy1));
                float2 f1 = __bfloat1622float2(h1);
                __nv_bfloat162 l1b = __float22bfloat162_rn(
                    make_float2(vx1 - f1.x, vy1 - f1.y));
                *(uint32_t*)&yh0[c] = *(uint32_t*)&h0;
                *(uint32_t*)&yl0[c] = *(uint32_t*)&l0b;
                *(uint32_t*)&yh1[c] = *(uint32_t*)&h1;
                *(uint32_t*)&yl1[c] = *(uint32_t*)&l1b;
            }
        }
    }
}

// ---------------------------------------------------------------------------

extern "C" void kernel_launch(void* const* d_in, const int* in_sizes, int n_in,
                              void* d_out, int out_size)
{
    const float* x     = (const float*)d_in[0];
    const float* cross = (const float*)d_in[1];
    const float* Wk  = (const float*)d_in[2];   const float* bk  = (const float*)d_in[3];
    const float* Wq  = (const float*)d_in[4];   const float* bq  = (const float*)d_in[5];
    const float* Wv  = (const float*)d_in[6];   const float* bv  = (const float*)d_in[7];
    const float* Wck = (const float*)d_in[8];   const float* bck = (const float*)d_in[9];
    const float* Wcq = (const float*)d_in[10];  const float* bcq = (const float*)d_in[11];
    const float* Wcv = (const float*)d_in[12];  const float* bcv = (const float*)d_in[13];
    const float* Wp  = (const float*)d_in[14];  const float* bp  = (const float*)d_in[15];
    float* out = (float*)d_out;

    __nv_bfloat16 *xh, *xl, *ch, *cl, *yh, *yl;
    cudaGetSymbolAddress((void**)&xh, g_xh); cudaGetSymbolAddress((void**)&xl, g_xl);
    cudaGetSymbolAddress((void**)&ch, g_ch); cudaGetSymbolAddress((void**)&cl, g_cl);
    cudaGetSymbolAddress((void**)&yh, g_yh); cudaGetSymbolAddress((void**)&yl, g_yl);

    __nv_bfloat16 *qkvh, *qkvl, *kvch, *kvcl;
    cudaGetSymbolAddress((void**)&qkvh, g_qkvh); cudaGetSymbolAddress((void**)&qkvl, g_qkvl);
    cudaGetSymbolAddress((void**)&kvch, g_kvch); cudaGetSymbolAddress((void**)&kvcl, g_kvcl);

    __nv_bfloat16 *w4h, *w4l, *w2h, *w2l, *wph, *wpl;
    cudaGetSymbolAddress((void**)&w4h, g_W4_h); cudaGetSymbolAddress((void**)&w4l, g_W4_l);
    cudaGetSymbolAddress((void**)&w2h, g_W2_h); cudaGetSymbolAddress((void**)&w2l, g_W2_l);
    cudaGetSymbolAddress((void**)&wph, g_Wp_h); cudaGetSymbolAddress((void**)&wpl, g_Wp_l);
    float *b4, *b2;
    cudaGetSymbolAddress((void**)&b4, g_b4); cudaGetSymbolAddress((void**)&b2, g_b2);

    // prep
    transpose_all_kernel<<<dim3(32, 32, 7), dim3(32, 8)>>>(Wq, Wk, Wv, Wcq, Wck, Wcv, Wp);
    bias_concat_kernel<<<24, 256>>>(bq, bk, bv, bcq, bck, bcv);
    const int nx = Bb * Tt * Cc, nc = Bb * TCc * CCc;
    cvt_kernel<<<(nx + 255) / 256, 256>>>(x, xh, xl, nx);
    cvt_kernel<<<(nc + 255) / 256, 256>>>(cross, ch, cl, nc);

    cudaFuncSetAttribute(hmma_gemm_kernel, cudaFuncAttributeMaxDynamicSharedMemorySize, GEMM_SMEM);
    const dim3 gblk(256);

    hmma_gemm_kernel<<<dim3(32, 32), gblk, GEMM_SMEM>>>(
        xh, xl, w4h, w4l, b4, nullptr, qkvh, qkvl, Bb*Tt, 4*Cc, Cc);
    hmma_gemm_kernel<<<dim3(16, 8), gblk, GEMM_SMEM>>>(
        ch, cl, w2h, w2l, b2, nullptr, kvch, kvcl, Bb*TCc, 2*Cc, CCc);

    cudaFuncSetAttribute(attn_fused_kernel, cudaFuncAttributeMaxDynamicSharedMemorySize, ATT_SMEM);
    attn_fused_kernel<<<dim3(Tt / 128, Hh, Bb), gblk, ATT_SMEM>>>(
        qkvh, qkvl, kvch, kvcl, yh, yl);

    hmma_gemm_kernel<<<dim3(8, 32), gblk, GEMM_SMEM>>>(
        yh, yl, wph, wpl, bp, out, nullptr, nullptr, Bb*Tt, Cc, Cc);
}

// round 8
// speedup vs baseline: 4.3176x; 1.4718x over previous
#include <cuda_runtime.h>
#include <cuda_fp16.h>
#include <cstdint>
#include <math.h>

#define Bb 2
#define Tt 2048
#define TCc 512
#define Cc 1024
#define CCc 512
#define Hh 16
#define Dd 64

// ---------------------------------------------------------------------------
// Scratch (__device__ globals; no allocation allowed)
// ---------------------------------------------------------------------------
__device__ __half g_xh[Bb*Tt*Cc],   g_xl[Bb*Tt*Cc];
__device__ __half g_ch[Bb*TCc*CCc], g_cl[Bb*TCc*CCc];
__device__ __half g_yh[Bb*Tt*Cc],   g_yl[Bb*Tt*Cc];

// fused projection outputs: [B*T, 4096] = [q | k | v | qc], fp16 hi/lo
__device__ __half g_qkvh[Bb*Tt*4*Cc], g_qkvl[Bb*Tt*4*Cc];
// fused cross outputs: [B*TC, 2048] = [kc | vc]
__device__ __half g_kvch[Bb*TCc*2*Cc], g_kvcl[Bb*TCc*2*Cc];

// fused transposed weights (SINGLE fp16 — b-side of asymmetric split)
__device__ __half g_W4_h[4*Cc*Cc];
__device__ __half g_W2_h[2*Cc*CCc];
__device__ __half g_Wp_h[Cc*Cc];
__device__ float g_b4[4*Cc], g_b2[2*Cc];

// ---------------------------------------------------------------------------
// helpers
// ---------------------------------------------------------------------------
__device__ __forceinline__ uint32_t smem_u32(const void* p) {
    uint32_t a;
    asm("{ .reg .u64 t; cvta.to.shared.u64 t, %1; cvt.u32.u64 %0, t; }"
        : "=r"(a) : "l"(p));
    return a;
}
__device__ __forceinline__ float ex2(float x) {
    float y; asm("ex2.approx.ftz.f32 %0, %1;" : "=f"(y) : "f"(x)); return y;
}

#define CP_ASYNC16(dst, src) \
    asm volatile("cp.async.cg.shared.global [%0], [%1], 16;" :: "r"(dst), "l"(src))
#define CP_COMMIT() asm volatile("cp.async.commit_group;" ::: "memory")
#define CP_WAIT0()  asm volatile("cp.async.wait_group 0;" ::: "memory")
#define CP_WAIT1()  asm volatile("cp.async.wait_group 1;" ::: "memory")

#define LDSM_X4(r0, r1, r2, r3, a) \
    asm volatile("ldmatrix.sync.aligned.m8n8.x4.shared.b16 {%0,%1,%2,%3}, [%4];" \
                 : "=r"(r0), "=r"(r1), "=r"(r2), "=r"(r3) : "r"(a))
#define LDSM_X4T(r0, r1, r2, r3, a) \
    asm volatile("ldmatrix.sync.aligned.m8n8.x4.trans.shared.b16 {%0,%1,%2,%3}, [%4];" \
                 : "=r"(r0), "=r"(r1), "=r"(r2), "=r"(r3) : "r"(a))

#define MMA_F16(d, a, b) \
    asm volatile("mma.sync.aligned.m16n8k16.row.col.f32.f16.f16.f32 " \
                 "{%0,%1,%2,%3}, {%4,%5,%6,%7}, {%8,%9}, {%0,%1,%2,%3};" \
                 : "+f"((d)[0]), "+f"((d)[1]), "+f"((d)[2]), "+f"((d)[3]) \
                 : "r"((a)[0]), "r"((a)[1]), "r"((a)[2]), "r"((a)[3]), \
                   "r"((b)[0]), "r"((b)[1]))

// ---------------------------------------------------------------------------
// prep kernels
// ---------------------------------------------------------------------------
__global__ void cvt_kernel(const float* __restrict__ s, __half* __restrict__ h,
                           __half* __restrict__ l, int n)
{
    int i = blockIdx.x * blockDim.x + threadIdx.x;
    if (i < n) {
        float v = s[i];
        __half hh = __float2half(v);
        h[i] = hh;
        l[i] = __float2half(v - __half2float(hh));
    }
}

__global__ void transpose_all_kernel(
    const float* __restrict__ Wq,  const float* __restrict__ Wk,
    const float* __restrict__ Wv,  const float* __restrict__ Wcq,
    const float* __restrict__ Wck, const float* __restrict__ Wcv,
    const float* __restrict__ Wp)
{
    const int z = blockIdx.z;
    const float* W;
    __half* Th;
    int K;
    switch (z) {
        case 0: W = Wq;  Th = g_W4_h;               K = 1024; break;
        case 1: W = Wk;  Th = g_W4_h + 1024 * 1024; K = 1024; break;
        case 2: W = Wv;  Th = g_W4_h + 2048 * 1024; K = 1024; break;
        case 3: W = Wcq; Th = g_W4_h + 3072 * 1024; K = 1024; break;
        case 4: W = Wck; Th = g_W2_h;               K = 512;  break;
        case 5: W = Wcv; Th = g_W2_h + 1024 * 512;  K = 512;  break;
        default: W = Wp; Th = g_Wp_h;               K = 1024; break;
    }
    if (K == 512 && blockIdx.y >= 16) return;

    __shared__ float t[32][33];
    const int n0 = blockIdx.x * 32, k0 = blockIdx.y * 32;
    const int tx = threadIdx.x, ty = threadIdx.y;
    #pragma unroll
    for (int i = 0; i < 4; i++)
        t[ty + 8 * i][tx] = W[(size_t)(k0 + ty + 8 * i) * 1024 + n0 + tx];
    __syncthreads();
    #pragma unroll
    for (int i = 0; i < 4; i++) {
        float v = t[tx][ty + 8 * i];
        Th[(size_t)(n0 + ty + 8 * i) * K + k0 + tx] = __float2half(v);
    }
}

__global__ void bias_concat_kernel(
    const float* __restrict__ bq, const float* __restrict__ bk,
    const float* __restrict__ bv, const float* __restrict__ bcq,
    const float* __restrict__ bck, const float* __restrict__ bcv)
{
    int i = blockIdx.x * blockDim.x + threadIdx.x;
    if (i < 4096) {
        const float* s[4] = {bq, bk, bv, bcq};
        g_b4[i] = s[i >> 10][i & 1023];
    } else if (i < 6144) {
        int j = i - 4096;
        g_b2[j] = (j < 1024) ? bck[j] : bcv[j - 1024];
    }
}

// ---------------------------------------------------------------------------
// HMMA GEMM, asymmetric 2-term fp16 split:
//   out = (Ah + Al) @ Bh^T + bias   (A split hi/lo, B single fp16)
// 3-stage cp.async pipeline, 3 tiles per stage.
// ---------------------------------------------------------------------------
#define BKg 32
#define LDAg 40
#define TILEB (128 * LDAg * 2)
#define STAGEB (3 * TILEB)
#define GEMM_SMEM (3 * STAGEB)          // 92160

__global__ __launch_bounds__(256, 1) void hmma_gemm_kernel(
    const __half* __restrict__ Ah, const __half* __restrict__ Al,
    const __half* __restrict__ Bh,
    const float* __restrict__ bias, float* __restrict__ outf,
    __half* __restrict__ outh, __half* __restrict__ outl,
    int M, int N, int K)
{
    extern __shared__ char smem[];
    const uint32_t sb = smem_u32(smem);
    const int tid = threadIdx.x;
    const int wid = tid >> 5, lane = tid & 31;
    const int bm = blockIdx.y * 128, bn = blockIdx.x * 128;

    const int wr = wid & 3;
    const int wc = wid >> 2;

    const char* gsrc[3] = {
        (const char*)(Ah + (size_t)bm * K),
        (const char*)(Al + (size_t)bm * K),
        (const char*)(Bh + (size_t)bn * K) };

    const int row0 = tid >> 2, c16a = tid & 3;
    const int row1 = (tid + 256) >> 2;

    auto load_chunk = [&](int kb, int st) {
        const uint32_t sdst = sb + st * STAGEB;
        #pragma unroll
        for (int m = 0; m < 3; m++) {
            const char* g = gsrc[m] + (size_t)kb * (BKg * 2);
            uint32_t d = sdst + m * TILEB;
            CP_ASYNC16(d + row0 * (LDAg * 2) + c16a * 16,
                       g + (size_t)row0 * (K * 2) + c16a * 16);
            CP_ASYNC16(d + row1 * (LDAg * 2) + c16a * 16,
                       g + (size_t)row1 * (K * 2) + c16a * 16);
        }
    };

    float acc[2][8][4] = {};

    const int nchunks = K / BKg;
    load_chunk(0, 0); CP_COMMIT();
    load_chunk(1, 1); CP_COMMIT();

    for (int kb = 0; kb < nchunks; kb++) {
        const int st = kb % 3;
        if (kb + 1 < nchunks) { CP_WAIT1(); } else { CP_WAIT0(); }
        __syncthreads();
        if (kb + 2 < nchunks) { load_chunk(kb + 2, (kb + 2) % 3); CP_COMMIT(); }

        const uint32_t ah = sb + st * STAGEB;
        const uint32_t al = ah + TILEB;
        const uint32_t bh = ah + 2 * TILEB;

        #pragma unroll
        for (int ks = 0; ks < 2; ks++) {
            const int k0 = ks * 16;
            uint32_t Ahf[2][4], Alf[2][4], Bhf[8][2];

            #pragma unroll
            for (int mt = 0; mt < 2; mt++) {
                const int arow = wr * 32 + mt * 16 + (lane & 15);
                const int acol = k0 + (lane >> 4) * 8;
                const uint32_t ao = (uint32_t)(arow * LDAg + acol) * 2;
                LDSM_X4(Ahf[mt][0], Ahf[mt][1], Ahf[mt][2], Ahf[mt][3], ah + ao);
                LDSM_X4(Alf[mt][0], Alf[mt][1], Alf[mt][2], Alf[mt][3], al + ao);
            }
            #pragma unroll
            for (int np = 0; np < 4; np++) {
                const int brow = wc * 64 + np * 16 + ((lane >> 4) & 1) * 8 + (lane & 7);
                const int bcol = k0 + ((lane >> 3) & 1) * 8;
                const uint32_t bo = (uint32_t)(brow * LDAg + bcol) * 2;
                LDSM_X4(Bhf[2*np][0], Bhf[2*np][1], Bhf[2*np+1][0], Bhf[2*np+1][1], bh + bo);
            }

            #pragma unroll
            for (int mt = 0; mt < 2; mt++)
                #pragma unroll
                for (int nt = 0; nt < 8; nt++) {
                    MMA_F16(acc[mt][nt], Ahf[mt], Bhf[nt]);
                    MMA_F16(acc[mt][nt], Alf[mt], Bhf[nt]);
                }
        }
    }

    const int crow = lane >> 2, ccol = (lane & 3) * 2;
    #pragma unroll
    for (int mt = 0; mt < 2; mt++) {
        #pragma unroll
        for (int half2i = 0; half2i < 2; half2i++) {
            const int r = bm + wr * 32 + mt * 16 + crow + half2i * 8;
            #pragma unroll
            for (int nt = 0; nt < 8; nt++) {
                const int c = bn + wc * 64 + nt * 8 + ccol;
                float2 b2 = *(const float2*)&bias[c];
                float vx = acc[mt][nt][half2i * 2 + 0] + b2.x;
                float vy = acc[mt][nt][half2i * 2 + 1] + b2.y;
                if (outf) {
                    float2 v; v.x = vx; v.y = vy;
                    *(float2*)&outf[(size_t)r * N + c] = v;
                } else {
                    __half2 hh = __float22half2_rn(make_float2(vx, vy));
                    float2 hf = __half22float2(hh);
                    __half2 ll = __float22half2_rn(make_float2(vx - hf.x, vy - hf.y));
                    *(uint32_t*)&outh[(size_t)r * N + c] = *(uint32_t*)&hh;
                    *(uint32_t*)&outl[(size_t)r * N + c] = *(uint32_t*)&ll;
                }
            }
        }
    }
}

// ---------------------------------------------------------------------------
// Fused HMMA flash attention (fp16, asymmetric splits):
//   S = (Qh + Ql) K_h^T        (2 MMAs/tile; K single fp16)
//   O += P_h (Vh + Vl)         (2 MMAs/tile; P single fp16)
// phase 0 = causal self, phase 1 = cross. Self parked in smem.
// ---------------------------------------------------------------------------
#define APB 144
#define QTILE (128 * APB)               // 18432
#define KVTILE (64 * APB)               // 9216
#define KVSTAGE (3 * KVTILE)            // 27648
#define SO_OFF (2 * QTILE + 2 * KVSTAGE)
#define ATT_SMEM (SO_OFF + 128 * 68 * 4)   // 127232

__global__ __launch_bounds__(256, 1) void attn_fused_kernel(
    const __half* __restrict__ qkvh, const __half* __restrict__ qkvl,
    const __half* __restrict__ kvch, const __half* __restrict__ kvcl,
    __half* __restrict__ Yh, __half* __restrict__ Yl)
{
    extern __shared__ char smem[];
    const uint32_t sb = smem_u32(smem);
    float* sO = (float*)(smem + SO_OFF);
    const int tid = threadIdx.x, wid = tid >> 5, lane = tid & 31;
    const int qt = gridDim.x - 1 - blockIdx.x;   // heavy first
    const int h = blockIdx.y, b = blockIdx.z;
    const int q0 = qt * 128;

    const uint32_t sQh = sb, sQl = sb + QTILE;
    const uint32_t sKV = sb + 2 * QTILE;

    const int crow = lane >> 2, ccol = (lane & 3) * 2;
    const int rloc = wid * 16 + crow;
    const int wrow = q0 + wid * 16;
    const float cs = 0.125f * 1.44269504089f;

    for (int phase = 0; phase < 2; phase++) {
        const bool causal = (phase == 0);
        const int ldq  = 4 * Cc;
        const int ldkv = causal ? 4 * Cc : 2 * Cc;
        const int ntt  = causal ? (2 * qt + 2) : (TCc / 64);

        const __half* Qhp = causal ? qkvh        : qkvh + 3072;
        const __half* Qlp = causal ? qkvl        : qkvl + 3072;
        const __half* Khp = causal ? qkvh + 1024 : kvch;
        const __half* Vhp = causal ? qkvh + 2048 : kvch + 1024;
        const __half* Vlp = causal ? qkvl + 2048 : kvcl + 1024;

        const size_t qoff = ((size_t)b * Tt + q0) * ldq + h * Dd;
        const size_t koff = ((size_t)b * (causal ? Tt : TCc)) * ldkv + h * Dd;

        // ---- load Q (hi/lo) ----
        {
            const char* gq[2] = { (const char*)(Qhp + qoff), (const char*)(Qlp + qoff) };
            #pragma unroll
            for (int m = 0; m < 2; m++) {
                uint32_t dst = m ? sQl : sQh;
                #pragma unroll
                for (int it = 0; it < 4; it++) {
                    int idx = it * 256 + tid;
                    int r = idx >> 3, c = idx & 7;
                    CP_ASYNC16(dst + r * APB + c * 16,
                               gq[m] + (size_t)r * (ldq * 2) + c * 16);
                }
            }
        }
        CP_COMMIT();

        const char* gk[3] = {
            (const char*)(Khp + koff),
            (const char*)(Vhp + koff), (const char*)(Vlp + koff) };
        auto load_kv = [&](int kt, int st) {
            uint32_t dst = sKV + st * KVSTAGE;
            #pragma unroll
            for (int m = 0; m < 3; m++) {
                #pragma unroll
                for (int it = 0; it < 2; it++) {
                    int idx = it * 256 + tid;
                    int r = idx >> 3, c = idx & 7;
                    CP_ASYNC16(dst + m * KVTILE + r * APB + c * 16,
                               gk[m] + ((size_t)(kt * 64 + r)) * (ldkv * 2) + c * 16);
                }
            }
        };

        load_kv(0, 0);
        CP_COMMIT();
        CP_WAIT1();
        __syncthreads();

        uint32_t Qhf[4][4], Qlf[4][4];
        {
            const int r = wid * 16 + (lane & 7) + 8 * ((lane >> 3) & 1);
            const int cb = 8 * (lane >> 4);
            #pragma unroll
            for (int kc = 0; kc < 4; kc++) {
                const uint32_t off = (uint32_t)r * APB + (kc * 16 + cb) * 2;
                LDSM_X4(Qhf[kc][0], Qhf[kc][1], Qhf[kc][2], Qhf[kc][3], sQh + off);
                LDSM_X4(Qlf[kc][0], Qlf[kc][1], Qlf[kc][2], Qlf[kc][3], sQl + off);
            }
        }

        float o[8][4] = {};
        float m0 = -1e30f, m1 = -1e30f, l0 = 0.f, l1 = 0.f;

        for (int kt = 0; kt < ntt; kt++) {
            const int st = kt & 1;
            if (kt + 1 < ntt) { load_kv(kt + 1, st ^ 1); CP_COMMIT(); CP_WAIT1(); }
            else              { CP_WAIT0(); }
            __syncthreads();

            const int k0 = kt * 64;
            const bool active = !causal || (k0 <= wrow + 15);
            if (active) {
                const uint32_t sKhT = sKV + st * KVSTAGE;
                const uint32_t sVhT = sKhT + KVTILE;
                const uint32_t sVlT = sKhT + 2 * KVTILE;

                // ---- S = (Qh + Ql) Kh^T ----
                float s[8][4] = {};
                {
                    const int krow = (lane & 7) + 8 * (lane >> 4);
                    const int kcolb = 8 * ((lane >> 3) & 1);
                    #pragma unroll
                    for (int kc = 0; kc < 4; kc++) {
                        uint32_t bh[8][2];
                        #pragma unroll
                        for (int np = 0; np < 4; np++) {
                            const uint32_t off =
                                (uint32_t)(np * 16 + krow) * APB + (kc * 16 + kcolb) * 2;
                            LDSM_X4(bh[2*np][0], bh[2*np][1], bh[2*np+1][0], bh[2*np+1][1],
                                    sKhT + off);
                        }
                        #pragma unroll
                        for (int nt = 0; nt < 8; nt++) {
                            MMA_F16(s[nt], Qhf[kc], bh[nt]);
                            MMA_F16(s[nt], Qlf[kc], bh[nt]);
                        }
                    }
                }

                const bool dm = causal && (k0 + 63 > wrow);
                float zx0 = -1e30f, zx1 = -1e30f;
                #pragma unroll
                for (int nt = 0; nt < 8; nt++) {
                    #pragma unroll
                    for (int r = 0; r < 4; r++) {
                        float z = s[nt][r] * cs;
                        if (dm) {
                            const int col = k0 + nt * 8 + ccol + (r & 1);
                            const int row = wrow + crow + 8 * (r >> 1);
                            if (col > row) z = -1e30f;
                        }
                        s[nt][r] = z;
                    }
                    zx0 = fmaxf(zx0, fmaxf(s[nt][0], s[nt][1]));
                    zx1 = fmaxf(zx1, fmaxf(s[nt][2], s[nt][3]));
                }
                zx0 = fmaxf(zx0, __shfl_xor_sync(0xffffffffu, zx0, 1));
                zx0 = fmaxf(zx0, __shfl_xor_sync(0xffffffffu, zx0, 2));
                zx1 = fmaxf(zx1, __shfl_xor_sync(0xffffffffu, zx1, 1));
                zx1 = fmaxf(zx1, __shfl_xor_sync(0xffffffffu, zx1, 2));
                const float mn0 = fmaxf(m0, zx0), mn1 = fmaxf(m1, zx1);
                const float a0 = ex2(m0 - mn0), a1 = ex2(m1 - mn1);
                m0 = mn0; m1 = mn1;

                float ps0 = 0.f, ps1 = 0.f;
                uint32_t pah[4][4];
                #pragma unroll
                for (int nt = 0; nt < 8; nt++) {
                    const float p0 = ex2(s[nt][0] - mn0), p1 = ex2(s[nt][1] - mn0);
                    const float p2 = ex2(s[nt][2] - mn1), p3 = ex2(s[nt][3] - mn1);
                    ps0 += p0 + p1; ps1 += p2 + p3;
                    __half2 h01 = __float22half2_rn(make_float2(p0, p1));
                    __half2 h23 = __float22half2_rn(make_float2(p2, p3));
                    pah[nt >> 1][(nt & 1) * 2 + 0] = *(uint32_t*)&h01;
                    pah[nt >> 1][(nt & 1) * 2 + 1] = *(uint32_t*)&h23;
                }
                l0 = l0 * a0 + ps0;
                l1 = l1 * a1 + ps1;
                #pragma unroll
                for (int nt = 0; nt < 8; nt++) {
                    o[nt][0] *= a0; o[nt][1] *= a0;
                    o[nt][2] *= a1; o[nt][3] *= a1;
                }

                // ---- O += Ph (Vh + Vl) ----
                {
                    const int vrl = (lane & 7) + 8 * ((lane >> 3) & 1);
                    const int vcb = 8 * (lane >> 4);
                    #pragma unroll
                    for (int kc = 0; kc < 4; kc++) {
                        uint32_t vh[8][2], vl[8][2];
                        #pragma unroll
                        for (int dp = 0; dp < 4; dp++) {
                            const uint32_t off =
                                (uint32_t)(kc * 16 + vrl) * APB + (dp * 16 + vcb) * 2;
                            LDSM_X4T(vh[2*dp][0], vh[2*dp][1], vh[2*dp+1][0], vh[2*dp+1][1],
                                     sVhT + off);
                            LDSM_X4T(vl[2*dp][0], vl[2*dp][1], vl[2*dp+1][0], vl[2*dp+1][1],
                                     sVlT + off);
                        }
                        #pragma unroll
                        for (int nt = 0; nt < 8; nt++) {
                            MMA_F16(o[nt], pah[kc], vh[nt]);
                            MMA_F16(o[nt], pah[kc], vl[nt]);
                        }
                    }
                }
            }
            __syncthreads();
        }

        l0 += __shfl_xor_sync(0xffffffffu, l0, 1);
        l0 += __shfl_xor_sync(0xffffffffu, l0, 2);
        l1 += __shfl_xor_sync(0xffffffffu, l1, 1);
        l1 += __shfl_xor_sync(0xffffffffu, l1, 2);
        const float i0 = 1.f / l0, i1 = 1.f / l1;

        if (phase == 0) {
            #pragma unroll
            for (int nt = 0; nt < 8; nt++) {
                const int c = nt * 8 + ccol;
                sO[rloc * 68 + c]           = o[nt][0] * i0;
                sO[rloc * 68 + c + 1]       = o[nt][1] * i0;
                sO[(rloc + 8) * 68 + c]     = o[nt][2] * i1;
                sO[(rloc + 8) * 68 + c + 1] = o[nt][3] * i1;
            }
        } else {
            const int r0 = q0 + wid * 16 + crow;
            __half* yh0 = Yh + ((size_t)b * Tt + r0) * Cc + h * Dd;
            __half* yl0 = Yl + ((size_t)b * Tt + r0) * Cc + h * Dd;
            __half* yh1 = yh0 + 8 * Cc;
            __half* yl1 = yl0 + 8 * Cc;
            #pragma unroll
            for (int nt = 0; nt < 8; nt++) {
                const int c = nt * 8 + ccol;
                float vx0 = sO[rloc * 68 + c]           + o[nt][0] * i0;
                float vy0 = sO[rloc * 68 + c + 1]       + o[nt][1] * i0;
                float vx1 = sO[(rloc + 8) * 68 + c]     + o[nt][2] * i1;
                float vy1 = sO[(rloc + 8) * 68 + c + 1] + o[nt][3] * i1;
                __half2 h0 = __float22half2_rn(make_float2(vx0, vy0));
                float2 f0 = __half22float2(h0);
                __half2 l0b = __float22half2_rn(make_float2(vx0 - f0.x, vy0 - f0.y));
                __half2 h1 = __float22half2_rn(make_float2(vx1, vy1));
                float2 f1 = __half22float2(h1);
                __half2 l1b = __float22half2_rn(make_float2(vx1 - f1.x, vy1 - f1.y));
                *(uint32_t*)&yh0[c] = *(uint32_t*)&h0;
                *(uint32_t*)&yl0[c] = *(uint32_t*)&l0b;
                *(uint32_t*)&yh1[c] = *(uint32_t*)&h1;
                *(uint32_t*)&yl1[c] = *(uint32_t*)&l1b;
            }
        }
    }
}

// ---------------------------------------------------------------------------

extern "C" void kernel_launch(void* const* d_in, const int* in_sizes, int n_in,
                              void* d_out, int out_size)
{
    const float* x     = (const float*)d_in[0];
    const float* cross = (const float*)d_in[1];
    const float* Wk  = (const float*)d_in[2];   const float* bk  = (const float*)d_in[3];
    const float* Wq  = (const float*)d_in[4];   const float* bq  = (const float*)d_in[5];
    const float* Wv  = (const float*)d_in[6];   const float* bv  = (const float*)d_in[7];
    const float* Wck = (const float*)d_in[8];   const float* bck = (const float*)d_in[9];
    const float* Wcq = (const float*)d_in[10];  const float* bcq = (const float*)d_in[11];
    const float* Wcv = (const float*)d_in[12];  const float* bcv = (const float*)d_in[13];
    const float* Wp  = (const float*)d_in[14];  const float* bp  = (const float*)d_in[15];
    float* out = (float*)d_out;

    __half *xh, *xl, *ch, *cl, *yh, *yl;
    cudaGetSymbolAddress((void**)&xh, g_xh); cudaGetSymbolAddress((void**)&xl, g_xl);
    cudaGetSymbolAddress((void**)&ch, g_ch); cudaGetSymbolAddress((void**)&cl, g_cl);
    cudaGetSymbolAddress((void**)&yh, g_yh); cudaGetSymbolAddress((void**)&yl, g_yl);

    __half *qkvh, *qkvl, *kvch, *kvcl;
    cudaGetSymbolAddress((void**)&qkvh, g_qkvh); cudaGetSymbolAddress((void**)&qkvl, g_qkvl);
    cudaGetSymbolAddress((void**)&kvch, g_kvch); cudaGetSymbolAddress((void**)&kvcl, g_kvcl);

    __half *w4h, *w2h, *wph;
    cudaGetSymbolAddress((void**)&w4h, g_W4_h);
    cudaGetSymbolAddress((void**)&w2h, g_W2_h);
    cudaGetSymbolAddress((void**)&wph, g_Wp_h);
    float *b4, *b2;
    cudaGetSymbolAddress((void**)&b4, g_b4); cudaGetSymbolAddress((void**)&b2, g_b2);

    // prep
    transpose_all_kernel<<<dim3(32, 32, 7), dim3(32, 8)>>>(Wq, Wk, Wv, Wcq, Wck, Wcv, Wp);
    bias_concat_kernel<<<24, 256>>>(bq, bk, bv, bcq, bck, bcv);
    const int nx = Bb * Tt * Cc, nc = Bb * TCc * CCc;
    cvt_kernel<<<(nx + 255) / 256, 256>>>(x, xh, xl, nx);
    cvt_kernel<<<(nc + 255) / 256, 256>>>(cross, ch, cl, nc);

    cudaFuncSetAttribute(hmma_gemm_kernel, cudaFuncAttributeMaxDynamicSharedMemorySize, GEMM_SMEM);
    const dim3 gblk(256);

    hmma_gemm_kernel<<<dim3(32, 32), gblk, GEMM_SMEM>>>(
        xh, xl, w4h, b4, nullptr, qkvh, qkvl, Bb*Tt, 4*Cc, Cc);
    hmma_gemm_kernel<<<dim3(16, 8), gblk, GEMM_SMEM>>>(
        ch, cl, w2h, b2, nullptr, kvch, kvcl, Bb*TCc, 2*Cc, CCc);

    cudaFuncSetAttribute(attn_fused_kernel, cudaFuncAttributeMaxDynamicSharedMemorySize, ATT_SMEM);
    attn_fused_kernel<<<dim3(Tt / 128, Hh, Bb), gblk, ATT_SMEM>>>(
        qkvh, qkvl, kvch, kvcl, yh, yl);

    hmma_gemm_kernel<<<dim3(8, 32), gblk, GEMM_SMEM>>>(
        yh, yl, wph, bp, out, nullptr, nullptr, Bb*Tt, Cc, Cc);
}

// round 9
// speedup vs baseline: 6.0584x; 1.4032x over previous
#include <cuda_runtime.h>
#include <cuda_fp16.h>
#include <cstdint>
#include <math.h>

#define Bb 2
#define Tt 2048
#define TCc 512
#define Cc 1024
#define CCc 512
#define Hh 16
#define Dd 64

// ---------------------------------------------------------------------------
// Scratch (__device__ globals; no allocation allowed)
// ---------------------------------------------------------------------------
__device__ __half g_xh[Bb*Tt*Cc];
__device__ __half g_ch[Bb*TCc*CCc], g_cl[Bb*TCc*CCc];
__device__ __half g_yh[Bb*Tt*Cc];

// fused projection outputs: [B*T, 4096] = [q | k | v | qc], fp16 hi/lo
// (lo only consumed for q/qc columns, but written everywhere)
__device__ __half g_qkvh[Bb*Tt*4*Cc], g_qkvl[Bb*Tt*4*Cc];
// fused cross outputs: [B*TC, 2048] = [kc | vc], single fp16
__device__ __half g_kvch[Bb*TCc*2*Cc];

// fused transposed weights (single fp16)
__device__ __half g_W4_h[4*Cc*Cc];
__device__ __half g_W2_h[2*Cc*CCc];
__device__ __half g_Wp_h[Cc*Cc];
__device__ float g_b4[4*Cc], g_b2[2*Cc];

// ---------------------------------------------------------------------------
// helpers
// ---------------------------------------------------------------------------
__device__ __forceinline__ uint32_t smem_u32(const void* p) {
    uint32_t a;
    asm("{ .reg .u64 t; cvta.to.shared.u64 t, %1; cvt.u32.u64 %0, t; }"
        : "=r"(a) : "l"(p));
    return a;
}
__device__ __forceinline__ float ex2(float x) {
    float y; asm("ex2.approx.ftz.f32 %0, %1;" : "=f"(y) : "f"(x)); return y;
}

#define CP_ASYNC16(dst, src) \
    asm volatile("cp.async.cg.shared.global [%0], [%1], 16;" :: "r"(dst), "l"(src))
#define CP_COMMIT() asm volatile("cp.async.commit_group;" ::: "memory")
#define CP_WAIT0()  asm volatile("cp.async.wait_group 0;" ::: "memory")
#define CP_WAIT1()  asm volatile("cp.async.wait_group 1;" ::: "memory")

#define LDSM_X4(r0, r1, r2, r3, a) \
    asm volatile("ldmatrix.sync.aligned.m8n8.x4.shared.b16 {%0,%1,%2,%3}, [%4];" \
                 : "=r"(r0), "=r"(r1), "=r"(r2), "=r"(r3) : "r"(a))
#define LDSM_X4T(r0, r1, r2, r3, a) \
    asm volatile("ldmatrix.sync.aligned.m8n8.x4.trans.shared.b16 {%0,%1,%2,%3}, [%4];" \
                 : "=r"(r0), "=r"(r1), "=r"(r2), "=r"(r3) : "r"(a))

#define MMA_F16(d, a, b) \
    asm volatile("mma.sync.aligned.m16n8k16.row.col.f32.f16.f16.f32 " \
                 "{%0,%1,%2,%3}, {%4,%5,%6,%7}, {%8,%9}, {%0,%1,%2,%3};" \
                 : "+f"((d)[0]), "+f"((d)[1]), "+f"((d)[2]), "+f"((d)[3]) \
                 : "r"((a)[0]), "r"((a)[1]), "r"((a)[2]), "r"((a)[3]), \
                   "r"((b)[0]), "r"((b)[1]))

// ---------------------------------------------------------------------------
// prep kernels
// ---------------------------------------------------------------------------
__global__ void cvt_pair_kernel(const float* __restrict__ s, __half* __restrict__ h,
                                __half* __restrict__ l, int n)
{
    int i = blockIdx.x * blockDim.x + threadIdx.x;
    if (i < n) {
        float v = s[i];
        __half hh = __float2half(v);
        h[i] = hh;
        l[i] = __float2half(v - __half2float(hh));
    }
}

__global__ void cvt_single_kernel(const float* __restrict__ s, __half* __restrict__ h, int n)
{
    int i = blockIdx.x * blockDim.x + threadIdx.x;
    if (i < n) h[i] = __float2half(s[i]);
}

__global__ void transpose_all_kernel(
    const float* __restrict__ Wq,  const float* __restrict__ Wk,
    const float* __restrict__ Wv,  const float* __restrict__ Wcq,
    const float* __restrict__ Wck, const float* __restrict__ Wcv,
    const float* __restrict__ Wp)
{
    const int z = blockIdx.z;
    const float* W;
    __half* Th;
    int K;
    switch (z) {
        case 0: W = Wq;  Th = g_W4_h;               K = 1024; break;
        case 1: W = Wk;  Th = g_W4_h + 1024 * 1024; K = 1024; break;
        case 2: W = Wv;  Th = g_W4_h + 2048 * 1024; K = 1024; break;
        case 3: W = Wcq; Th = g_W4_h + 3072 * 1024; K = 1024; break;
        case 4: W = Wck; Th = g_W2_h;               K = 512;  break;
        case 5: W = Wcv; Th = g_W2_h + 1024 * 512;  K = 512;  break;
        default: W = Wp; Th = g_Wp_h;               K = 1024; break;
    }
    if (K == 512 && blockIdx.y >= 16) return;

    __shared__ float t[32][33];
    const int n0 = blockIdx.x * 32, k0 = blockIdx.y * 32;
    const int tx = threadIdx.x, ty = threadIdx.y;
    #pragma unroll
    for (int i = 0; i < 4; i++)
        t[ty + 8 * i][tx] = W[(size_t)(k0 + ty + 8 * i) * 1024 + n0 + tx];
    __syncthreads();
    #pragma unroll
    for (int i = 0; i < 4; i++) {
        float v = t[tx][ty + 8 * i];
        Th[(size_t)(n0 + ty + 8 * i) * K + k0 + tx] = __float2half(v);
    }
}

__global__ void bias_concat_kernel(
    const float* __restrict__ bq, const float* __restrict__ bk,
    const float* __restrict__ bv, const float* __restrict__ bcq,
    const float* __restrict__ bck, const float* __restrict__ bcv)
{
    int i = blockIdx.x * blockDim.x + threadIdx.x;
    if (i < 4096) {
        const float* s[4] = {bq, bk, bv, bcq};
        g_b4[i] = s[i >> 10][i & 1023];
    } else if (i < 6144) {
        int j = i - 4096;
        g_b2[j] = (j < 1024) ? bck[j] : bcv[j - 1024];
    }
}

// ---------------------------------------------------------------------------
// HMMA GEMM. TWO=true:  out = (Ah+Al) @ Bh^T + bias  (3 smem tiles/stage)
//            TWO=false: out = Ah @ Bh^T + bias       (2 smem tiles/stage)
// Output: fp32 (outf) OR fp16 (outh [+ outl hi/lo split if non-null]).
// ---------------------------------------------------------------------------
#define BKg 32
#define LDAg 40
#define TILEB (128 * LDAg * 2)

template<bool TWO>
__global__ __launch_bounds__(256) void hmma_gemm_kernel(
    const __half* __restrict__ Ah, const __half* __restrict__ Al,
    const __half* __restrict__ Bh,
    const float* __restrict__ bias, float* __restrict__ outf,
    __half* __restrict__ outh, __half* __restrict__ outl,
    int M, int N, int K)
{
    constexpr int NT = TWO ? 3 : 2;
    constexpr int STG = NT * TILEB;

    extern __shared__ char smem[];
    const uint32_t sb = smem_u32(smem);
    const int tid = threadIdx.x;
    const int wid = tid >> 5, lane = tid & 31;
    const int bm = blockIdx.y * 128, bn = blockIdx.x * 128;

    const int wr = wid & 3;
    const int wc = wid >> 2;

    const char* gA  = (const char*)(Ah + (size_t)bm * K);
    const char* gAl = TWO ? (const char*)(Al + (size_t)bm * K) : nullptr;
    const char* gB  = (const char*)(Bh + (size_t)bn * K);

    const int row0 = tid >> 2, c16a = tid & 3;
    const int row1 = (tid + 256) >> 2;

    auto load_tile = [&](const char* g, uint32_t d, int kb) {
        g += (size_t)kb * (BKg * 2);
        CP_ASYNC16(d + row0 * (LDAg * 2) + c16a * 16,
                   g + (size_t)row0 * (K * 2) + c16a * 16);
        CP_ASYNC16(d + row1 * (LDAg * 2) + c16a * 16,
                   g + (size_t)row1 * (K * 2) + c16a * 16);
    };
    auto load_chunk = [&](int kb, int st) {
        const uint32_t sdst = sb + st * STG;
        load_tile(gA, sdst, kb);
        if (TWO) load_tile(gAl, sdst + TILEB, kb);
        load_tile(gB, sdst + (NT - 1) * TILEB, kb);
    };

    float acc[2][8][4] = {};

    const int nchunks = K / BKg;
    load_chunk(0, 0); CP_COMMIT();
    load_chunk(1, 1); CP_COMMIT();

    for (int kb = 0; kb < nchunks; kb++) {
        const int st = kb % 3;
        if (kb + 1 < nchunks) { CP_WAIT1(); } else { CP_WAIT0(); }
        __syncthreads();
        if (kb + 2 < nchunks) { load_chunk(kb + 2, (kb + 2) % 3); CP_COMMIT(); }

        const uint32_t ah = sb + st * STG;
        const uint32_t al = ah + TILEB;
        const uint32_t bh = ah + (NT - 1) * TILEB;

        #pragma unroll
        for (int ks = 0; ks < 2; ks++) {
            const int k0 = ks * 16;
            uint32_t Ahf[2][4], Alf[2][4], Bhf[8][2];

            #pragma unroll
            for (int mt = 0; mt < 2; mt++) {
                const int arow = wr * 32 + mt * 16 + (lane & 15);
                const int acol = k0 + (lane >> 4) * 8;
                const uint32_t ao = (uint32_t)(arow * LDAg + acol) * 2;
                LDSM_X4(Ahf[mt][0], Ahf[mt][1], Ahf[mt][2], Ahf[mt][3], ah + ao);
                if (TWO)
                    LDSM_X4(Alf[mt][0], Alf[mt][1], Alf[mt][2], Alf[mt][3], al + ao);
            }
            #pragma unroll
            for (int np = 0; np < 4; np++) {
                const int brow = wc * 64 + np * 16 + ((lane >> 4) & 1) * 8 + (lane & 7);
                const int bcol = k0 + ((lane >> 3) & 1) * 8;
                const uint32_t bo = (uint32_t)(brow * LDAg + bcol) * 2;
                LDSM_X4(Bhf[2*np][0], Bhf[2*np][1], Bhf[2*np+1][0], Bhf[2*np+1][1], bh + bo);
            }

            #pragma unroll
            for (int mt = 0; mt < 2; mt++)
                #pragma unroll
                for (int nt = 0; nt < 8; nt++) {
                    MMA_F16(acc[mt][nt], Ahf[mt], Bhf[nt]);
                    if (TWO) MMA_F16(acc[mt][nt], Alf[mt], Bhf[nt]);
                }
        }
    }

    const int crow = lane >> 2, ccol = (lane & 3) * 2;
    #pragma unroll
    for (int mt = 0; mt < 2; mt++) {
        #pragma unroll
        for (int hf2 = 0; hf2 < 2; hf2++) {
            const int r = bm + wr * 32 + mt * 16 + crow + hf2 * 8;
            #pragma unroll
            for (int nt = 0; nt < 8; nt++) {
                const int c = bn + wc * 64 + nt * 8 + ccol;
                float2 b2 = *(const float2*)&bias[c];
                float vx = acc[mt][nt][hf2 * 2 + 0] + b2.x;
                float vy = acc[mt][nt][hf2 * 2 + 1] + b2.y;
                if (outf) {
                    float2 v; v.x = vx; v.y = vy;
                    *(float2*)&outf[(size_t)r * N + c] = v;
                } else {
                    __half2 hh = __float22half2_rn(make_float2(vx, vy));
                    *(uint32_t*)&outh[(size_t)r * N + c] = *(uint32_t*)&hh;
                    if (outl) {
                        float2 hfv = __half22float2(hh);
                        __half2 ll = __float22half2_rn(make_float2(vx - hfv.x, vy - hfv.y));
                        *(uint32_t*)&outl[(size_t)r * N + c] = *(uint32_t*)&ll;
                    }
                }
            }
        }
    }
}

// ---------------------------------------------------------------------------
// Fused HMMA flash attention (fp16):
//   S = (Qh + Ql) Kh^T   (2 MMAs/tile; K single)
//   O += Ph Vh           (1 MMA/tile;  P and V single)
// phase 0 = causal self, phase 1 = cross. Self parked in smem fp32.
// Output: single fp16 y.
// ---------------------------------------------------------------------------
#define APB 144
#define QTILE (128 * APB)               // 18432
#define KVTILE (64 * APB)               // 9216
#define KVSTAGE (2 * KVTILE)            // 18432
#define SO_OFF (2 * QTILE + 2 * KVSTAGE)   // 73728
#define ATT_SMEM (SO_OFF + 128 * 68 * 4)   // 108544

__global__ __launch_bounds__(256, 1) void attn_fused_kernel(
    const __half* __restrict__ qkvh, const __half* __restrict__ qkvl,
    const __half* __restrict__ kvch, __half* __restrict__ Yh)
{
    extern __shared__ char smem[];
    const uint32_t sb = smem_u32(smem);
    float* sO = (float*)(smem + SO_OFF);
    const int tid = threadIdx.x, wid = tid >> 5, lane = tid & 31;
    const int qt = gridDim.x - 1 - blockIdx.x;   // heavy first
    const int h = blockIdx.y, b = blockIdx.z;
    const int q0 = qt * 128;

    const uint32_t sQh = sb, sQl = sb + QTILE;
    const uint32_t sKV = sb + 2 * QTILE;

    const int crow = lane >> 2, ccol = (lane & 3) * 2;
    const int rloc = wid * 16 + crow;
    const int wrow = q0 + wid * 16;
    const float cs = 0.125f * 1.44269504089f;

    for (int phase = 0; phase < 2; phase++) {
        const bool causal = (phase == 0);
        const int ldq  = 4 * Cc;
        const int ldkv = causal ? 4 * Cc : 2 * Cc;
        const int ntt  = causal ? (2 * qt + 2) : (TCc / 64);

        const __half* Qhp = causal ? qkvh        : qkvh + 3072;
        const __half* Qlp = causal ? qkvl        : qkvl + 3072;
        const __half* Khp = causal ? qkvh + 1024 : kvch;
        const __half* Vhp = causal ? qkvh + 2048 : kvch + 1024;

        const size_t qoff = ((size_t)b * Tt + q0) * ldq + h * Dd;
        const size_t koff = ((size_t)b * (causal ? Tt : TCc)) * ldkv + h * Dd;

        // ---- load Q (hi/lo) ----
        {
            const char* gq[2] = { (const char*)(Qhp + qoff), (const char*)(Qlp + qoff) };
            #pragma unroll
            for (int m = 0; m < 2; m++) {
                uint32_t dst = m ? sQl : sQh;
                #pragma unroll
                for (int it = 0; it < 4; it++) {
                    int idx = it * 256 + tid;
                    int r = idx >> 3, c = idx & 7;
                    CP_ASYNC16(dst + r * APB + c * 16,
                               gq[m] + (size_t)r * (ldq * 2) + c * 16);
                }
            }
        }
        CP_COMMIT();

        const char* gk[2] = { (const char*)(Khp + koff), (const char*)(Vhp + koff) };
        auto load_kv = [&](int kt, int st) {
            uint32_t dst = sKV + st * KVSTAGE;
            #pragma unroll
            for (int m = 0; m < 2; m++) {
                #pragma unroll
                for (int it = 0; it < 2; it++) {
                    int idx = it * 256 + tid;
                    int r = idx >> 3, c = idx & 7;
                    CP_ASYNC16(dst + m * KVTILE + r * APB + c * 16,
                               gk[m] + ((size_t)(kt * 64 + r)) * (ldkv * 2) + c * 16);
                }
            }
        };

        load_kv(0, 0);
        CP_COMMIT();
        CP_WAIT1();
        __syncthreads();

        uint32_t Qhf[4][4], Qlf[4][4];
        {
            const int r = wid * 16 + (lane & 7) + 8 * ((lane >> 3) & 1);
            const int cb = 8 * (lane >> 4);
            #pragma unroll
            for (int kc = 0; kc < 4; kc++) {
                const uint32_t off = (uint32_t)r * APB + (kc * 16 + cb) * 2;
                LDSM_X4(Qhf[kc][0], Qhf[kc][1], Qhf[kc][2], Qhf[kc][3], sQh + off);
                LDSM_X4(Qlf[kc][0], Qlf[kc][1], Qlf[kc][2], Qlf[kc][3], sQl + off);
            }
        }

        float o[8][4] = {};
        float m0 = -1e30f, m1 = -1e30f, l0 = 0.f, l1 = 0.f;

        for (int kt = 0; kt < ntt; kt++) {
            const int st = kt & 1;
            if (kt + 1 < ntt) { load_kv(kt + 1, st ^ 1); CP_COMMIT(); CP_WAIT1(); }
            else              { CP_WAIT0(); }
            __syncthreads();

            const int k0 = kt * 64;
            const bool active = !causal || (k0 <= wrow + 15);
            if (active) {
                const uint32_t sKhT = sKV + st * KVSTAGE;
                const uint32_t sVhT = sKhT + KVTILE;

                // ---- S = (Qh + Ql) Kh^T ----
                float s[8][4] = {};
                {
                    const int krow = (lane & 7) + 8 * (lane >> 4);
                    const int kcolb = 8 * ((lane >> 3) & 1);
                    #pragma unroll
                    for (int kc = 0; kc < 4; kc++) {
                        uint32_t bh[8][2];
                        #pragma unroll
                        for (int np = 0; np < 4; np++) {
                            const uint32_t off =
                                (uint32_t)(np * 16 + krow) * APB + (kc * 16 + kcolb) * 2;
                            LDSM_X4(bh[2*np][0], bh[2*np][1], bh[2*np+1][0], bh[2*np+1][1],
                                    sKhT + off);
                        }
                        #pragma unroll
                        for (int nt = 0; nt < 8; nt++) {
                            MMA_F16(s[nt], Qhf[kc], bh[nt]);
                            MMA_F16(s[nt], Qlf[kc], bh[nt]);
                        }
                    }
                }

                const bool dm = causal && (k0 + 63 > wrow);
                float zx0 = -1e30f, zx1 = -1e30f;
                #pragma unroll
                for (int nt = 0; nt < 8; nt++) {
                    #pragma unroll
                    for (int r = 0; r < 4; r++) {
                        float z = s[nt][r] * cs;
                        if (dm) {
                            const int col = k0 + nt * 8 + ccol + (r & 1);
                            const int row = wrow + crow + 8 * (r >> 1);
                            if (col > row) z = -1e30f;
                        }
                        s[nt][r] = z;
                    }
                    zx0 = fmaxf(zx0, fmaxf(s[nt][0], s[nt][1]));
                    zx1 = fmaxf(zx1, fmaxf(s[nt][2], s[nt][3]));
                }
                zx0 = fmaxf(zx0, __shfl_xor_sync(0xffffffffu, zx0, 1));
                zx0 = fmaxf(zx0, __shfl_xor_sync(0xffffffffu, zx0, 2));
                zx1 = fmaxf(zx1, __shfl_xor_sync(0xffffffffu, zx1, 1));
                zx1 = fmaxf(zx1, __shfl_xor_sync(0xffffffffu, zx1, 2));
                const float mn0 = fmaxf(m0, zx0), mn1 = fmaxf(m1, zx1);
                const float a0 = ex2(m0 - mn0), a1 = ex2(m1 - mn1);
                m0 = mn0; m1 = mn1;

                float ps0 = 0.f, ps1 = 0.f;
                uint32_t pah[4][4];
                #pragma unroll
                for (int nt = 0; nt < 8; nt++) {
                    const float p0 = ex2(s[nt][0] - mn0), p1 = ex2(s[nt][1] - mn0);
                    const float p2 = ex2(s[nt][2] - mn1), p3 = ex2(s[nt][3] - mn1);
                    ps0 += p0 + p1; ps1 += p2 + p3;
                    __half2 h01 = __float22half2_rn(make_float2(p0, p1));
                    __half2 h23 = __float22half2_rn(make_float2(p2, p3));
                    pah[nt >> 1][(nt & 1) * 2 + 0] = *(uint32_t*)&h01;
                    pah[nt >> 1][(nt & 1) * 2 + 1] = *(uint32_t*)&h23;
                }
                l0 = l0 * a0 + ps0;
                l1 = l1 * a1 + ps1;
                #pragma unroll
                for (int nt = 0; nt < 8; nt++) {
                    o[nt][0] *= a0; o[nt][1] *= a0;
                    o[nt][2] *= a1; o[nt][3] *= a1;
                }

                // ---- O += Ph Vh ----
                {
                    const int vrl = (lane & 7) + 8 * ((lane >> 3) & 1);
                    const int vcb = 8 * (lane >> 4);
                    #pragma unroll
                    for (int kc = 0; kc < 4; kc++) {
                        uint32_t vh[8][2];
                        #pragma unroll
                        for (int dp = 0; dp < 4; dp++) {
                            const uint32_t off =
                                (uint32_t)(kc * 16 + vrl) * APB + (dp * 16 + vcb) * 2;
                            LDSM_X4T(vh[2*dp][0], vh[2*dp][1], vh[2*dp+1][0], vh[2*dp+1][1],
                                     sVhT + off);
                        }
                        #pragma unroll
                        for (int nt = 0; nt < 8; nt++)
                            MMA_F16(o[nt], pah[kc], vh[nt]);
                    }
                }
            }
            __syncthreads();
        }

        l0 += __shfl_xor_sync(0xffffffffu, l0, 1);
        l0 += __shfl_xor_sync(0xffffffffu, l0, 2);
        l1 += __shfl_xor_sync(0xffffffffu, l1, 1);
        l1 += __shfl_xor_sync(0xffffffffu, l1, 2);
        const float i0 = 1.f / l0, i1 = 1.f / l1;

        if (phase == 0) {
            #pragma unroll
            for (int nt = 0; nt < 8; nt++) {
                const int c = nt * 8 + ccol;
                sO[rloc * 68 + c]           = o[nt][0] * i0;
                sO[rloc * 68 + c + 1]       = o[nt][1] * i0;
                sO[(rloc + 8) * 68 + c]     = o[nt][2] * i1;
                sO[(rloc + 8) * 68 + c + 1] = o[nt][3] * i1;
            }
        } else {
            const int r0 = q0 + wid * 16 + crow;
            __half* yh0 = Yh + ((size_t)b * Tt + r0) * Cc + h * Dd;
            __half* yh1 = yh0 + 8 * Cc;
            #pragma unroll
            for (int nt = 0; nt < 8; nt++) {
                const int c = nt * 8 + ccol;
                float vx0 = sO[rloc * 68 + c]           + o[nt][0] * i0;
                float vy0 = sO[rloc * 68 + c + 1]       + o[nt][1] * i0;
                float vx1 = sO[(rloc + 8) * 68 + c]     + o[nt][2] * i1;
                float vy1 = sO[(rloc + 8) * 68 + c + 1] + o[nt][3] * i1;
                __half2 h0 = __float22half2_rn(make_float2(vx0, vy0));
                __half2 h1 = __float22half2_rn(make_float2(vx1, vy1));
                *(uint32_t*)&yh0[c] = *(uint32_t*)&h0;
                *(uint32_t*)&yh1[c] = *(uint32_t*)&h1;
            }
        }
    }
}

// ---------------------------------------------------------------------------

extern "C" void kernel_launch(void* const* d_in, const int* in_sizes, int n_in,
                              void* d_out, int out_size)
{
    const float* x     = (const float*)d_in[0];
    const float* cross = (const float*)d_in[1];
    const float* Wk  = (const float*)d_in[2];   const float* bk  = (const float*)d_in[3];
    const float* Wq  = (const float*)d_in[4];   const float* bq  = (const float*)d_in[5];
    const float* Wv  = (const float*)d_in[6];   const float* bv  = (const float*)d_in[7];
    const float* Wck = (const float*)d_in[8];   const float* bck = (const float*)d_in[9];
    const float* Wcq = (const float*)d_in[10];  const float* bcq = (const float*)d_in[11];
    const float* Wcv = (const float*)d_in[12];  const float* bcv = (const float*)d_in[13];
    const float* Wp  = (const float*)d_in[14];  const float* bp  = (const float*)d_in[15];
    float* out = (float*)d_out;

    __half *xh, *ch, *cl, *yh;
    cudaGetSymbolAddress((void**)&xh, g_xh);
    cudaGetSymbolAddress((void**)&ch, g_ch); cudaGetSymbolAddress((void**)&cl, g_cl);
    cudaGetSymbolAddress((void**)&yh, g_yh);

    __half *qkvh, *qkvl, *kvch;
    cudaGetSymbolAddress((void**)&qkvh, g_qkvh); cudaGetSymbolAddress((void**)&qkvl, g_qkvl);
    cudaGetSymbolAddress((void**)&kvch, g_kvch);

    __half *w4h, *w2h, *wph;
    cudaGetSymbolAddress((void**)&w4h, g_W4_h);
    cudaGetSymbolAddress((void**)&w2h, g_W2_h);
    cudaGetSymbolAddress((void**)&wph, g_Wp_h);
    float *b4, *b2;
    cudaGetSymbolAddress((void**)&b4, g_b4); cudaGetSymbolAddress((void**)&b2, g_b2);

    // prep
    transpose_all_kernel<<<dim3(32, 32, 7), dim3(32, 8)>>>(Wq, Wk, Wv, Wcq, Wck, Wcv, Wp);
    bias_concat_kernel<<<24, 256>>>(bq, bk, bv, bcq, bck, bcv);
    const int nx = Bb * Tt * Cc, nc = Bb * TCc * CCc;
    cvt_single_kernel<<<(nx + 255) / 256, 256>>>(x, xh, nx);
    cvt_pair_kernel<<<(nc + 255) / 256, 256>>>(cross, ch, cl, nc);

    const int SM1 = 3 * 2 * TILEB;   // 1-term GEMM smem (61440)
    const int SM2 = 3 * 3 * TILEB;   // 2-term GEMM smem (92160)
    cudaFuncSetAttribute(hmma_gemm_kernel<false>,
                         cudaFuncAttributeMaxDynamicSharedMemorySize, SM1);
    cudaFuncSetAttribute(hmma_gemm_kernel<true>,
                         cudaFuncAttributeMaxDynamicSharedMemorySize, SM2);
    const dim3 gblk(256);

    // QKV projection: single x @ single W4  -> hi/lo qkv
    hmma_gemm_kernel<false><<<dim3(32, 32), gblk, SM1>>>(
        xh, nullptr, w4h, b4, nullptr, qkvh, qkvl, Bb*Tt, 4*Cc, Cc);
    // cross projection: (ch+cl) @ single W2 -> single kvc
    hmma_gemm_kernel<true><<<dim3(16, 8), gblk, SM2>>>(
        ch, cl, w2h, b2, nullptr, kvch, nullptr, Bb*TCc, 2*Cc, CCc);

    cudaFuncSetAttribute(attn_fused_kernel, cudaFuncAttributeMaxDynamicSharedMemorySize, ATT_SMEM);
    attn_fused_kernel<<<dim3(Tt / 128, Hh, Bb), gblk, ATT_SMEM>>>(
        qkvh, qkvl, kvch, yh);

    // output projection: single y @ single Wp -> fp32 out
    hmma_gemm_kernel<false><<<dim3(8, 32), gblk, SM1>>>(
        yh, nullptr, wph, bp, out, nullptr, nullptr, Bb*Tt, Cc, Cc);
}

// round 10
// speedup vs baseline: 6.5549x; 1.0820x over previous
#include <cuda_runtime.h>
#include <cuda_fp16.h>
#include <cstdint>
#include <math.h>

#define Bb 2
#define Tt 2048
#define TCc 512
#define Cc 1024
#define CCc 512
#define Hh 16
#define Dd 64

// ---------------------------------------------------------------------------
// Scratch (__device__ globals; no allocation allowed)
// ---------------------------------------------------------------------------
__device__ __half g_xh[Bb*Tt*Cc];
__device__ __half g_ch[Bb*TCc*CCc], g_cl[Bb*TCc*CCc];
__device__ __half g_yh[Bb*Tt*Cc];

// fused projection outputs: [B*T, 4096] = [q | k | v | qc], single fp16
__device__ __half g_qkvh[Bb*Tt*4*Cc];
// fused cross outputs: [B*TC, 2048] = [kc | vc], single fp16
__device__ __half g_kvch[Bb*TCc*2*Cc];

// fused transposed weights (single fp16)
__device__ __half g_W4_h[4*Cc*Cc];
__device__ __half g_W2_h[2*Cc*CCc];
__device__ __half g_Wp_h[Cc*Cc];
__device__ float g_b4[4*Cc], g_b2[2*Cc];

// ---------------------------------------------------------------------------
// helpers
// ---------------------------------------------------------------------------
__device__ __forceinline__ uint32_t smem_u32(const void* p) {
    uint32_t a;
    asm("{ .reg .u64 t; cvta.to.shared.u64 t, %1; cvt.u32.u64 %0, t; }"
        : "=r"(a) : "l"(p));
    return a;
}
__device__ __forceinline__ float ex2(float x) {
    float y; asm("ex2.approx.ftz.f32 %0, %1;" : "=f"(y) : "f"(x)); return y;
}

#define CP_ASYNC16(dst, src) \
    asm volatile("cp.async.cg.shared.global [%0], [%1], 16;" :: "r"(dst), "l"(src))
#define CP_COMMIT() asm volatile("cp.async.commit_group;" ::: "memory")
#define CP_WAIT0()  asm volatile("cp.async.wait_group 0;" ::: "memory")
#define CP_WAIT1()  asm volatile("cp.async.wait_group 1;" ::: "memory")

#define LDSM_X4(r0, r1, r2, r3, a) \
    asm volatile("ldmatrix.sync.aligned.m8n8.x4.shared.b16 {%0,%1,%2,%3}, [%4];" \
                 : "=r"(r0), "=r"(r1), "=r"(r2), "=r"(r3) : "r"(a))
#define LDSM_X4T(r0, r1, r2, r3, a) \
    asm volatile("ldmatrix.sync.aligned.m8n8.x4.trans.shared.b16 {%0,%1,%2,%3}, [%4];" \
                 : "=r"(r0), "=r"(r1), "=r"(r2), "=r"(r3) : "r"(a))

#define MMA_F16(d, a, b) \
    asm volatile("mma.sync.aligned.m16n8k16.row.col.f32.f16.f16.f32 " \
                 "{%0,%1,%2,%3}, {%4,%5,%6,%7}, {%8,%9}, {%0,%1,%2,%3};" \
                 : "+f"((d)[0]), "+f"((d)[1]), "+f"((d)[2]), "+f"((d)[3]) \
                 : "r"((a)[0]), "r"((a)[1]), "r"((a)[2]), "r"((a)[3]), \
                   "r"((b)[0]), "r"((b)[1]))

// ---------------------------------------------------------------------------
// prep kernels
// ---------------------------------------------------------------------------
__global__ void cvt_pair_kernel(const float* __restrict__ s, __half* __restrict__ h,
                                __half* __restrict__ l, int n)
{
    int i = blockIdx.x * blockDim.x + threadIdx.x;
    if (i < n) {
        float v = s[i];
        __half hh = __float2half(v);
        h[i] = hh;
        l[i] = __float2half(v - __half2float(hh));
    }
}

__global__ void cvt_single_kernel(const float* __restrict__ s, __half* __restrict__ h, int n)
{
    int i = blockIdx.x * blockDim.x + threadIdx.x;
    if (i < n) h[i] = __float2half(s[i]);
}

__global__ void transpose_all_kernel(
    const float* __restrict__ Wq,  const float* __restrict__ Wk,
    const float* __restrict__ Wv,  const float* __restrict__ Wcq,
    const float* __restrict__ Wck, const float* __restrict__ Wcv,
    const float* __restrict__ Wp)
{
    const int z = blockIdx.z;
    const float* W;
    __half* Th;
    int K;
    switch (z) {
        case 0: W = Wq;  Th = g_W4_h;               K = 1024; break;
        case 1: W = Wk;  Th = g_W4_h + 1024 * 1024; K = 1024; break;
        case 2: W = Wv;  Th = g_W4_h + 2048 * 1024; K = 1024; break;
        case 3: W = Wcq; Th = g_W4_h + 3072 * 1024; K = 1024; break;
        case 4: W = Wck; Th = g_W2_h;               K = 512;  break;
        case 5: W = Wcv; Th = g_W2_h + 1024 * 512;  K = 512;  break;
        default: W = Wp; Th = g_Wp_h;               K = 1024; break;
    }
    if (K == 512 && blockIdx.y >= 16) return;

    __shared__ float t[32][33];
    const int n0 = blockIdx.x * 32, k0 = blockIdx.y * 32;
    const int tx = threadIdx.x, ty = threadIdx.y;
    #pragma unroll
    for (int i = 0; i < 4; i++)
        t[ty + 8 * i][tx] = W[(size_t)(k0 + ty + 8 * i) * 1024 + n0 + tx];
    __syncthreads();
    #pragma unroll
    for (int i = 0; i < 4; i++) {
        float v = t[tx][ty + 8 * i];
        Th[(size_t)(n0 + ty + 8 * i) * K + k0 + tx] = __float2half(v);
    }
}

__global__ void bias_concat_kernel(
    const float* __restrict__ bq, const float* __restrict__ bk,
    const float* __restrict__ bv, const float* __restrict__ bcq,
    const float* __restrict__ bck, const float* __restrict__ bcv)
{
    int i = blockIdx.x * blockDim.x + threadIdx.x;
    if (i < 4096) {
        const float* s[4] = {bq, bk, bv, bcq};
        g_b4[i] = s[i >> 10][i & 1023];
    } else if (i < 6144) {
        int j = i - 4096;
        g_b2[j] = (j < 1024) ? bck[j] : bcv[j - 1024];
    }
}

// ---------------------------------------------------------------------------
// HMMA GEMM. TWO=true:  out = (Ah+Al) @ Bh^T + bias  (3 smem tiles/stage)
//            TWO=false: out = Ah @ Bh^T + bias       (2 smem tiles/stage)
// Output: fp32 (outf) OR single fp16 (outh).
// ---------------------------------------------------------------------------
#define BKg 32
#define LDAg 40
#define TILEB (128 * LDAg * 2)

template<bool TWO>
__global__ __launch_bounds__(256) void hmma_gemm_kernel(
    const __half* __restrict__ Ah, const __half* __restrict__ Al,
    const __half* __restrict__ Bh,
    const float* __restrict__ bias, float* __restrict__ outf,
    __half* __restrict__ outh,
    int M, int N, int K)
{
    constexpr int NT = TWO ? 3 : 2;
    constexpr int STG = NT * TILEB;

    extern __shared__ char smem[];
    const uint32_t sb = smem_u32(smem);
    const int tid = threadIdx.x;
    const int wid = tid >> 5, lane = tid & 31;
    const int bm = blockIdx.y * 128, bn = blockIdx.x * 128;

    const int wr = wid & 3;
    const int wc = wid >> 2;

    const char* gA  = (const char*)(Ah + (size_t)bm * K);
    const char* gAl = TWO ? (const char*)(Al + (size_t)bm * K) : nullptr;
    const char* gB  = (const char*)(Bh + (size_t)bn * K);

    const int row0 = tid >> 2, c16a = tid & 3;
    const int row1 = (tid + 256) >> 2;

    auto load_tile = [&](const char* g, uint32_t d, int kb) {
        g += (size_t)kb * (BKg * 2);
        CP_ASYNC16(d + row0 * (LDAg * 2) + c16a * 16,
                   g + (size_t)row0 * (K * 2) + c16a * 16);
        CP_ASYNC16(d + row1 * (LDAg * 2) + c16a * 16,
                   g + (size_t)row1 * (K * 2) + c16a * 16);
    };
    auto load_chunk = [&](int kb, int st) {
        const uint32_t sdst = sb + st * STG;
        load_tile(gA, sdst, kb);
        if (TWO) load_tile(gAl, sdst + TILEB, kb);
        load_tile(gB, sdst + (NT - 1) * TILEB, kb);
    };

    float acc[2][8][4] = {};

    const int nchunks = K / BKg;
    load_chunk(0, 0); CP_COMMIT();
    load_chunk(1, 1); CP_COMMIT();

    for (int kb = 0; kb < nchunks; kb++) {
        const int st = kb % 3;
        if (kb + 1 < nchunks) { CP_WAIT1(); } else { CP_WAIT0(); }
        __syncthreads();
        if (kb + 2 < nchunks) { load_chunk(kb + 2, (kb + 2) % 3); CP_COMMIT(); }

        const uint32_t ah = sb + st * STG;
        const uint32_t al = ah + TILEB;
        const uint32_t bh = ah + (NT - 1) * TILEB;

        #pragma unroll
        for (int ks = 0; ks < 2; ks++) {
            const int k0 = ks * 16;
            uint32_t Ahf[2][4], Alf[2][4], Bhf[8][2];

            #pragma unroll
            for (int mt = 0; mt < 2; mt++) {
                const int arow = wr * 32 + mt * 16 + (lane & 15);
                const int acol = k0 + (lane >> 4) * 8;
                const uint32_t ao = (uint32_t)(arow * LDAg + acol) * 2;
                LDSM_X4(Ahf[mt][0], Ahf[mt][1], Ahf[mt][2], Ahf[mt][3], ah + ao);
                if (TWO)
                    LDSM_X4(Alf[mt][0], Alf[mt][1], Alf[mt][2], Alf[mt][3], al + ao);
            }
            #pragma unroll
            for (int np = 0; np < 4; np++) {
                const int brow = wc * 64 + np * 16 + ((lane >> 4) & 1) * 8 + (lane & 7);
                const int bcol = k0 + ((lane >> 3) & 1) * 8;
                const uint32_t bo = (uint32_t)(brow * LDAg + bcol) * 2;
                LDSM_X4(Bhf[2*np][0], Bhf[2*np][1], Bhf[2*np+1][0], Bhf[2*np+1][1], bh + bo);
            }

            #pragma unroll
            for (int mt = 0; mt < 2; mt++)
                #pragma unroll
                for (int nt = 0; nt < 8; nt++) {
                    MMA_F16(acc[mt][nt], Ahf[mt], Bhf[nt]);
                    if (TWO) MMA_F16(acc[mt][nt], Alf[mt], Bhf[nt]);
                }
        }
    }

    const int crow = lane >> 2, ccol = (lane & 3) * 2;
    #pragma unroll
    for (int mt = 0; mt < 2; mt++) {
        #pragma unroll
        for (int hf2 = 0; hf2 < 2; hf2++) {
            const int r = bm + wr * 32 + mt * 16 + crow + hf2 * 8;
            #pragma unroll
            for (int nt = 0; nt < 8; nt++) {
                const int c = bn + wc * 64 + nt * 8 + ccol;
                float2 b2 = *(const float2*)&bias[c];
                float vx = acc[mt][nt][hf2 * 2 + 0] + b2.x;
                float vy = acc[mt][nt][hf2 * 2 + 1] + b2.y;
                if (outf) {
                    float2 v; v.x = vx; v.y = vy;
                    *(float2*)&outf[(size_t)r * N + c] = v;
                } else {
                    __half2 hh = __float22half2_rn(make_float2(vx, vy));
                    *(uint32_t*)&outh[(size_t)r * N + c] = *(uint32_t*)&hh;
                }
            }
        }
    }
}

// ---------------------------------------------------------------------------
// Fused HMMA flash attention (all single fp16 operands):
//   S = Qh Kh^T   (1 MMA/frag)
//   O += Ph Vh    (1 MMA/frag)
// phase 0 = causal self, phase 1 = cross. Self parked in smem fp32.
// ---------------------------------------------------------------------------
#define APB 144
#define QTILE (128 * APB)               // 18432
#define KVTILE (64 * APB)               // 9216
#define KVSTAGE (2 * KVTILE)            // 18432
#define SO_OFF (QTILE + 2 * KVSTAGE)    // 55296
#define ATT_SMEM (SO_OFF + 128 * 68 * 4)   // 90112

__global__ __launch_bounds__(256, 1) void attn_fused_kernel(
    const __half* __restrict__ qkvh,
    const __half* __restrict__ kvch, __half* __restrict__ Yh)
{
    extern __shared__ char smem[];
    const uint32_t sb = smem_u32(smem);
    float* sO = (float*)(smem + SO_OFF);
    const int tid = threadIdx.x, wid = tid >> 5, lane = tid & 31;
    const int qt = gridDim.x - 1 - blockIdx.x;   // heavy first
    const int h = blockIdx.y, b = blockIdx.z;
    const int q0 = qt * 128;

    const uint32_t sQh = sb;
    const uint32_t sKV = sb + QTILE;

    const int crow = lane >> 2, ccol = (lane & 3) * 2;
    const int rloc = wid * 16 + crow;
    const int wrow = q0 + wid * 16;
    const float cs = 0.125f * 1.44269504089f;

    for (int phase = 0; phase < 2; phase++) {
        const bool causal = (phase == 0);
        const int ldq  = 4 * Cc;
        const int ldkv = causal ? 4 * Cc : 2 * Cc;
        const int ntt  = causal ? (2 * qt + 2) : (TCc / 64);

        const __half* Qhp = causal ? qkvh        : qkvh + 3072;
        const __half* Khp = causal ? qkvh + 1024 : kvch;
        const __half* Vhp = causal ? qkvh + 2048 : kvch + 1024;

        const size_t qoff = ((size_t)b * Tt + q0) * ldq + h * Dd;
        const size_t koff = ((size_t)b * (causal ? Tt : TCc)) * ldkv + h * Dd;

        // ---- load Q ----
        {
            const char* gq = (const char*)(Qhp + qoff);
            #pragma unroll
            for (int it = 0; it < 4; it++) {
                int idx = it * 256 + tid;
                int r = idx >> 3, c = idx & 7;
                CP_ASYNC16(sQh + r * APB + c * 16,
                           gq + (size_t)r * (ldq * 2) + c * 16);
            }
        }
        CP_COMMIT();

        const char* gk[2] = { (const char*)(Khp + koff), (const char*)(Vhp + koff) };
        auto load_kv = [&](int kt, int st) {
            uint32_t dst = sKV + st * KVSTAGE;
            #pragma unroll
            for (int m = 0; m < 2; m++) {
                #pragma unroll
                for (int it = 0; it < 2; it++) {
                    int idx = it * 256 + tid;
                    int r = idx >> 3, c = idx & 7;
                    CP_ASYNC16(dst + m * KVTILE + r * APB + c * 16,
                               gk[m] + ((size_t)(kt * 64 + r)) * (ldkv * 2) + c * 16);
                }
            }
        };

        load_kv(0, 0);
        CP_COMMIT();
        CP_WAIT1();
        __syncthreads();

        uint32_t Qhf[4][4];
        {
            const int r = wid * 16 + (lane & 7) + 8 * ((lane >> 3) & 1);
            const int cb = 8 * (lane >> 4);
            #pragma unroll
            for (int kc = 0; kc < 4; kc++) {
                const uint32_t off = (uint32_t)r * APB + (kc * 16 + cb) * 2;
                LDSM_X4(Qhf[kc][0], Qhf[kc][1], Qhf[kc][2], Qhf[kc][3], sQh + off);
            }
        }

        float o[8][4] = {};
        float m0 = -1e30f, m1 = -1e30f, l0 = 0.f, l1 = 0.f;

        for (int kt = 0; kt < ntt; kt++) {
            const int st = kt & 1;
            if (kt + 1 < ntt) { load_kv(kt + 1, st ^ 1); CP_COMMIT(); CP_WAIT1(); }
            else              { CP_WAIT0(); }
            __syncthreads();

            const int k0 = kt * 64;
            const bool active = !causal || (k0 <= wrow + 15);
            if (active) {
                const uint32_t sKhT = sKV + st * KVSTAGE;
                const uint32_t sVhT = sKhT + KVTILE;

                // ---- S = Qh Kh^T ----
                float s[8][4] = {};
                {
                    const int krow = (lane & 7) + 8 * (lane >> 4);
                    const int kcolb = 8 * ((lane >> 3) & 1);
                    #pragma unroll
                    for (int kc = 0; kc < 4; kc++) {
                        uint32_t bh[8][2];
                        #pragma unroll
                        for (int np = 0; np < 4; np++) {
                            const uint32_t off =
                                (uint32_t)(np * 16 + krow) * APB + (kc * 16 + kcolb) * 2;
                            LDSM_X4(bh[2*np][0], bh[2*np][1], bh[2*np+1][0], bh[2*np+1][1],
                                    sKhT + off);
                        }
                        #pragma unroll
                        for (int nt = 0; nt < 8; nt++)
                            MMA_F16(s[nt], Qhf[kc], bh[nt]);
                    }
                }

                const bool dm = causal && (k0 + 63 > wrow);
                float zx0 = -1e30f, zx1 = -1e30f;
                #pragma unroll
                for (int nt = 0; nt < 8; nt++) {
                    #pragma unroll
                    for (int r = 0; r < 4; r++) {
                        float z = s[nt][r] * cs;
                        if (dm) {
                            const int col = k0 + nt * 8 + ccol + (r & 1);
                            const int row = wrow + crow + 8 * (r >> 1);
                            if (col > row) z = -1e30f;
                        }
                        s[nt][r] = z;
                    }
                    zx0 = fmaxf(zx0, fmaxf(s[nt][0], s[nt][1]));
                    zx1 = fmaxf(zx1, fmaxf(s[nt][2], s[nt][3]));
                }
                zx0 = fmaxf(zx0, __shfl_xor_sync(0xffffffffu, zx0, 1));
                zx0 = fmaxf(zx0, __shfl_xor_sync(0xffffffffu, zx0, 2));
                zx1 = fmaxf(zx1, __shfl_xor_sync(0xffffffffu, zx1, 1));
                zx1 = fmaxf(zx1, __shfl_xor_sync(0xffffffffu, zx1, 2));
                const float mn0 = fmaxf(m0, zx0), mn1 = fmaxf(m1, zx1);
                const float a0 = ex2(m0 - mn0), a1 = ex2(m1 - mn1);
                m0 = mn0; m1 = mn1;

                float ps0 = 0.f, ps1 = 0.f;
                uint32_t pah[4][4];
                #pragma unroll
                for (int nt = 0; nt < 8; nt++) {
                    const float p0 = ex2(s[nt][0] - mn0), p1 = ex2(s[nt][1] - mn0);
                    const float p2 = ex2(s[nt][2] - mn1), p3 = ex2(s[nt][3] - mn1);
                    ps0 += p0 + p1; ps1 += p2 + p3;
                    __half2 h01 = __float22half2_rn(make_float2(p0, p1));
                    __half2 h23 = __float22half2_rn(make_float2(p2, p3));
                    pah[nt >> 1][(nt & 1) * 2 + 0] = *(uint32_t*)&h01;
                    pah[nt >> 1][(nt & 1) * 2 + 1] = *(uint32_t*)&h23;
                }
                l0 = l0 * a0 + ps0;
                l1 = l1 * a1 + ps1;
                #pragma unroll
                for (int nt = 0; nt < 8; nt++) {
                    o[nt][0] *= a0; o[nt][1] *= a0;
                    o[nt][2] *= a1; o[nt][3] *= a1;
                }

                // ---- O += Ph Vh ----
                {
                    const int vrl = (lane & 7) + 8 * ((lane >> 3) & 1);
                    const int vcb = 8 * (lane >> 4);
                    #pragma unroll
                    for (int kc = 0; kc < 4; kc++) {
                        uint32_t vh[8][2];
                        #pragma unroll
                        for (int dp = 0; dp < 4; dp++) {
                            const uint32_t off =
                                (uint32_t)(kc * 16 + vrl) * APB + (dp * 16 + vcb) * 2;
                            LDSM_X4T(vh[2*dp][0], vh[2*dp][1], vh[2*dp+1][0], vh[2*dp+1][1],
                                     sVhT + off);
                        }
                        #pragma unroll
                        for (int nt = 0; nt < 8; nt++)
                            MMA_F16(o[nt], pah[kc], vh[nt]);
                    }
                }
            }
            __syncthreads();
        }

        l0 += __shfl_xor_sync(0xffffffffu, l0, 1);
        l0 += __shfl_xor_sync(0xffffffffu, l0, 2);
        l1 += __shfl_xor_sync(0xffffffffu, l1, 1);
        l1 += __shfl_xor_sync(0xffffffffu, l1, 2);
        const float i0 = 1.f / l0, i1 = 1.f / l1;

        if (phase == 0) {
            #pragma unroll
            for (int nt = 0; nt < 8; nt++) {
                const int c = nt * 8 + ccol;
                sO[rloc * 68 + c]           = o[nt][0] * i0;
                sO[rloc * 68 + c + 1]       = o[nt][1] * i0;
                sO[(rloc + 8) * 68 + c]     = o[nt][2] * i1;
                sO[(rloc + 8) * 68 + c + 1] = o[nt][3] * i1;
            }
        } else {
            const int r0 = q0 + wid * 16 + crow;
            __half* yh0 = Yh + ((size_t)b * Tt + r0) * Cc + h * Dd;
            __half* yh1 = yh0 + 8 * Cc;
            #pragma unroll
            for (int nt = 0; nt < 8; nt++) {
                const int c = nt * 8 + ccol;
                float vx0 = sO[rloc * 68 + c]           + o[nt][0] * i0;
                float vy0 = sO[rloc * 68 + c + 1]       + o[nt][1] * i0;
                float vx1 = sO[(rloc + 8) * 68 + c]     + o[nt][2] * i1;
                float vy1 = sO[(rloc + 8) * 68 + c + 1] + o[nt][3] * i1;
                __half2 h0 = __float22half2_rn(make_float2(vx0, vy0));
                __half2 h1 = __float22half2_rn(make_float2(vx1, vy1));
                *(uint32_t*)&yh0[c] = *(uint32_t*)&h0;
                *(uint32_t*)&yh1[c] = *(uint32_t*)&h1;
            }
        }
    }
}

// ---------------------------------------------------------------------------

extern "C" void kernel_launch(void* const* d_in, const int* in_sizes, int n_in,
                              void* d_out, int out_size)
{
    const float* x     = (const float*)d_in[0];
    const float* cross = (const float*)d_in[1];
    const float* Wk  = (const float*)d_in[2];   const float* bk  = (const float*)d_in[3];
    const float* Wq  = (const float*)d_in[4];   const float* bq  = (const float*)d_in[5];
    const float* Wv  = (const float*)d_in[6];   const float* bv  = (const float*)d_in[7];
    const float* Wck = (const float*)d_in[8];   const float* bck = (const float*)d_in[9];
    const float* Wcq = (const float*)d_in[10];  const float* bcq = (const float*)d_in[11];
    const float* Wcv = (const float*)d_in[12];  const float* bcv = (const float*)d_in[13];
    const float* Wp  = (const float*)d_in[14];  const float* bp  = (const float*)d_in[15];
    float* out = (float*)d_out;

    __half *xh, *ch, *cl, *yh;
    cudaGetSymbolAddress((void**)&xh, g_xh);
    cudaGetSymbolAddress((void**)&ch, g_ch); cudaGetSymbolAddress((void**)&cl, g_cl);
    cudaGetSymbolAddress((void**)&yh, g_yh);

    __half *qkvh, *kvch;
    cudaGetSymbolAddress((void**)&qkvh, g_qkvh);
    cudaGetSymbolAddress((void**)&kvch, g_kvch);

    __half *w4h, *w2h, *wph;
    cudaGetSymbolAddress((void**)&w4h, g_W4_h);
    cudaGetSymbolAddress((void**)&w2h, g_W2_h);
    cudaGetSymbolAddress((void**)&wph, g_Wp_h);
    float *b4, *b2;
    cudaGetSymbolAddress((void**)&b4, g_b4); cudaGetSymbolAddress((void**)&b2, g_b2);

    // prep
    transpose_all_kernel<<<dim3(32, 32, 7), dim3(32, 8)>>>(Wq, Wk, Wv, Wcq, Wck, Wcv, Wp);
    bias_concat_kernel<<<24, 256>>>(bq, bk, bv, bcq, bck, bcv);
    const int nx = Bb * Tt * Cc, nc = Bb * TCc * CCc;
    cvt_single_kernel<<<(nx + 255) / 256, 256>>>(x, xh, nx);
    cvt_pair_kernel<<<(nc + 255) / 256, 256>>>(cross, ch, cl, nc);

    const int SM1 = 3 * 2 * TILEB;   // 1-term GEMM smem (61440)
    const int SM2 = 3 * 3 * TILEB;   // 2-term GEMM smem (92160)
    cudaFuncSetAttribute(hmma_gemm_kernel<false>,
                         cudaFuncAttributeMaxDynamicSharedMemorySize, SM1);
    cudaFuncSetAttribute(hmma_gemm_kernel<true>,
                         cudaFuncAttributeMaxDynamicSharedMemorySize, SM2);
    const dim3 gblk(256);

    // QKV projection: single x @ single W4 -> single qkv
    hmma_gemm_kernel<false><<<dim3(32, 32), gblk, SM1>>>(
        xh, nullptr, w4h, b4, nullptr, qkvh, Bb*Tt, 4*Cc, Cc);
    // cross projection: (ch+cl) @ single W2 -> single kvc
    hmma_gemm_kernel<true><<<dim3(16, 8), gblk, SM2>>>(
        ch, cl, w2h, b2, nullptr, kvch, Bb*TCc, 2*Cc, CCc);

    cudaFuncSetAttribute(attn_fused_kernel, cudaFuncAttributeMaxDynamicSharedMemorySize, ATT_SMEM);
    attn_fused_kernel<<<dim3(Tt / 128, Hh, Bb), gblk, ATT_SMEM>>>(
        qkvh, kvch, yh);

    // output projection: single y @ single Wp -> fp32 out
    hmma_gemm_kernel<false><<<dim3(8, 32), gblk, SM1>>>(
        yh, nullptr, wph, bp, out, nullptr, Bb*Tt, Cc, Cc);
}